// round 6
// baseline (speedup 1.0000x reference)
#include <cuda_runtime.h>
#include <math.h>

#define G 1024
#define NNODE 256
#define FIN 128
#define DH 256
#define MAXD 128

// ---------------- scratch (device globals; no allocations allowed) -------------
__device__ float g_norm0[G * NNODE];
__device__ unsigned char g_cols[(long)G * NNODE * MAXD];
__device__ int   g_cnt [G * NNODE];
__device__ float g_Y  [G * NNODE * FIN];    // norm.*(A@(norm.*x))
__device__ float g_X1 [G * NNODE * DH];
__device__ float g_spre[2 * G * NNODE];     // partial X1·Ws0 dots (one per bn block)
__device__ float g_Xp1[G * 32 * DH];
__device__ float g_A1 [G * 32 * 32];
__device__ float g_norm1[G * 32];
__device__ float g_H1 [G * 32 * DH];
__device__ float g_Xp2[G * 16 * DH];
__device__ float g_A2 [G * 16 * 16];
__device__ float g_norm2[G * 16];
__device__ float g_H2 [G * 16 * DH];
__device__ float g_Xp3[G * 8 * DH];
__device__ float g_read[G * 1536];
__device__ float g_h  [G * 128];

// ---------------- build sparse adjacency lists + degree norm -------------------
__global__ void build_adj_kernel(const float* __restrict__ adj,
                                 unsigned char* __restrict__ cols,
                                 int* __restrict__ cnt, float* __restrict__ nrm)
{
    int row  = blockIdx.x * 8 + (threadIdx.x >> 5);
    int lane = threadIdx.x & 31;
    const float* a = adj + (long)row * 256;
    unsigned char* lst = cols + (long)row * MAXD;
    int base = 0;
#pragma unroll
    for (int c = 0; c < 8; c++) {
        float v = a[c * 32 + lane];
        unsigned m = __ballot_sync(0xffffffffu, v != 0.f);
        if (v != 0.f) {
            int pos = base + __popc(m & ((1u << lane) - 1));
            if (pos < MAXD) lst[pos] = (unsigned char)(c * 32 + lane);
        }
        base += __popc(m);
    }
    if (lane == 0) {
        cnt[row] = (base > MAXD) ? MAXD : base;
        nrm[row] = rsqrtf(fmaxf((float)base, 1.f));
    }
}

// ------- layer-0 sparse aggregation, 64-col halves for 2 CTA/SM ----------------
// Y[g,i,c] = norm[i] * sum_{j in N(i)} norm[j] * x[g,j,c],  c in [half*64, half*64+64)
__global__ void spmm_feat_kernel(const unsigned char* __restrict__ cols,
                                 const int* __restrict__ cnt,
                                 const float* __restrict__ feat,
                                 const float* __restrict__ nrm,
                                 float* __restrict__ Y)
{
    extern __shared__ float sX[];                 // [256][64] = 64 KB
    __shared__ float snrm[256];
    __shared__ int   scnt[256];

    int g = blockIdx.y, half = blockIdx.x;
    int tid = threadIdx.x;
    snrm[tid] = nrm[g * 256 + tid];
    scnt[tid] = cnt[g * 256 + tid];
    __syncthreads();

    {
        const float4* F = (const float4*)(feat + (long)g * 32768 + half * 64);
        float4* s4 = (float4*)sX;
        for (int t = tid; t < 4096; t += 256) {
            int r = t >> 4, c4 = t & 15;
            float4 v = F[(long)r * 32 + c4];
            float s = snrm[r];
            v.x *= s; v.y *= s; v.z *= s; v.w *= s;
            s4[r * 16 + c4] = v;
        }
    }
    __syncthreads();

    int lane = tid & 31, warp = tid >> 5;
    for (int i = warp; i < 256; i += 8) {
        int d = scnt[i];
        const unsigned char* lst = cols + ((long)g * 256 + i) * MAXD;
        float a0 = 0.f, a1 = 0.f;
        int k = 0;
        for (; k + 4 <= d; k += 4) {
            unsigned w = *(const unsigned*)(lst + k);   // uniform per warp -> broadcast
            int j0 = w & 255, j1 = (w >> 8) & 255, j2 = (w >> 16) & 255, j3 = w >> 24;
            float2 h0 = *(const float2*)(sX + j0 * 64 + lane * 2);
            float2 h1 = *(const float2*)(sX + j1 * 64 + lane * 2);
            float2 h2 = *(const float2*)(sX + j2 * 64 + lane * 2);
            float2 h3 = *(const float2*)(sX + j3 * 64 + lane * 2);
            a0 += h0.x + h1.x + h2.x + h3.x;
            a1 += h0.y + h1.y + h2.y + h3.y;
        }
        for (; k < d; k++) {
            int j = lst[k];
            float2 h = *(const float2*)(sX + j * 64 + lane * 2);
            a0 += h.x; a1 += h.y;
        }
        float nr = snrm[i];
        *(float2*)(Y + (long)g * 32768 + (long)i * 128 + half * 64 + lane * 2) =
            make_float2(a0 * nr, a1 * nr);
    }
}

// ---------------- dense scalar SGEMM + optional fused score-dot ----------------
#define BM 128
#define BN 128
#define BK 8

__global__ void sgemm_kernel(const float* __restrict__ A, const float* __restrict__ B,
                             float* __restrict__ C,
                             int M, int N, int K,
                             long bA, long bB, long bC,
                             const float* __restrict__ rsA, int rsAstride,
                             const float* __restrict__ rsC, int rsCstride,
                             const float* __restrict__ bias, int leaky,
                             const float* __restrict__ Wsp, float* __restrict__ spreOut)
{
    int g = blockIdx.z;
    const float* Ag = A + (long)g * bA;
    const float* Bg = B + (long)g * bB;
    float* Cg = C + (long)g * bC;
    const float* rsAg = rsA ? rsA + (long)g * rsAstride : nullptr;
    const float* rsCg = rsC ? rsC + (long)g * rsCstride : nullptr;

    int bm = blockIdx.y * BM;
    int bn = blockIdx.x * BN;

    __shared__ __align__(16) float sA[BK][BM + 4];
    __shared__ __align__(16) float sB[BK][BN + 4];

    int tid = threadIdx.x;
    int a_row = tid >> 1;
    int a_col = (tid & 1) * 4;
    int b_row = tid >> 5;
    int b_col = (tid & 31) * 4;
    int tr = tid >> 4;
    int tc = tid & 15;

    float acc[8][8];
#pragma unroll
    for (int i = 0; i < 8; i++)
#pragma unroll
        for (int j = 0; j < 8; j++) acc[i][j] = 0.f;

    float aScale = rsAg ? rsAg[bm + a_row] : 1.f;

    for (int k0 = 0; k0 < K; k0 += BK) {
        float4 av = *(const float4*)(Ag + (long)(bm + a_row) * K + k0 + a_col);
        av.x *= aScale; av.y *= aScale; av.z *= aScale; av.w *= aScale;
        sA[a_col + 0][a_row] = av.x;
        sA[a_col + 1][a_row] = av.y;
        sA[a_col + 2][a_row] = av.z;
        sA[a_col + 3][a_row] = av.w;
        float4 bv = *(const float4*)(Bg + (long)(k0 + b_row) * N + bn + b_col);
        *(float4*)&sB[b_row][b_col] = bv;
        __syncthreads();
#pragma unroll
        for (int k = 0; k < BK; k++) {
            float4 a0 = *(const float4*)&sA[k][tr * 4];
            float4 a1 = *(const float4*)&sA[k][tr * 4 + 64];
            float4 b0 = *(const float4*)&sB[k][tc * 4];
            float4 b1 = *(const float4*)&sB[k][tc * 4 + 64];
            float ar[8] = {a0.x, a0.y, a0.z, a0.w, a1.x, a1.y, a1.z, a1.w};
            float br[8] = {b0.x, b0.y, b0.z, b0.w, b1.x, b1.y, b1.z, b1.w};
#pragma unroll
            for (int i = 0; i < 8; i++)
#pragma unroll
                for (int j = 0; j < 8; j++) acc[i][j] += ar[i] * br[j];
        }
        __syncthreads();
    }

#pragma unroll
    for (int i = 0; i < 8; i++) {
        int row = bm + ((i < 4) ? (tr * 4 + i) : (64 + tr * 4 + i - 4));
        float rs = rsCg ? rsCg[row] : 1.f;
        float rd = 0.f;
#pragma unroll
        for (int jg = 0; jg < 2; jg++) {
            int col = bn + tc * 4 + jg * 64;
            float v[4];
#pragma unroll
            for (int jj = 0; jj < 4; jj++) {
                float c = acc[i][jg * 4 + jj] * rs;
                if (bias) c += bias[col + jj];
                if (leaky) c = (c > 0.f) ? c : 0.01f * c;
                v[jj] = c;
                if (Wsp) rd += c * __ldg(&Wsp[col + jj]);
            }
            float4 o = make_float4(v[0], v[1], v[2], v[3]);
            *(float4*)(Cg + (long)row * N + col) = o;
        }
        if (Wsp) {
#pragma unroll
            for (int s = 8; s > 0; s >>= 1)
                rd += __shfl_xor_sync(0xffffffffu, rd, s);
            if (tc == 0) spreOut[(long)blockIdx.x * M + row] = rd;
        }
    }
}

// ---------------- layer-0 SAGPool (unchanged from round 5) ---------------------
template <int NV, int KK>
__global__ void pool_kernel(const float* __restrict__ X, const float* __restrict__ A,
                            const float* __restrict__ nrm,
                            const float* __restrict__ bs,
                            const unsigned char* __restrict__ colsL,
                            const int* __restrict__ cntL,
                            const float* __restrict__ spreParts,
                            float* __restrict__ Xp, float* __restrict__ Aout,
                            float* __restrict__ normOut, float* __restrict__ readout,
                            int roff)
{
    int g = blockIdx.x;
    const float* Xg = X + (long)g * NV * 256;
    const float* Ag = A + (long)g * NV * NV;
    const float* ng = nrm + (long)g * NV;

    __shared__ float spre[NV];
    __shared__ float ssc[NV];
    __shared__ int   sidx[NV];
    __shared__ float sAn[KK * KK];

    int tid = threadIdx.x, lane = tid & 31, warp = tid >> 5;

    if (tid < NV)
        spre[tid] = (spreParts[(long)g * NV + tid] +
                     spreParts[(long)G * NNODE + (long)g * NV + tid]) * ng[tid];
    __syncthreads();

    float bsv = bs[0];
    for (int r = warp; r < NV; r += 8) {
        int d = cntL[g * NV + r];
        const unsigned char* lst = colsL + ((long)g * NV + r) * MAXD;
        float acc = 0.f;
        for (int q = lane; q < d; q += 32) acc += spre[lst[q]];
#pragma unroll
        for (int s = 16; s > 0; s >>= 1) acc += __shfl_down_sync(0xffffffffu, acc, s);
        if (lane == 0) { ssc[r] = ng[r] * acc + bsv; sidx[r] = r; }
    }
    __syncthreads();

    for (int ksz = 2; ksz <= NV; ksz <<= 1) {
        for (int j = ksz >> 1; j > 0; j >>= 1) {
            if (tid < NV) {
                int ixj = tid ^ j;
                if (ixj > tid) {
                    float s1 = ssc[tid], s2 = ssc[ixj];
                    int i1 = sidx[tid], i2 = sidx[ixj];
                    bool firstWorse = (s1 < s2) || (s1 == s2 && i1 > i2);
                    bool descRegion = ((tid & ksz) == 0);
                    bool doSwap = descRegion ? firstWorse : !firstWorse;
                    if (doSwap) {
                        ssc[tid] = s2; ssc[ixj] = s1;
                        sidx[tid] = i2; sidx[ixj] = i1;
                    }
                }
            }
            __syncthreads();
        }
    }

    if (tid < KK) ssc[tid] = tanhf(ssc[tid]);
    __syncthreads();

    {
        int j = tid;
        float csum = 0.f, cmax = -3.402823466e38f;
#pragma unroll 4
        for (int r = 0; r < KK; r++) {
            int row = sidx[r];
            float v = Xg[(long)row * 256 + j] * ssc[r];
            Xp[(long)g * KK * 256 + (long)r * 256 + j] = v;
            csum += v;
            cmax = fmaxf(cmax, v);
        }
        readout[(long)g * 1536 + roff + j] = csum;
        readout[(long)g * 1536 + roff + 256 + j] = cmax;
    }

    for (int t = tid; t < KK * KK; t += 256) {
        int r = t / KK, c = t % KK;
        sAn[t] = Ag[(long)sidx[r] * NV + sidx[c]];
    }
    __syncthreads();
    for (int t = tid; t < KK * KK; t += 256) Aout[(long)g * KK * KK + t] = sAn[t];
    if (tid < KK) {
        float d = 0.f;
#pragma unroll
        for (int c = 0; c < KK; c++) d += sAn[tid * KK + c];
        normOut[(long)g * KK + tid] = rsqrtf(fmaxf(d, 1.f));
    }
}

// ====== fused conv + SAGPool for small layers (X never touches gmem) ==========
// X = leaky(A@H * nrm + b);  score = nrm.*(A@(nrm.*(X@Ws))) + bs; topk KK;
// Xp = gather*tanh; readout sum/max; Aout = induced subgraph; normOut.
template <int NN, int KK>
__global__ void fused_conv_pool_kernel(const float* __restrict__ A,
                                       const float* __restrict__ H,
                                       const float* __restrict__ nrm,
                                       const float* __restrict__ bias,
                                       const float* __restrict__ Ws,
                                       const float* __restrict__ bs,
                                       float* __restrict__ Xp,
                                       float* __restrict__ Aout,
                                       float* __restrict__ normOut,
                                       float* __restrict__ readout, int roff)
{
    extern __shared__ float sm[];
    float* sH   = sm;                    // NN*256
    float* sX   = sH + NN * 256;         // NN*256
    float* sAdj = sX + NN * 256;         // NN*NN
    float* sWs  = sAdj + NN * NN;        // 256

    __shared__ float snrm[NN];
    __shared__ float spre[NN];
    __shared__ float ssc[NN];
    __shared__ int   sidx[NN];
    __shared__ float sAn[KK * KK];

    int g = blockIdx.x;
    int tid = threadIdx.x, lane = tid & 31, warp = tid >> 5;

    sWs[tid] = Ws[tid];
    if (tid < NN) snrm[tid] = nrm[(long)g * NN + tid];
    for (int t = tid; t < NN * NN; t += 256) sAdj[t] = A[(long)g * NN * NN + t];
    {
        const float4* Hg = (const float4*)(H + (long)g * NN * 256);
        float4* s4 = (float4*)sH;
        for (int t = tid; t < NN * 64; t += 256) s4[t] = Hg[t];
    }
    __syncthreads();

    // conv: column j = tid
    {
        float bj = bias[tid];
#pragma unroll 4
        for (int i = 0; i < NN; i++) {
            float acc = 0.f;
#pragma unroll
            for (int k = 0; k < NN; k++) acc += sAdj[i * NN + k] * sH[k * 256 + tid];
            float v = acc * snrm[i] + bj;
            sX[i * 256 + tid] = (v > 0.f) ? v : 0.01f * v;
        }
    }
    __syncthreads();

    // spre[r] = nrm[r] * (X[r,:] . Ws)
    for (int r = warp; r < NN; r += 8) {
        float acc = 0.f;
#pragma unroll
        for (int q = lane; q < 256; q += 32) acc += sX[r * 256 + q] * sWs[q];
#pragma unroll
        for (int s = 16; s > 0; s >>= 1) acc += __shfl_down_sync(0xffffffffu, acc, s);
        if (lane == 0) spre[r] = snrm[r] * acc;
    }
    __syncthreads();

    // scores
    if (tid < NN) {
        float acc = 0.f;
#pragma unroll
        for (int q = 0; q < NN; q++) acc += sAdj[tid * NN + q] * spre[q];
        ssc[tid] = snrm[tid] * acc + bs[0];
        sidx[tid] = tid;
    }
    __syncthreads();

    // bitonic sort on NN, descending, ties -> lower index
    for (int ksz = 2; ksz <= NN; ksz <<= 1) {
        for (int j = ksz >> 1; j > 0; j >>= 1) {
            if (tid < NN) {
                int ixj = tid ^ j;
                if (ixj > tid) {
                    float s1 = ssc[tid], s2 = ssc[ixj];
                    int i1 = sidx[tid], i2 = sidx[ixj];
                    bool firstWorse = (s1 < s2) || (s1 == s2 && i1 > i2);
                    bool descRegion = ((tid & ksz) == 0);
                    bool doSwap = descRegion ? firstWorse : !firstWorse;
                    if (doSwap) {
                        ssc[tid] = s2; ssc[ixj] = s1;
                        sidx[tid] = i2; sidx[ixj] = i1;
                    }
                }
            }
            __syncthreads();
        }
    }

    if (tid < KK) ssc[tid] = tanhf(ssc[tid]);
    __syncthreads();

    // gather + gate + readout
    {
        int j = tid;
        float csum = 0.f, cmax = -3.402823466e38f;
#pragma unroll
        for (int r = 0; r < KK; r++) {
            int row = sidx[r];
            float v = sX[row * 256 + j] * ssc[r];
            Xp[(long)g * KK * 256 + (long)r * 256 + j] = v;
            csum += v;
            cmax = fmaxf(cmax, v);
        }
        readout[(long)g * 1536 + roff + j] = csum;
        readout[(long)g * 1536 + roff + 256 + j] = cmax;
    }

    // induced sub-adjacency + next norm
    if (Aout) {
        for (int t = tid; t < KK * KK; t += 256) {
            int r = t / KK, c = t % KK;
            sAn[t] = sAdj[sidx[r] * NN + sidx[c]];
        }
        __syncthreads();
        for (int t = tid; t < KK * KK; t += 256) Aout[(long)g * KK * KK + t] = sAn[t];
        if (tid < KK) {
            float d = 0.f;
#pragma unroll
            for (int c = 0; c < KK; c++) d += sAn[tid * KK + c];
            normOut[(long)g * KK + tid] = rsqrtf(fmaxf(d, 1.f));
        }
    }
}

// ---------------- final head ---------------------------------------------------
__global__ void head_kernel(const float* __restrict__ H, const float* __restrict__ Wd2,
                            const float* __restrict__ bd2, float* __restrict__ out)
{
    int g = blockIdx.x;
    int o = threadIdx.x >> 5;
    int lane = threadIdx.x & 31;
    float acc = 0.f;
#pragma unroll
    for (int k = lane; k < 128; k += 32) acc += H[(long)g * 128 + k] * Wd2[k * 2 + o];
#pragma unroll
    for (int s = 16; s > 0; s >>= 1) acc += __shfl_down_sync(0xffffffffu, acc, s);
    if (lane == 0) {
        float z = acc + bd2[o];
        out[g * 2 + o] = 1.f / (1.f + expf(-z));
    }
}

// --------------------------------- launch --------------------------------------
extern "C" void kernel_launch(void* const* d_in, const int* in_sizes, int n_in,
                              void* d_out, int out_size)
{
    const float* feat = (const float*)d_in[0];
    const float* adj  = (const float*)d_in[1];
    const float* W0   = (const float*)d_in[2];
    const float* b0   = (const float*)d_in[3];
    const float* Ws0  = (const float*)d_in[4];
    const float* bs0  = (const float*)d_in[5];
    const float* W1   = (const float*)d_in[6];
    const float* b1   = (const float*)d_in[7];
    const float* Ws1  = (const float*)d_in[8];
    const float* bs1  = (const float*)d_in[9];
    const float* W2   = (const float*)d_in[10];
    const float* b2   = (const float*)d_in[11];
    const float* Ws2  = (const float*)d_in[12];
    const float* bs2  = (const float*)d_in[13];
    const float* Wd1  = (const float*)d_in[14];
    const float* bd1  = (const float*)d_in[15];
    const float* Wd2  = (const float*)d_in[16];
    const float* bd2  = (const float*)d_in[17];
    float* out = (float*)d_out;

    float *p_norm0, *p_Y, *p_X1, *p_spre, *p_Xp1, *p_A1, *p_norm1, *p_H1;
    float *p_Xp2, *p_A2, *p_norm2, *p_H2, *p_Xp3, *p_read, *p_h;
    unsigned char* p_cols; int* p_cnt;
    cudaGetSymbolAddress((void**)&p_norm0, g_norm0);
    cudaGetSymbolAddress((void**)&p_cols, g_cols);
    cudaGetSymbolAddress((void**)&p_cnt, g_cnt);
    cudaGetSymbolAddress((void**)&p_Y, g_Y);
    cudaGetSymbolAddress((void**)&p_X1, g_X1);
    cudaGetSymbolAddress((void**)&p_spre, g_spre);
    cudaGetSymbolAddress((void**)&p_Xp1, g_Xp1);
    cudaGetSymbolAddress((void**)&p_A1, g_A1);
    cudaGetSymbolAddress((void**)&p_norm1, g_norm1);
    cudaGetSymbolAddress((void**)&p_H1, g_H1);
    cudaGetSymbolAddress((void**)&p_Xp2, g_Xp2);
    cudaGetSymbolAddress((void**)&p_A2, g_A2);
    cudaGetSymbolAddress((void**)&p_norm2, g_norm2);
    cudaGetSymbolAddress((void**)&p_H2, g_H2);
    cudaGetSymbolAddress((void**)&p_Xp3, g_Xp3);
    cudaGetSymbolAddress((void**)&p_read, g_read);
    cudaGetSymbolAddress((void**)&p_h, g_h);

    const int spmmSmem = 65536;
    const int fcp32Smem = (32 * 256 * 2 + 32 * 32 + 256) * 4;   // 69.25 KB
    const int fcp16Smem = (16 * 256 * 2 + 16 * 16 + 256) * 4;   // 34.25 KB
    cudaFuncSetAttribute(spmm_feat_kernel, cudaFuncAttributeMaxDynamicSharedMemorySize, spmmSmem);
    cudaFuncSetAttribute(fused_conv_pool_kernel<32, 16>, cudaFuncAttributeMaxDynamicSharedMemorySize, fcp32Smem);
    cudaFuncSetAttribute(fused_conv_pool_kernel<16, 8>, cudaFuncAttributeMaxDynamicSharedMemorySize, fcp16Smem);

    // ---- layer 0: Y = norm.*(A@(norm.*x)); X1 = leaky(Y@W0 + b0) [+fused dot]
    build_adj_kernel<<<G * NNODE / 8, 256>>>(adj, p_cols, p_cnt, p_norm0);
    spmm_feat_kernel<<<dim3(2, G, 1), 256, spmmSmem>>>(p_cols, p_cnt, feat, p_norm0, p_Y);
    sgemm_kernel<<<dim3(2, 2048, 1), 256>>>(p_Y, W0, p_X1, G * NNODE, DH, FIN,
                                            0, 0, 0, nullptr, 0, nullptr, 0, b0, 1,
                                            Ws0, p_spre);
    pool_kernel<256, 32><<<G, 256>>>(p_X1, adj, p_norm0, bs0, p_cols, p_cnt,
                                     p_spre, p_Xp1, p_A1, p_norm1, p_read, 0);
    // ---- layer 1
    sgemm_kernel<<<dim3(2, 256, 1), 256>>>(p_Xp1, W1, p_H1, G * 32, DH, DH,
                                           0, 0, 0, p_norm1, 0, nullptr, 0, nullptr, 0,
                                           nullptr, nullptr);
    fused_conv_pool_kernel<32, 16><<<G, 256, fcp32Smem>>>(p_A1, p_H1, p_norm1, b1,
                                                          Ws1, bs1, p_Xp2, p_A2,
                                                          p_norm2, p_read, 512);
    // ---- layer 2
    sgemm_kernel<<<dim3(2, 128, 1), 256>>>(p_Xp2, W2, p_H2, G * 16, DH, DH,
                                           0, 0, 0, p_norm2, 0, nullptr, 0, nullptr, 0,
                                           nullptr, nullptr);
    fused_conv_pool_kernel<16, 8><<<G, 256, fcp16Smem>>>(p_A2, p_H2, p_norm2, b2,
                                                         Ws2, bs2, p_Xp3, nullptr,
                                                         nullptr, p_read, 1024);
    // ---- MLP head
    sgemm_kernel<<<dim3(1, 8, 1), 256>>>(p_read, Wd1, p_h, G, 128, 1536,
                                         0, 0, 0, nullptr, 0, nullptr, 0, bd1, 1,
                                         nullptr, nullptr);
    head_kernel<<<G, 64>>>(p_h, Wd2, bd2, out);
}

// round 7
// speedup vs baseline: 1.2486x; 1.2486x over previous
#include <cuda_runtime.h>
#include <math.h>

#define G 1024
#define NNODE 256
#define FIN 128
#define DH 256
#define MAXD 128

// ---------------- scratch (device globals; no allocations allowed) -------------
__device__ float g_norm0[G * NNODE];
__device__ unsigned char g_cols[(long)G * NNODE * MAXD];
__device__ int   g_cnt [G * NNODE];
__device__ float g_Y  [G * NNODE * FIN];    // norm.*(A@(norm.*x))
__device__ float g_X1 [G * NNODE * DH];
__device__ float g_spre[2 * G * NNODE];     // partial X1·Ws0 dots (one per bn block)
__device__ float g_Xp1[G * 32 * DH];
__device__ float g_A1 [G * 32 * 32];
__device__ float g_norm1[G * 32];
__device__ float g_H1 [G * 32 * DH];
__device__ float g_X2 [G * 32 * DH];
__device__ float g_Xp2[G * 16 * DH];
__device__ float g_A2 [G * 16 * 16];
__device__ float g_norm2[G * 16];
__device__ float g_H2 [G * 16 * DH];
__device__ float g_X3 [G * 16 * DH];
__device__ float g_Xp3[G * 8 * DH];
__device__ float g_read[G * 1536];

// ---------------- build sparse adjacency lists + degree norm -------------------
__global__ void build_adj_kernel(const float* __restrict__ adj,
                                 unsigned char* __restrict__ cols,
                                 int* __restrict__ cnt, float* __restrict__ nrm)
{
    int row  = blockIdx.x * 8 + (threadIdx.x >> 5);
    int lane = threadIdx.x & 31;
    const float* a = adj + (long)row * 256;
    unsigned char* lst = cols + (long)row * MAXD;
    int base = 0;
#pragma unroll
    for (int c = 0; c < 8; c++) {
        float v = a[c * 32 + lane];
        unsigned m = __ballot_sync(0xffffffffu, v != 0.f);
        if (v != 0.f) {
            int pos = base + __popc(m & ((1u << lane) - 1));
            if (pos < MAXD) lst[pos] = (unsigned char)(c * 32 + lane);
        }
        base += __popc(m);
    }
    if (lane == 0) {
        cnt[row] = (base > MAXD) ? MAXD : base;
        nrm[row] = rsqrtf(fmaxf((float)base, 1.f));
    }
}

// ------- layer-0 sparse aggregation in INPUT space (128 cols) ------------------
__global__ void spmm_feat_kernel(const unsigned char* __restrict__ cols,
                                 const int* __restrict__ cnt,
                                 const float* __restrict__ feat,
                                 const float* __restrict__ nrm,
                                 float* __restrict__ Y)
{
    extern __shared__ float sX[];                 // [256][128] = 128 KB
    __shared__ unsigned char sCols[256 * MAXD];   // 32 KB
    __shared__ int   scnt[256];
    __shared__ float snrm[256];

    int g = blockIdx.x, tid = threadIdx.x;
    scnt[tid] = cnt[g * 256 + tid];
    snrm[tid] = nrm[g * 256 + tid];
    __syncthreads();

    {
        const float4* Xg = (const float4*)(feat + (long)g * 32768);
        float4* s4 = (float4*)sX;
        for (int t = tid; t < 8192; t += 256) {
            int r = t >> 5;
            float4 v = Xg[t];
            float s = snrm[r];
            v.x *= s; v.y *= s; v.z *= s; v.w *= s;
            s4[t] = v;
        }
        const uint4* gc = (const uint4*)(cols + (long)g * 256 * MAXD);
        uint4* sc = (uint4*)sCols;
        for (int t = tid; t < 2048; t += 256) sc[t] = gc[t];
    }
    __syncthreads();

    int col4 = tid & 31;
    int rg   = tid >> 5;
    for (int i = rg; i < 256; i += 8) {
        int d = scnt[i];
        const unsigned char* lst = &sCols[i * MAXD];
        float a0 = 0.f, a1 = 0.f, a2 = 0.f, a3 = 0.f;
        int k = 0;
        for (; k + 4 <= d; k += 4) {
            unsigned w = *(const unsigned*)(lst + k);
            int j0 = w & 255, j1 = (w >> 8) & 255, j2 = (w >> 16) & 255, j3 = w >> 24;
            float4 h0 = *(const float4*)(sX + j0 * 128 + col4 * 4);
            float4 h1 = *(const float4*)(sX + j1 * 128 + col4 * 4);
            float4 h2 = *(const float4*)(sX + j2 * 128 + col4 * 4);
            float4 h3 = *(const float4*)(sX + j3 * 128 + col4 * 4);
            a0 += h0.x + h1.x + h2.x + h3.x;
            a1 += h0.y + h1.y + h2.y + h3.y;
            a2 += h0.z + h1.z + h2.z + h3.z;
            a3 += h0.w + h1.w + h2.w + h3.w;
        }
        for (; k < d; k++) {
            int j = lst[k];
            float4 h = *(const float4*)(sX + j * 128 + col4 * 4);
            a0 += h.x; a1 += h.y; a2 += h.z; a3 += h.w;
        }
        float nr = snrm[i];
        *(float4*)(Y + (long)g * 32768 + (long)i * 128 + col4 * 4) =
            make_float4(a0 * nr, a1 * nr, a2 * nr, a3 * nr);
    }
}

// ---------------- dense scalar SGEMM + optional fused score-dot ----------------
#define BM 128
#define BN 128
#define BK 8

__global__ void sgemm_kernel(const float* __restrict__ A, const float* __restrict__ B,
                             float* __restrict__ C,
                             int M, int N, int K,
                             long bA, long bB, long bC,
                             const float* __restrict__ rsA, int rsAstride,
                             const float* __restrict__ rsC, int rsCstride,
                             const float* __restrict__ bias, int leaky,
                             const float* __restrict__ Wsp, float* __restrict__ spreOut)
{
    int g = blockIdx.z;
    const float* Ag = A + (long)g * bA;
    const float* Bg = B + (long)g * bB;
    float* Cg = C + (long)g * bC;
    const float* rsAg = rsA ? rsA + (long)g * rsAstride : nullptr;
    const float* rsCg = rsC ? rsC + (long)g * rsCstride : nullptr;

    int bm = blockIdx.y * BM;
    int bn = blockIdx.x * BN;

    __shared__ __align__(16) float sA[BK][BM + 4];
    __shared__ __align__(16) float sB[BK][BN + 4];

    int tid = threadIdx.x;
    int a_row = tid >> 1;
    int a_col = (tid & 1) * 4;
    int b_row = tid >> 5;
    int b_col = (tid & 31) * 4;
    int tr = tid >> 4;
    int tc = tid & 15;

    float acc[8][8];
#pragma unroll
    for (int i = 0; i < 8; i++)
#pragma unroll
        for (int j = 0; j < 8; j++) acc[i][j] = 0.f;

    float aScale = rsAg ? rsAg[bm + a_row] : 1.f;

    for (int k0 = 0; k0 < K; k0 += BK) {
        float4 av = *(const float4*)(Ag + (long)(bm + a_row) * K + k0 + a_col);
        av.x *= aScale; av.y *= aScale; av.z *= aScale; av.w *= aScale;
        sA[a_col + 0][a_row] = av.x;
        sA[a_col + 1][a_row] = av.y;
        sA[a_col + 2][a_row] = av.z;
        sA[a_col + 3][a_row] = av.w;
        float4 bv = *(const float4*)(Bg + (long)(k0 + b_row) * N + bn + b_col);
        *(float4*)&sB[b_row][b_col] = bv;
        __syncthreads();
#pragma unroll
        for (int k = 0; k < BK; k++) {
            float4 a0 = *(const float4*)&sA[k][tr * 4];
            float4 a1 = *(const float4*)&sA[k][tr * 4 + 64];
            float4 b0 = *(const float4*)&sB[k][tc * 4];
            float4 b1 = *(const float4*)&sB[k][tc * 4 + 64];
            float ar[8] = {a0.x, a0.y, a0.z, a0.w, a1.x, a1.y, a1.z, a1.w};
            float br[8] = {b0.x, b0.y, b0.z, b0.w, b1.x, b1.y, b1.z, b1.w};
#pragma unroll
            for (int i = 0; i < 8; i++)
#pragma unroll
                for (int j = 0; j < 8; j++) acc[i][j] += ar[i] * br[j];
        }
        __syncthreads();
    }

#pragma unroll
    for (int i = 0; i < 8; i++) {
        int row = bm + ((i < 4) ? (tr * 4 + i) : (64 + tr * 4 + i - 4));
        float rs = rsCg ? rsCg[row] : 1.f;
        float rd = 0.f;
#pragma unroll
        for (int jg = 0; jg < 2; jg++) {
            int col = bn + tc * 4 + jg * 64;
            float v[4];
#pragma unroll
            for (int jj = 0; jj < 4; jj++) {
                float c = acc[i][jg * 4 + jj] * rs;
                if (bias) c += bias[col + jj];
                if (leaky) c = (c > 0.f) ? c : 0.01f * c;
                v[jj] = c;
                if (Wsp) rd += c * __ldg(&Wsp[col + jj]);
            }
            float4 o = make_float4(v[0], v[1], v[2], v[3]);
            *(float4*)(Cg + (long)row * N + col) = o;
        }
        if (Wsp) {
#pragma unroll
            for (int s = 8; s > 0; s >>= 1)
                rd += __shfl_xor_sync(0xffffffffu, rd, s);
            if (tc == 0) spreOut[(long)blockIdx.x * M + row] = rd;
        }
    }
}

// ---------------- small batched conv: X = leaky(adj@H * norm + b) ---------------
template <int NN>
__global__ void conv_small_kernel(const float* __restrict__ A, const float* __restrict__ H,
                                  const float* __restrict__ nrm, const float* __restrict__ bias,
                                  float* __restrict__ X)
{
    int g = blockIdx.x;
    __shared__ float sAdj[NN][NN + 1];
    __shared__ float sH[NN][256];
    const float* Ag = A + (long)g * NN * NN;
    const float* Hg = H + (long)g * NN * 256;
    int tid = threadIdx.x;
    for (int t = tid; t < NN * NN; t += 256) sAdj[t / NN][t % NN] = Ag[t];
    for (int t = tid; t < NN * 256; t += 256) sH[t / 256][t % 256] = Hg[t];
    __syncthreads();
    int j = tid;
    float bj = bias[j];
#pragma unroll 4
    for (int i = 0; i < NN; i++) {
        float acc = 0.f;
#pragma unroll
        for (int k = 0; k < NN; k++) acc += sAdj[i][k] * sH[k][j];
        float v = acc * nrm[(long)g * NN + i] + bj;
        X[(long)g * NN * 256 + (long)i * 256 + j] = (v > 0.f) ? v : 0.01f * v;
    }
}

// ---------------- SAGPool (round-5 proven version) -----------------------------
template <int NV, int KK>
__global__ void pool_kernel(const float* __restrict__ X, const float* __restrict__ A,
                            const float* __restrict__ nrm,
                            const float* __restrict__ Ws, const float* __restrict__ bs,
                            const unsigned char* __restrict__ colsL,
                            const int* __restrict__ cntL,
                            const float* __restrict__ spreParts,
                            float* __restrict__ Xp, float* __restrict__ Aout,
                            float* __restrict__ normOut, float* __restrict__ readout,
                            int roff)
{
    int g = blockIdx.x;
    const float* Xg = X + (long)g * NV * 256;
    const float* Ag = A + (long)g * NV * NV;
    const float* ng = nrm + (long)g * NV;

    __shared__ float sWs[256];
    __shared__ float spre[NV];
    __shared__ float ssc[NV];
    __shared__ int   sidx[NV];
    __shared__ float sAn[KK * KK];

    int tid = threadIdx.x, lane = tid & 31, warp = tid >> 5;

    if (spreParts) {
        if (tid < NV)
            spre[tid] = (spreParts[(long)g * NV + tid] +
                         spreParts[(long)G * NNODE + (long)g * NV + tid]) * ng[tid];
        __syncthreads();
    } else {
        sWs[tid] = Ws[tid];
        __syncthreads();
        for (int r = warp; r < NV; r += 8) {
            float acc = 0.f;
            for (int q = lane; q < 256; q += 32) acc += Xg[(long)r * 256 + q] * sWs[q];
#pragma unroll
            for (int s = 16; s > 0; s >>= 1) acc += __shfl_down_sync(0xffffffffu, acc, s);
            if (lane == 0) spre[r] = ng[r] * acc;
        }
        __syncthreads();
    }

    float bsv = bs[0];
    if (colsL) {
        for (int r = warp; r < NV; r += 8) {
            int d = cntL[g * NV + r];
            const unsigned char* lst = colsL + ((long)g * NV + r) * MAXD;
            float acc = 0.f;
            for (int q = lane; q < d; q += 32) acc += spre[lst[q]];
#pragma unroll
            for (int s = 16; s > 0; s >>= 1) acc += __shfl_down_sync(0xffffffffu, acc, s);
            if (lane == 0) { ssc[r] = ng[r] * acc + bsv; sidx[r] = r; }
        }
    } else {
        for (int r = warp; r < NV; r += 8) {
            float acc = 0.f;
            for (int q = lane; q < NV; q += 32) acc += Ag[(long)r * NV + q] * spre[q];
#pragma unroll
            for (int s = 16; s > 0; s >>= 1) acc += __shfl_down_sync(0xffffffffu, acc, s);
            if (lane == 0) { ssc[r] = ng[r] * acc + bsv; sidx[r] = r; }
        }
    }
    __syncthreads();

    for (int ksz = 2; ksz <= NV; ksz <<= 1) {
        for (int j = ksz >> 1; j > 0; j >>= 1) {
            if (tid < NV) {
                int ixj = tid ^ j;
                if (ixj > tid) {
                    float s1 = ssc[tid], s2 = ssc[ixj];
                    int i1 = sidx[tid], i2 = sidx[ixj];
                    bool firstWorse = (s1 < s2) || (s1 == s2 && i1 > i2);
                    bool descRegion = ((tid & ksz) == 0);
                    bool doSwap = descRegion ? firstWorse : !firstWorse;
                    if (doSwap) {
                        ssc[tid] = s2; ssc[ixj] = s1;
                        sidx[tid] = i2; sidx[ixj] = i1;
                    }
                }
            }
            __syncthreads();
        }
    }

    if (tid < KK) ssc[tid] = tanhf(ssc[tid]);
    __syncthreads();

    {
        int j = tid;
        float csum = 0.f, cmax = -3.402823466e38f;
#pragma unroll 4
        for (int r = 0; r < KK; r++) {
            int row = sidx[r];
            float v = Xg[(long)row * 256 + j] * ssc[r];
            Xp[(long)g * KK * 256 + (long)r * 256 + j] = v;
            csum += v;
            cmax = fmaxf(cmax, v);
        }
        readout[(long)g * 1536 + roff + j] = csum;
        readout[(long)g * 1536 + roff + 256 + j] = cmax;
    }

    if (Aout) {
        for (int t = tid; t < KK * KK; t += 256) {
            int r = t / KK, c = t % KK;
            sAn[t] = Ag[(long)sidx[r] * NV + sidx[c]];
        }
        __syncthreads();
        for (int t = tid; t < KK * KK; t += 256) Aout[(long)g * KK * KK + t] = sAn[t];
        if (tid < KK) {
            float d = 0.f;
#pragma unroll
            for (int c = 0; c < KK; c++) d += sAn[tid * KK + c];
            normOut[(long)g * KK + tid] = rsqrtf(fmaxf(d, 1.f));
        }
    }
}

// ====== fused MLP head: out = sigmoid(leaky(read@Wd1+bd1)@Wd2+bd2) =============
// 256 blocks x 4 graphs; 8 warps split K=1536 into 192-chunks (split-K),
// Wd1 streamed once per block via LDG.128; smem reduce; warp dots for layer 2.
__global__ void __launch_bounds__(256) mlp_head_kernel(
    const float* __restrict__ read, const float* __restrict__ Wd1,
    const float* __restrict__ bd1, const float* __restrict__ Wd2,
    const float* __restrict__ bd2, float* __restrict__ out)
{
    extern __shared__ float sm[];
    float* sR = sm;                 // [4][1536]
    float* sP = sm + 4 * 1536;      // [8][4][128] split-K partials
    float* sH = sP;                 // reuse after reduce: [4][128]

    int tid = threadIdx.x;
    int g0 = blockIdx.x * 4;
    int lane = tid & 31, kw = tid >> 5;

    // stage 4 readout rows (coalesced float4)
    {
        const float4* src = (const float4*)(read + (long)g0 * 1536);
        float4* d4 = (float4*)sR;
#pragma unroll
        for (int i = 0; i < 6; i++) d4[tid + i * 256] = src[tid + i * 256];
    }
    __syncthreads();

    // split-K accumulate: warp kw covers k in [kw*192, kw*192+192)
    float4 acc[4];
#pragma unroll
    for (int gg = 0; gg < 4; gg++) acc[gg] = make_float4(0.f, 0.f, 0.f, 0.f);
    {
        const float4* W14 = (const float4*)Wd1;
        int kbeg = kw * 192;
#pragma unroll 2
        for (int k = kbeg; k < kbeg + 192; k++) {
            float4 wd = __ldg(&W14[k * 32 + lane]);
#pragma unroll
            for (int gg = 0; gg < 4; gg++) {
                float rv = sR[gg * 1536 + k];
                acc[gg].x += rv * wd.x;
                acc[gg].y += rv * wd.y;
                acc[gg].z += rv * wd.z;
                acc[gg].w += rv * wd.w;
            }
        }
    }
#pragma unroll
    for (int gg = 0; gg < 4; gg++)
        ((float4*)sP)[(kw * 4 + gg) * 32 + lane] = acc[gg];
    __syncthreads();

    // reduce split-K (fixed order), bias, leaky -> sH[4][128]
    // 512 outputs / 256 threads: 2 per thread
#pragma unroll
    for (int rep = 0; rep < 2; rep++) {
        int idx = tid + rep * 256;        // [0,512)
        int gg = idx >> 7, j = idx & 127;
        float s = 0.f;
#pragma unroll
        for (int w = 0; w < 8; w++) s += sP[(w * 4 + gg) * 128 + j];
        s += bd1[j];
        s = (s > 0.f) ? s : 0.01f * s;
        // write into a disjoint region (after all reads): stash in registers first
        acc[0].x = s;                     // reuse reg
        __syncthreads();                  // all reads of sP done before overwrite
        sH[gg * 128 + j] = acc[0].x;
        __syncthreads();
    }

    // layer 2: warps 0-3 -> graphs 0-3; both outputs per warp
    if (kw < 4) {
        float a0 = 0.f, a1 = 0.f;
#pragma unroll
        for (int c = 0; c < 4; c++) {
            int k = lane + c * 32;
            float h = sH[kw * 128 + k];
            a0 += h * Wd2[k * 2 + 0];
            a1 += h * Wd2[k * 2 + 1];
        }
#pragma unroll
        for (int s = 16; s > 0; s >>= 1) {
            a0 += __shfl_down_sync(0xffffffffu, a0, s);
            a1 += __shfl_down_sync(0xffffffffu, a1, s);
        }
        if (lane == 0) {
            out[(g0 + kw) * 2 + 0] = 1.f / (1.f + expf(-(a0 + bd2[0])));
            out[(g0 + kw) * 2 + 1] = 1.f / (1.f + expf(-(a1 + bd2[1])));
        }
    }
}

// --------------------------------- launch --------------------------------------
extern "C" void kernel_launch(void* const* d_in, const int* in_sizes, int n_in,
                              void* d_out, int out_size)
{
    const float* feat = (const float*)d_in[0];
    const float* adj  = (const float*)d_in[1];
    const float* W0   = (const float*)d_in[2];
    const float* b0   = (const float*)d_in[3];
    const float* Ws0  = (const float*)d_in[4];
    const float* bs0  = (const float*)d_in[5];
    const float* W1   = (const float*)d_in[6];
    const float* b1   = (const float*)d_in[7];
    const float* Ws1  = (const float*)d_in[8];
    const float* bs1  = (const float*)d_in[9];
    const float* W2   = (const float*)d_in[10];
    const float* b2   = (const float*)d_in[11];
    const float* Ws2  = (const float*)d_in[12];
    const float* bs2  = (const float*)d_in[13];
    const float* Wd1  = (const float*)d_in[14];
    const float* bd1  = (const float*)d_in[15];
    const float* Wd2  = (const float*)d_in[16];
    const float* bd2  = (const float*)d_in[17];
    float* out = (float*)d_out;

    float *p_norm0, *p_Y, *p_X1, *p_spre, *p_Xp1, *p_A1, *p_norm1, *p_H1, *p_X2;
    float *p_Xp2, *p_A2, *p_norm2, *p_H2, *p_X3, *p_Xp3, *p_read;
    unsigned char* p_cols; int* p_cnt;
    cudaGetSymbolAddress((void**)&p_norm0, g_norm0);
    cudaGetSymbolAddress((void**)&p_cols, g_cols);
    cudaGetSymbolAddress((void**)&p_cnt, g_cnt);
    cudaGetSymbolAddress((void**)&p_Y, g_Y);
    cudaGetSymbolAddress((void**)&p_X1, g_X1);
    cudaGetSymbolAddress((void**)&p_spre, g_spre);
    cudaGetSymbolAddress((void**)&p_Xp1, g_Xp1);
    cudaGetSymbolAddress((void**)&p_A1, g_A1);
    cudaGetSymbolAddress((void**)&p_norm1, g_norm1);
    cudaGetSymbolAddress((void**)&p_H1, g_H1);
    cudaGetSymbolAddress((void**)&p_X2, g_X2);
    cudaGetSymbolAddress((void**)&p_Xp2, g_Xp2);
    cudaGetSymbolAddress((void**)&p_A2, g_A2);
    cudaGetSymbolAddress((void**)&p_norm2, g_norm2);
    cudaGetSymbolAddress((void**)&p_H2, g_H2);
    cudaGetSymbolAddress((void**)&p_X3, g_X3);
    cudaGetSymbolAddress((void**)&p_Xp3, g_Xp3);
    cudaGetSymbolAddress((void**)&p_read, g_read);

    const int headSmem = (4 * 1536 + 8 * 4 * 128) * 4;   // 40 KB
    cudaFuncSetAttribute(spmm_feat_kernel, cudaFuncAttributeMaxDynamicSharedMemorySize, 131072);
    cudaFuncSetAttribute(mlp_head_kernel, cudaFuncAttributeMaxDynamicSharedMemorySize, headSmem);

    // ---- layer 0: Y = norm.*(A@(norm.*x)); X1 = leaky(Y@W0 + b0) [+fused dot]
    build_adj_kernel<<<G * NNODE / 8, 256>>>(adj, p_cols, p_cnt, p_norm0);
    spmm_feat_kernel<<<G, 256, 131072>>>(p_cols, p_cnt, feat, p_norm0, p_Y);
    sgemm_kernel<<<dim3(2, 2048, 1), 256>>>(p_Y, W0, p_X1, G * NNODE, DH, FIN,
                                            0, 0, 0, nullptr, 0, nullptr, 0, b0, 1,
                                            Ws0, p_spre);
    pool_kernel<256, 32><<<G, 256>>>(p_X1, adj, p_norm0, Ws0, bs0, p_cols, p_cnt,
                                     p_spre, p_Xp1, p_A1, p_norm1, p_read, 0);
    // ---- layer 1
    sgemm_kernel<<<dim3(2, 256, 1), 256>>>(p_Xp1, W1, p_H1, G * 32, DH, DH,
                                           0, 0, 0, p_norm1, 0, nullptr, 0, nullptr, 0,
                                           nullptr, nullptr);
    conv_small_kernel<32><<<G, 256>>>(p_A1, p_H1, p_norm1, b1, p_X2);
    pool_kernel<32, 16><<<G, 256>>>(p_X2, p_A1, p_norm1, Ws1, bs1, nullptr, nullptr,
                                    nullptr, p_Xp2, p_A2, p_norm2, p_read, 512);
    // ---- layer 2
    sgemm_kernel<<<dim3(2, 128, 1), 256>>>(p_Xp2, W2, p_H2, G * 16, DH, DH,
                                           0, 0, 0, p_norm2, 0, nullptr, 0, nullptr, 0,
                                           nullptr, nullptr);
    conv_small_kernel<16><<<G, 256>>>(p_A2, p_H2, p_norm2, b2, p_X3);
    pool_kernel<16, 8><<<G, 256>>>(p_X3, p_A2, p_norm2, Ws2, bs2, nullptr, nullptr,
                                   nullptr, p_Xp3, nullptr, nullptr, p_read, 1024);
    // ---- fused MLP head
    mlp_head_kernel<<<G / 4, 256, headSmem>>>(p_read, Wd1, bd1, Wd2, bd2, out);
}

// round 8
// speedup vs baseline: 1.2582x; 1.0077x over previous
#include <cuda_runtime.h>
#include <cuda_bf16.h>
#include <mma.h>
#include <math.h>

using namespace nvcuda;

#define G 1024
#define NNODE 256
#define FIN 128
#define DH 256
#define MAXD 128

// ---------------- scratch (device globals; no allocations allowed) -------------
__device__ float g_norm0[G * NNODE];
__device__ unsigned char g_cols[(long)G * NNODE * MAXD];
__device__ int   g_cnt [G * NNODE];
__device__ __nv_bfloat16 g_Yh[(long)G * NNODE * FIN];
__device__ __nv_bfloat16 g_Yl[(long)G * NNODE * FIN];
__device__ __nv_bfloat16 g_W0h[FIN * DH];
__device__ __nv_bfloat16 g_W0l[FIN * DH];
__device__ float g_X1 [G * NNODE * DH];
__device__ float g_spre[2 * G * NNODE];
__device__ float g_Xp1[G * 32 * DH];
__device__ float g_A1 [G * 32 * 32];
__device__ float g_norm1[G * 32];
__device__ float g_H1 [G * 32 * DH];
__device__ float g_X2 [G * 32 * DH];
__device__ float g_Xp2[G * 16 * DH];
__device__ float g_A2 [G * 16 * 16];
__device__ float g_norm2[G * 16];
__device__ float g_H2 [G * 16 * DH];
__device__ float g_X3 [G * 16 * DH];
__device__ float g_Xp3[G * 8 * DH];
__device__ float g_read[G * 1536];

// ---------------- build sparse adjacency lists + degree norm -------------------
__global__ void build_adj_kernel(const float* __restrict__ adj,
                                 unsigned char* __restrict__ cols,
                                 int* __restrict__ cnt, float* __restrict__ nrm)
{
    int row  = blockIdx.x * 8 + (threadIdx.x >> 5);
    int lane = threadIdx.x & 31;
    const float* a = adj + (long)row * 256;
    unsigned char* lst = cols + (long)row * MAXD;
    int base = 0;
#pragma unroll
    for (int c = 0; c < 8; c++) {
        float v = a[c * 32 + lane];
        unsigned m = __ballot_sync(0xffffffffu, v != 0.f);
        if (v != 0.f) {
            int pos = base + __popc(m & ((1u << lane) - 1));
            if (pos < MAXD) lst[pos] = (unsigned char)(c * 32 + lane);
        }
        base += __popc(m);
    }
    if (lane == 0) {
        cnt[row] = (base > MAXD) ? MAXD : base;
        nrm[row] = rsqrtf(fmaxf((float)base, 1.f));
    }
}

// ---------------- split W0 into bf16 hi/lo -------------------------------------
__global__ void split_w_kernel(const float* __restrict__ W,
                               __nv_bfloat16* __restrict__ Wh,
                               __nv_bfloat16* __restrict__ Wl, int n)
{
    int i = blockIdx.x * 256 + threadIdx.x;
    if (i < n) {
        float v = W[i];
        __nv_bfloat16 h = __float2bfloat16_rn(v);
        Wh[i] = h;
        Wl[i] = __float2bfloat16_rn(v - __bfloat162float(h));
    }
}

// ------- layer-0 sparse aggregation in INPUT space; emits bf16 hi/lo -----------
__global__ void spmm_feat_kernel(const unsigned char* __restrict__ cols,
                                 const int* __restrict__ cnt,
                                 const float* __restrict__ feat,
                                 const float* __restrict__ nrm,
                                 __nv_bfloat16* __restrict__ Yh,
                                 __nv_bfloat16* __restrict__ Yl)
{
    extern __shared__ float sX[];                 // [256][128] = 128 KB
    __shared__ unsigned char sCols[256 * MAXD];   // 32 KB
    __shared__ int   scnt[256];
    __shared__ float snrm[256];

    int g = blockIdx.x, tid = threadIdx.x;
    scnt[tid] = cnt[g * 256 + tid];
    snrm[tid] = nrm[g * 256 + tid];
    __syncthreads();

    {
        const float4* Xg = (const float4*)(feat + (long)g * 32768);
        float4* s4 = (float4*)sX;
        for (int t = tid; t < 8192; t += 256) {
            int r = t >> 5;
            float4 v = Xg[t];
            float s = snrm[r];
            v.x *= s; v.y *= s; v.z *= s; v.w *= s;
            s4[t] = v;
        }
        const uint4* gc = (const uint4*)(cols + (long)g * 256 * MAXD);
        uint4* sc = (uint4*)sCols;
        for (int t = tid; t < 2048; t += 256) sc[t] = gc[t];
    }
    __syncthreads();

    int col4 = tid & 31;
    int rg   = tid >> 5;
    for (int i = rg; i < 256; i += 8) {
        int d = scnt[i];
        const unsigned char* lst = &sCols[i * MAXD];
        float a0 = 0.f, a1 = 0.f, a2 = 0.f, a3 = 0.f;
        int k = 0;
        for (; k + 4 <= d; k += 4) {
            unsigned w = *(const unsigned*)(lst + k);
            int j0 = w & 255, j1 = (w >> 8) & 255, j2 = (w >> 16) & 255, j3 = w >> 24;
            float4 h0 = *(const float4*)(sX + j0 * 128 + col4 * 4);
            float4 h1 = *(const float4*)(sX + j1 * 128 + col4 * 4);
            float4 h2 = *(const float4*)(sX + j2 * 128 + col4 * 4);
            float4 h3 = *(const float4*)(sX + j3 * 128 + col4 * 4);
            a0 += h0.x + h1.x + h2.x + h3.x;
            a1 += h0.y + h1.y + h2.y + h3.y;
            a2 += h0.z + h1.z + h2.z + h3.z;
            a3 += h0.w + h1.w + h2.w + h3.w;
        }
        for (; k < d; k++) {
            int j = lst[k];
            float4 h = *(const float4*)(sX + j * 128 + col4 * 4);
            a0 += h.x; a1 += h.y; a2 += h.z; a3 += h.w;
        }
        float nr = snrm[i];
        float o0 = a0 * nr, o1 = a1 * nr, o2 = a2 * nr, o3 = a3 * nr;
        __nv_bfloat16 h0 = __float2bfloat16_rn(o0);
        __nv_bfloat16 h1 = __float2bfloat16_rn(o1);
        __nv_bfloat16 h2 = __float2bfloat16_rn(o2);
        __nv_bfloat16 h3 = __float2bfloat16_rn(o3);
        long base = (long)g * 32768 + (long)i * 128 + col4 * 4;
        *(__nv_bfloat162*)(Yh + base)     = __nv_bfloat162(h0, h1);
        *(__nv_bfloat162*)(Yh + base + 2) = __nv_bfloat162(h2, h3);
        *(__nv_bfloat162*)(Yl + base) = __nv_bfloat162(
            __float2bfloat16_rn(o0 - __bfloat162float(h0)),
            __float2bfloat16_rn(o1 - __bfloat162float(h1)));
        *(__nv_bfloat162*)(Yl + base + 2) = __nv_bfloat162(
            __float2bfloat16_rn(o2 - __bfloat162float(h2)),
            __float2bfloat16_rn(o3 - __bfloat162float(h3)));
    }
}

// ===== bf16 wmma 3-chain GEMM: X1 = leaky(Y@W0 + b0), fused Ws0 dot ============
// grid (2, 2048), 256 threads (8 warps, 2x4), warp tile 64x32, BK=32.
#define WAL 40     // A smem row stride (elems)
#define WBL 136    // B smem row stride (elems)

__global__ void __launch_bounds__(256) wmma_feat_kernel(
    const __nv_bfloat16* __restrict__ Yh, const __nv_bfloat16* __restrict__ Yl,
    const __nv_bfloat16* __restrict__ Wh, const __nv_bfloat16* __restrict__ Wl,
    const float* __restrict__ bias, const float* __restrict__ Wsp,
    float* __restrict__ X1, float* __restrict__ spreOut)
{
    extern __shared__ char smem[];
    __nv_bfloat16* sAh = (__nv_bfloat16*)smem;      // [128][WAL]
    __nv_bfloat16* sAl = sAh + 128 * WAL;
    __nv_bfloat16* sBh = sAl + 128 * WAL;           // [32][WBL]
    __nv_bfloat16* sBl = sBh + 32 * WBL;
    float* sC = (float*)smem;                       // [128][128] (reused)

    int tid = threadIdx.x, warp = tid >> 5;
    int bm = blockIdx.y * 128, bn = blockIdx.x * 128;
    int wm = warp >> 2, wn = warp & 3;

    wmma::fragment<wmma::accumulator, 16, 16, 16, float> acc[4][2];
#pragma unroll
    for (int i = 0; i < 4; i++)
#pragma unroll
        for (int j = 0; j < 2; j++) wmma::fill_fragment(acc[i][j], 0.f);

    for (int k0 = 0; k0 < 128; k0 += 32) {
        // A tile: 128 rows x 32 cols, hi+lo  (512 uint4 each -> 2 per thread)
#pragma unroll
        for (int it = 0; it < 2; it++) {
            int idx = tid + it * 256;
            int r = idx >> 2, c8 = (idx & 3) * 8;
            long gofs = (long)(bm + r) * 128 + k0 + c8;
            *(uint4*)(sAh + r * WAL + c8) = *(const uint4*)(Yh + gofs);
            *(uint4*)(sAl + r * WAL + c8) = *(const uint4*)(Yl + gofs);
        }
        // B tile: 32 rows x 128 cols, hi+lo
#pragma unroll
        for (int it = 0; it < 2; it++) {
            int idx = tid + it * 256;
            int r = idx >> 4, c8 = (idx & 15) * 8;
            long gofs = (long)(k0 + r) * 256 + bn + c8;
            *(uint4*)(sBh + r * WBL + c8) = *(const uint4*)(Wh + gofs);
            *(uint4*)(sBl + r * WBL + c8) = *(const uint4*)(Wl + gofs);
        }
        __syncthreads();

#pragma unroll
        for (int kk = 0; kk < 32; kk += 16) {
            wmma::fragment<wmma::matrix_b, 16, 16, 16, __nv_bfloat16, wmma::row_major> bh[2], bl[2];
#pragma unroll
            for (int j = 0; j < 2; j++) {
                wmma::load_matrix_sync(bh[j], sBh + kk * WBL + wn * 32 + j * 16, WBL);
                wmma::load_matrix_sync(bl[j], sBl + kk * WBL + wn * 32 + j * 16, WBL);
            }
#pragma unroll
            for (int i = 0; i < 4; i++) {
                wmma::fragment<wmma::matrix_a, 16, 16, 16, __nv_bfloat16, wmma::row_major> ah, al;
                wmma::load_matrix_sync(ah, sAh + (wm * 64 + i * 16) * WAL + kk, WAL);
                wmma::load_matrix_sync(al, sAl + (wm * 64 + i * 16) * WAL + kk, WAL);
#pragma unroll
                for (int j = 0; j < 2; j++) {
                    wmma::mma_sync(acc[i][j], ah, bh[j], acc[i][j]);
                    wmma::mma_sync(acc[i][j], ah, bl[j], acc[i][j]);
                    wmma::mma_sync(acc[i][j], al, bh[j], acc[i][j]);
                }
            }
        }
        __syncthreads();
    }

    // stage C through smem (operand tiles dead now)
#pragma unroll
    for (int i = 0; i < 4; i++)
#pragma unroll
        for (int j = 0; j < 2; j++)
            wmma::store_matrix_sync(sC + (wm * 64 + i * 16) * 128 + wn * 32 + j * 16,
                                    acc[i][j], 128, wmma::mem_row_major);
    __syncthreads();

    // epilogue: bias + leaky + fused Ws0 dot; row = tid>>1, 64 cols per thread
    {
        int row = tid >> 1, half = tid & 1;
        int gRow = bm + row;
        float rd = 0.f;
        float* dst = X1 + (long)gRow * 256 + bn + half * 64;
#pragma unroll
        for (int c4 = 0; c4 < 16; c4++) {
            int col = half * 64 + c4 * 4;
            float4 v = *(float4*)(sC + row * 128 + col);
            float4 bv = *(const float4*)(bias + bn + col);
            v.x += bv.x; v.y += bv.y; v.z += bv.z; v.w += bv.w;
            v.x = (v.x > 0.f) ? v.x : 0.01f * v.x;
            v.y = (v.y > 0.f) ? v.y : 0.01f * v.y;
            v.z = (v.z > 0.f) ? v.z : 0.01f * v.z;
            v.w = (v.w > 0.f) ? v.w : 0.01f * v.w;
            float4 wv = *(const float4*)(Wsp + bn + col);
            rd += v.x * wv.x + v.y * wv.y + v.z * wv.z + v.w * wv.w;
            *(float4*)(dst + c4 * 4) = v;
        }
        rd += __shfl_xor_sync(0xffffffffu, rd, 1);
        if (half == 0) spreOut[(long)blockIdx.x * (G * NNODE) + gRow] = rd;
    }
}

// ---------------- dense scalar SGEMM (layers 1/2) ------------------------------
#define BM 128
#define BN 128
#define BK 8

__global__ void sgemm_kernel(const float* __restrict__ A, const float* __restrict__ B,
                             float* __restrict__ C,
                             int M, int N, int K,
                             long bA, long bB, long bC,
                             const float* __restrict__ rsA, int rsAstride,
                             const float* __restrict__ rsC, int rsCstride,
                             const float* __restrict__ bias, int leaky)
{
    int g = blockIdx.z;
    const float* Ag = A + (long)g * bA;
    const float* Bg = B + (long)g * bB;
    float* Cg = C + (long)g * bC;
    const float* rsAg = rsA ? rsA + (long)g * rsAstride : nullptr;
    const float* rsCg = rsC ? rsC + (long)g * rsCstride : nullptr;

    int bm = blockIdx.y * BM;
    int bn = blockIdx.x * BN;

    __shared__ __align__(16) float sA[BK][BM + 4];
    __shared__ __align__(16) float sB[BK][BN + 4];

    int tid = threadIdx.x;
    int a_row = tid >> 1;
    int a_col = (tid & 1) * 4;
    int b_row = tid >> 5;
    int b_col = (tid & 31) * 4;
    int tr = tid >> 4;
    int tc = tid & 15;

    float acc[8][8];
#pragma unroll
    for (int i = 0; i < 8; i++)
#pragma unroll
        for (int j = 0; j < 8; j++) acc[i][j] = 0.f;

    float aScale = rsAg ? rsAg[bm + a_row] : 1.f;

    for (int k0 = 0; k0 < K; k0 += BK) {
        float4 av = *(const float4*)(Ag + (long)(bm + a_row) * K + k0 + a_col);
        av.x *= aScale; av.y *= aScale; av.z *= aScale; av.w *= aScale;
        sA[a_col + 0][a_row] = av.x;
        sA[a_col + 1][a_row] = av.y;
        sA[a_col + 2][a_row] = av.z;
        sA[a_col + 3][a_row] = av.w;
        float4 bv = *(const float4*)(Bg + (long)(k0 + b_row) * N + bn + b_col);
        *(float4*)&sB[b_row][b_col] = bv;
        __syncthreads();
#pragma unroll
        for (int k = 0; k < BK; k++) {
            float4 a0 = *(const float4*)&sA[k][tr * 4];
            float4 a1 = *(const float4*)&sA[k][tr * 4 + 64];
            float4 b0 = *(const float4*)&sB[k][tc * 4];
            float4 b1 = *(const float4*)&sB[k][tc * 4 + 64];
            float ar[8] = {a0.x, a0.y, a0.z, a0.w, a1.x, a1.y, a1.z, a1.w};
            float br[8] = {b0.x, b0.y, b0.z, b0.w, b1.x, b1.y, b1.z, b1.w};
#pragma unroll
            for (int i = 0; i < 8; i++)
#pragma unroll
                for (int j = 0; j < 8; j++) acc[i][j] += ar[i] * br[j];
        }
        __syncthreads();
    }

#pragma unroll
    for (int i = 0; i < 8; i++) {
        int row = bm + ((i < 4) ? (tr * 4 + i) : (64 + tr * 4 + i - 4));
        float rs = rsCg ? rsCg[row] : 1.f;
#pragma unroll
        for (int jg = 0; jg < 2; jg++) {
            int col = bn + tc * 4 + jg * 64;
            float v[4];
#pragma unroll
            for (int jj = 0; jj < 4; jj++) {
                float c = acc[i][jg * 4 + jj] * rs;
                if (bias) c += bias[col + jj];
                if (leaky) c = (c > 0.f) ? c : 0.01f * c;
                v[jj] = c;
            }
            float4 o = make_float4(v[0], v[1], v[2], v[3]);
            *(float4*)(Cg + (long)row * N + col) = o;
        }
    }
}

// ---------------- small batched conv: X = leaky(adj@H * norm + b) ---------------
template <int NN>
__global__ void conv_small_kernel(const float* __restrict__ A, const float* __restrict__ H,
                                  const float* __restrict__ nrm, const float* __restrict__ bias,
                                  float* __restrict__ X)
{
    int g = blockIdx.x;
    __shared__ float sAdj[NN][NN + 1];
    __shared__ float sH[NN][256];
    const float* Ag = A + (long)g * NN * NN;
    const float* Hg = H + (long)g * NN * 256;
    int tid = threadIdx.x;
    for (int t = tid; t < NN * NN; t += 256) sAdj[t / NN][t % NN] = Ag[t];
    for (int t = tid; t < NN * 256; t += 256) sH[t / 256][t % 256] = Hg[t];
    __syncthreads();
    int j = tid;
    float bj = bias[j];
#pragma unroll 4
    for (int i = 0; i < NN; i++) {
        float acc = 0.f;
#pragma unroll
        for (int k = 0; k < NN; k++) acc += sAdj[i][k] * sH[k][j];
        float v = acc * nrm[(long)g * NN + i] + bj;
        X[(long)g * NN * 256 + (long)i * 256 + j] = (v > 0.f) ? v : 0.01f * v;
    }
}

// ---------------- SAGPool (round-5 proven version) -----------------------------
template <int NV, int KK>
__global__ void pool_kernel(const float* __restrict__ X, const float* __restrict__ A,
                            const float* __restrict__ nrm,
                            const float* __restrict__ Ws, const float* __restrict__ bs,
                            const unsigned char* __restrict__ colsL,
                            const int* __restrict__ cntL,
                            const float* __restrict__ spreParts,
                            float* __restrict__ Xp, float* __restrict__ Aout,
                            float* __restrict__ normOut, float* __restrict__ readout,
                            int roff)
{
    int g = blockIdx.x;
    const float* Xg = X + (long)g * NV * 256;
    const float* Ag = A + (long)g * NV * NV;
    const float* ng = nrm + (long)g * NV;

    __shared__ float sWs[256];
    __shared__ float spre[NV];
    __shared__ float ssc[NV];
    __shared__ int   sidx[NV];
    __shared__ float sAn[KK * KK];

    int tid = threadIdx.x, lane = tid & 31, warp = tid >> 5;

    if (spreParts) {
        if (tid < NV)
            spre[tid] = (spreParts[(long)g * NV + tid] +
                         spreParts[(long)G * NNODE + (long)g * NV + tid]) * ng[tid];
        __syncthreads();
    } else {
        sWs[tid] = Ws[tid];
        __syncthreads();
        for (int r = warp; r < NV; r += 8) {
            float acc = 0.f;
            for (int q = lane; q < 256; q += 32) acc += Xg[(long)r * 256 + q] * sWs[q];
#pragma unroll
            for (int s = 16; s > 0; s >>= 1) acc += __shfl_down_sync(0xffffffffu, acc, s);
            if (lane == 0) spre[r] = ng[r] * acc;
        }
        __syncthreads();
    }

    float bsv = bs[0];
    if (colsL) {
        for (int r = warp; r < NV; r += 8) {
            int d = cntL[g * NV + r];
            const unsigned char* lst = colsL + ((long)g * NV + r) * MAXD;
            float acc = 0.f;
            for (int q = lane; q < d; q += 32) acc += spre[lst[q]];
#pragma unroll
            for (int s = 16; s > 0; s >>= 1) acc += __shfl_down_sync(0xffffffffu, acc, s);
            if (lane == 0) { ssc[r] = ng[r] * acc + bsv; sidx[r] = r; }
        }
    } else {
        for (int r = warp; r < NV; r += 8) {
            float acc = 0.f;
            for (int q = lane; q < NV; q += 32) acc += Ag[(long)r * NV + q] * spre[q];
#pragma unroll
            for (int s = 16; s > 0; s >>= 1) acc += __shfl_down_sync(0xffffffffu, acc, s);
            if (lane == 0) { ssc[r] = ng[r] * acc + bsv; sidx[r] = r; }
        }
    }
    __syncthreads();

    for (int ksz = 2; ksz <= NV; ksz <<= 1) {
        for (int j = ksz >> 1; j > 0; j >>= 1) {
            if (tid < NV) {
                int ixj = tid ^ j;
                if (ixj > tid) {
                    float s1 = ssc[tid], s2 = ssc[ixj];
                    int i1 = sidx[tid], i2 = sidx[ixj];
                    bool firstWorse = (s1 < s2) || (s1 == s2 && i1 > i2);
                    bool descRegion = ((tid & ksz) == 0);
                    bool doSwap = descRegion ? firstWorse : !firstWorse;
                    if (doSwap) {
                        ssc[tid] = s2; ssc[ixj] = s1;
                        sidx[tid] = i2; sidx[ixj] = i1;
                    }
                }
            }
            __syncthreads();
        }
    }

    if (tid < KK) ssc[tid] = tanhf(ssc[tid]);
    __syncthreads();

    {
        int j = tid;
        float csum = 0.f, cmax = -3.402823466e38f;
#pragma unroll 4
        for (int r = 0; r < KK; r++) {
            int row = sidx[r];
            float v = Xg[(long)row * 256 + j] * ssc[r];
            Xp[(long)g * KK * 256 + (long)r * 256 + j] = v;
            csum += v;
            cmax = fmaxf(cmax, v);
        }
        readout[(long)g * 1536 + roff + j] = csum;
        readout[(long)g * 1536 + roff + 256 + j] = cmax;
    }

    if (Aout) {
        for (int t = tid; t < KK * KK; t += 256) {
            int r = t / KK, c = t % KK;
            sAn[t] = Ag[(long)sidx[r] * NV + sidx[c]];
        }
        __syncthreads();
        for (int t = tid; t < KK * KK; t += 256) Aout[(long)g * KK * KK + t] = sAn[t];
        if (tid < KK) {
            float d = 0.f;
#pragma unroll
            for (int c = 0; c < KK; c++) d += sAn[tid * KK + c];
            normOut[(long)g * KK + tid] = rsqrtf(fmaxf(d, 1.f));
        }
    }
}

// ====== fused MLP head (round-7 proven) ========================================
__global__ void __launch_bounds__(256) mlp_head_kernel(
    const float* __restrict__ read, const float* __restrict__ Wd1,
    const float* __restrict__ bd1, const float* __restrict__ Wd2,
    const float* __restrict__ bd2, float* __restrict__ out)
{
    extern __shared__ float sm[];
    float* sR = sm;
    float* sP = sm + 4 * 1536;
    float* sH = sP;

    int tid = threadIdx.x;
    int g0 = blockIdx.x * 4;
    int lane = tid & 31, kw = tid >> 5;

    {
        const float4* src = (const float4*)(read + (long)g0 * 1536);
        float4* d4 = (float4*)sR;
#pragma unroll
        for (int i = 0; i < 6; i++) d4[tid + i * 256] = src[tid + i * 256];
    }
    __syncthreads();

    float4 acc[4];
#pragma unroll
    for (int gg = 0; gg < 4; gg++) acc[gg] = make_float4(0.f, 0.f, 0.f, 0.f);
    {
        const float4* W14 = (const float4*)Wd1;
        int kbeg = kw * 192;
#pragma unroll 2
        for (int k = kbeg; k < kbeg + 192; k++) {
            float4 wd = __ldg(&W14[k * 32 + lane]);
#pragma unroll
            for (int gg = 0; gg < 4; gg++) {
                float rv = sR[gg * 1536 + k];
                acc[gg].x += rv * wd.x;
                acc[gg].y += rv * wd.y;
                acc[gg].z += rv * wd.z;
                acc[gg].w += rv * wd.w;
            }
        }
    }
#pragma unroll
    for (int gg = 0; gg < 4; gg++)
        ((float4*)sP)[(kw * 4 + gg) * 32 + lane] = acc[gg];
    __syncthreads();

#pragma unroll
    for (int rep = 0; rep < 2; rep++) {
        int idx = tid + rep * 256;
        int gg = idx >> 7, j = idx & 127;
        float s = 0.f;
#pragma unroll
        for (int w = 0; w < 8; w++) s += sP[(w * 4 + gg) * 128 + j];
        s += bd1[j];
        s = (s > 0.f) ? s : 0.01f * s;
        acc[0].x = s;
        __syncthreads();
        sH[gg * 128 + j] = acc[0].x;
        __syncthreads();
    }

    if (kw < 4) {
        float a0 = 0.f, a1 = 0.f;
#pragma unroll
        for (int c = 0; c < 4; c++) {
            int k = lane + c * 32;
            float h = sH[kw * 128 + k];
            a0 += h * Wd2[k * 2 + 0];
            a1 += h * Wd2[k * 2 + 1];
        }
#pragma unroll
        for (int s = 16; s > 0; s >>= 1) {
            a0 += __shfl_down_sync(0xffffffffu, a0, s);
            a1 += __shfl_down_sync(0xffffffffu, a1, s);
        }
        if (lane == 0) {
            out[(g0 + kw) * 2 + 0] = 1.f / (1.f + expf(-(a0 + bd2[0])));
            out[(g0 + kw) * 2 + 1] = 1.f / (1.f + expf(-(a1 + bd2[1])));
        }
    }
}

// --------------------------------- launch --------------------------------------
extern "C" void kernel_launch(void* const* d_in, const int* in_sizes, int n_in,
                              void* d_out, int out_size)
{
    const float* feat = (const float*)d_in[0];
    const float* adj  = (const float*)d_in[1];
    const float* W0   = (const float*)d_in[2];
    const float* b0   = (const float*)d_in[3];
    const float* Ws0  = (const float*)d_in[4];
    const float* bs0  = (const float*)d_in[5];
    const float* W1   = (const float*)d_in[6];
    const float* b1   = (const float*)d_in[7];
    const float* Ws1  = (const float*)d_in[8];
    const float* bs1  = (const float*)d_in[9];
    const float* W2   = (const float*)d_in[10];
    const float* b2   = (const float*)d_in[11];
    const float* Ws2  = (const float*)d_in[12];
    const float* bs2  = (const float*)d_in[13];
    const float* Wd1  = (const float*)d_in[14];
    const float* bd1  = (const float*)d_in[15];
    const float* Wd2  = (const float*)d_in[16];
    const float* bd2  = (const float*)d_in[17];
    float* out = (float*)d_out;

    float *p_norm0, *p_X1, *p_spre, *p_Xp1, *p_A1, *p_norm1, *p_H1, *p_X2;
    float *p_Xp2, *p_A2, *p_norm2, *p_H2, *p_X3, *p_Xp3, *p_read;
    unsigned char* p_cols; int* p_cnt;
    __nv_bfloat16 *p_Yh, *p_Yl, *p_W0h, *p_W0l;
    cudaGetSymbolAddress((void**)&p_norm0, g_norm0);
    cudaGetSymbolAddress((void**)&p_cols, g_cols);
    cudaGetSymbolAddress((void**)&p_cnt, g_cnt);
    cudaGetSymbolAddress((void**)&p_Yh, g_Yh);
    cudaGetSymbolAddress((void**)&p_Yl, g_Yl);
    cudaGetSymbolAddress((void**)&p_W0h, g_W0h);
    cudaGetSymbolAddress((void**)&p_W0l, g_W0l);
    cudaGetSymbolAddress((void**)&p_X1, g_X1);
    cudaGetSymbolAddress((void**)&p_spre, g_spre);
    cudaGetSymbolAddress((void**)&p_Xp1, g_Xp1);
    cudaGetSymbolAddress((void**)&p_A1, g_A1);
    cudaGetSymbolAddress((void**)&p_norm1, g_norm1);
    cudaGetSymbolAddress((void**)&p_H1, g_H1);
    cudaGetSymbolAddress((void**)&p_X2, g_X2);
    cudaGetSymbolAddress((void**)&p_Xp2, g_Xp2);
    cudaGetSymbolAddress((void**)&p_A2, g_A2);
    cudaGetSymbolAddress((void**)&p_norm2, g_norm2);
    cudaGetSymbolAddress((void**)&p_H2, g_H2);
    cudaGetSymbolAddress((void**)&p_X3, g_X3);
    cudaGetSymbolAddress((void**)&p_Xp3, g_Xp3);
    cudaGetSymbolAddress((void**)&p_read, g_read);

    const int headSmem = (4 * 1536 + 8 * 4 * 128) * 4;
    const int wmmaSmem = 128 * 128 * 4;   // 64 KB (epilogue C; operands fit inside)
    cudaFuncSetAttribute(spmm_feat_kernel, cudaFuncAttributeMaxDynamicSharedMemorySize, 131072);
    cudaFuncSetAttribute(mlp_head_kernel, cudaFuncAttributeMaxDynamicSharedMemorySize, headSmem);
    cudaFuncSetAttribute(wmma_feat_kernel, cudaFuncAttributeMaxDynamicSharedMemorySize, wmmaSmem);

    // ---- layer 0
    build_adj_kernel<<<G * NNODE / 8, 256>>>(adj, p_cols, p_cnt, p_norm0);
    split_w_kernel<<<(FIN * DH + 255) / 256, 256>>>(W0, p_W0h, p_W0l, FIN * DH);
    spmm_feat_kernel<<<G, 256, 131072>>>(p_cols, p_cnt, feat, p_norm0, p_Yh, p_Yl);
    wmma_feat_kernel<<<dim3(2, 2048, 1), 256, wmmaSmem>>>(p_Yh, p_Yl, p_W0h, p_W0l,
                                                          b0, Ws0, p_X1, p_spre);
    pool_kernel<256, 32><<<G, 256>>>(p_X1, adj, p_norm0, Ws0, bs0, p_cols, p_cnt,
                                     p_spre, p_Xp1, p_A1, p_norm1, p_read, 0);
    // ---- layer 1
    sgemm_kernel<<<dim3(2, 256, 1), 256>>>(p_Xp1, W1, p_H1, G * 32, DH, DH,
                                           0, 0, 0, p_norm1, 0, nullptr, 0, nullptr, 0);
    conv_small_kernel<32><<<G, 256>>>(p_A1, p_H1, p_norm1, b1, p_X2);
    pool_kernel<32, 16><<<G, 256>>>(p_X2, p_A1, p_norm1, Ws1, bs1, nullptr, nullptr,
                                    nullptr, p_Xp2, p_A2, p_norm2, p_read, 512);
    // ---- layer 2
    sgemm_kernel<<<dim3(2, 128, 1), 256>>>(p_Xp2, W2, p_H2, G * 16, DH, DH,
                                           0, 0, 0, p_norm2, 0, nullptr, 0, nullptr, 0);
    conv_small_kernel<16><<<G, 256>>>(p_A2, p_H2, p_norm2, b2, p_X3);
    pool_kernel<16, 8><<<G, 256>>>(p_X3, p_A2, p_norm2, Ws2, bs2, nullptr, nullptr,
                                   nullptr, p_Xp3, nullptr, nullptr, p_read, 1024);
    // ---- fused MLP head
    mlp_head_kernel<<<G / 4, 256, headSmem>>>(p_read, Wd1, bd1, Wd2, bd2, out);
}

// round 9
// speedup vs baseline: 1.3053x; 1.0374x over previous
#include <cuda_runtime.h>
#include <cuda_bf16.h>
#include <mma.h>
#include <math.h>

using namespace nvcuda;

#define G 1024
#define NNODE 256
#define FIN 128
#define DH 256
#define MAXD 128

// ---------------- scratch (device globals; no allocations allowed) -------------
__device__ float g_norm0[G * NNODE];
__device__ unsigned char g_cols[(long)G * NNODE * MAXD];
__device__ int   g_cnt [G * NNODE];
__device__ __nv_bfloat16 g_Yh[(long)G * NNODE * FIN];
__device__ __nv_bfloat16 g_Yl[(long)G * NNODE * FIN];
__device__ __nv_bfloat16 g_W0h[FIN * DH];
__device__ __nv_bfloat16 g_W0l[FIN * DH];
__device__ float g_X1 [G * NNODE * DH];
__device__ float g_spre[2 * G * NNODE];
__device__ float g_Xp1[G * 32 * DH];
__device__ float g_A1 [G * 32 * 32];
__device__ float g_norm1[G * 32];
__device__ float g_H1 [G * 32 * DH];
__device__ float g_X2 [G * 32 * DH];
__device__ float g_Xp2[G * 16 * DH];
__device__ float g_A2 [G * 16 * 16];
__device__ float g_norm2[G * 16];
__device__ float g_H2 [G * 16 * DH];
__device__ float g_X3 [G * 16 * DH];
__device__ float g_Xp3[G * 8 * DH];
__device__ float g_read[G * 1536];

// ---------------- build sparse adjacency lists + degree norm -------------------
__global__ void build_adj_kernel(const float* __restrict__ adj,
                                 unsigned char* __restrict__ cols,
                                 int* __restrict__ cnt, float* __restrict__ nrm)
{
    int row  = blockIdx.x * 8 + (threadIdx.x >> 5);
    int lane = threadIdx.x & 31;
    const float* a = adj + (long)row * 256;
    unsigned char* lst = cols + (long)row * MAXD;
    int base = 0;
#pragma unroll
    for (int c = 0; c < 8; c++) {
        float v = a[c * 32 + lane];
        unsigned m = __ballot_sync(0xffffffffu, v != 0.f);
        if (v != 0.f) {
            int pos = base + __popc(m & ((1u << lane) - 1));
            if (pos < MAXD) lst[pos] = (unsigned char)(c * 32 + lane);
        }
        base += __popc(m);
    }
    if (lane == 0) {
        cnt[row] = (base > MAXD) ? MAXD : base;
        nrm[row] = rsqrtf(fmaxf((float)base, 1.f));
    }
}

// ---------------- split W0 into bf16 hi/lo -------------------------------------
__global__ void split_w_kernel(const float* __restrict__ W,
                               __nv_bfloat16* __restrict__ Wh,
                               __nv_bfloat16* __restrict__ Wl, int n)
{
    int i = blockIdx.x * 256 + threadIdx.x;
    if (i < n) {
        float v = W[i];
        __nv_bfloat16 h = __float2bfloat16_rn(v);
        Wh[i] = h;
        Wl[i] = __float2bfloat16_rn(v - __bfloat162float(h));
    }
}

// ------- layer-0 sparse aggregation in INPUT space; emits bf16 hi/lo -----------
__global__ void spmm_feat_kernel(const unsigned char* __restrict__ cols,
                                 const int* __restrict__ cnt,
                                 const float* __restrict__ feat,
                                 const float* __restrict__ nrm,
                                 __nv_bfloat16* __restrict__ Yh,
                                 __nv_bfloat16* __restrict__ Yl)
{
    extern __shared__ float sX[];                 // [256][128] = 128 KB
    __shared__ unsigned char sCols[256 * MAXD];   // 32 KB
    __shared__ int   scnt[256];
    __shared__ float snrm[256];

    int g = blockIdx.x, tid = threadIdx.x;
    scnt[tid] = cnt[g * 256 + tid];
    snrm[tid] = nrm[g * 256 + tid];
    __syncthreads();

    {
        const float4* Xg = (const float4*)(feat + (long)g * 32768);
        float4* s4 = (float4*)sX;
        for (int t = tid; t < 8192; t += 256) {
            int r = t >> 5;
            float4 v = Xg[t];
            float s = snrm[r];
            v.x *= s; v.y *= s; v.z *= s; v.w *= s;
            s4[t] = v;
        }
        const uint4* gc = (const uint4*)(cols + (long)g * 256 * MAXD);
        uint4* sc = (uint4*)sCols;
        for (int t = tid; t < 2048; t += 256) sc[t] = gc[t];
    }
    __syncthreads();

    int col4 = tid & 31;
    int rg   = tid >> 5;
    for (int i = rg; i < 256; i += 8) {
        int d = scnt[i];
        const unsigned char* lst = &sCols[i * MAXD];
        float a0 = 0.f, a1 = 0.f, a2 = 0.f, a3 = 0.f;
        int k = 0;
        for (; k + 4 <= d; k += 4) {
            unsigned w = *(const unsigned*)(lst + k);
            int j0 = w & 255, j1 = (w >> 8) & 255, j2 = (w >> 16) & 255, j3 = w >> 24;
            float4 h0 = *(const float4*)(sX + j0 * 128 + col4 * 4);
            float4 h1 = *(const float4*)(sX + j1 * 128 + col4 * 4);
            float4 h2 = *(const float4*)(sX + j2 * 128 + col4 * 4);
            float4 h3 = *(const float4*)(sX + j3 * 128 + col4 * 4);
            a0 += h0.x + h1.x + h2.x + h3.x;
            a1 += h0.y + h1.y + h2.y + h3.y;
            a2 += h0.z + h1.z + h2.z + h3.z;
            a3 += h0.w + h1.w + h2.w + h3.w;
        }
        for (; k < d; k++) {
            int j = lst[k];
            float4 h = *(const float4*)(sX + j * 128 + col4 * 4);
            a0 += h.x; a1 += h.y; a2 += h.z; a3 += h.w;
        }
        float nr = snrm[i];
        float o0 = a0 * nr, o1 = a1 * nr, o2 = a2 * nr, o3 = a3 * nr;
        __nv_bfloat16 h0 = __float2bfloat16_rn(o0);
        __nv_bfloat16 h1 = __float2bfloat16_rn(o1);
        __nv_bfloat16 h2 = __float2bfloat16_rn(o2);
        __nv_bfloat16 h3 = __float2bfloat16_rn(o3);
        long base = (long)g * 32768 + (long)i * 128 + col4 * 4;
        *(__nv_bfloat162*)(Yh + base)     = __nv_bfloat162(h0, h1);
        *(__nv_bfloat162*)(Yh + base + 2) = __nv_bfloat162(h2, h3);
        *(__nv_bfloat162*)(Yl + base) = __nv_bfloat162(
            __float2bfloat16_rn(o0 - __bfloat162float(h0)),
            __float2bfloat16_rn(o1 - __bfloat162float(h1)));
        *(__nv_bfloat162*)(Yl + base + 2) = __nv_bfloat162(
            __float2bfloat16_rn(o2 - __bfloat162float(h2)),
            __float2bfloat16_rn(o3 - __bfloat162float(h3)));
    }
}

// ===== bf16 wmma 3-chain GEMM: X1 = leaky(Y@W0 + b0), fused Ws0 dot ============
// grid (2, 2048), 256 threads (8 warps, 2x4), warp tile 64x32, BK=32.
// __launch_bounds__(256, 2): cap at 128 regs -> 2 CTAs/SM (was 140 regs, 1 CTA,
// occ 12.5%, tensor pipe 22% — latency-bound).
#define WAL 40     // A smem row stride (elems)
#define WBL 136    // B smem row stride (elems)

__global__ void __launch_bounds__(256, 2) wmma_feat_kernel(
    const __nv_bfloat16* __restrict__ Yh, const __nv_bfloat16* __restrict__ Yl,
    const __nv_bfloat16* __restrict__ Wh, const __nv_bfloat16* __restrict__ Wl,
    const float* __restrict__ bias, const float* __restrict__ Wsp,
    float* __restrict__ X1, float* __restrict__ spreOut)
{
    extern __shared__ char smem[];
    __nv_bfloat16* sAh = (__nv_bfloat16*)smem;      // [128][WAL]
    __nv_bfloat16* sAl = sAh + 128 * WAL;
    __nv_bfloat16* sBh = sAl + 128 * WAL;           // [32][WBL]
    __nv_bfloat16* sBl = sBh + 32 * WBL;
    float* sC = (float*)smem;                       // [128][128] (reused)

    int tid = threadIdx.x, warp = tid >> 5;
    int bm = blockIdx.y * 128, bn = blockIdx.x * 128;
    int wm = warp >> 2, wn = warp & 3;

    wmma::fragment<wmma::accumulator, 16, 16, 16, float> acc[4][2];
#pragma unroll
    for (int i = 0; i < 4; i++)
#pragma unroll
        for (int j = 0; j < 2; j++) wmma::fill_fragment(acc[i][j], 0.f);

    for (int k0 = 0; k0 < 128; k0 += 32) {
        // A tile: 128 rows x 32 cols, hi+lo  (512 uint4 each -> 2 per thread)
#pragma unroll
        for (int it = 0; it < 2; it++) {
            int idx = tid + it * 256;
            int r = idx >> 2, c8 = (idx & 3) * 8;
            long gofs = (long)(bm + r) * 128 + k0 + c8;
            *(uint4*)(sAh + r * WAL + c8) = *(const uint4*)(Yh + gofs);
            *(uint4*)(sAl + r * WAL + c8) = *(const uint4*)(Yl + gofs);
        }
        // B tile: 32 rows x 128 cols, hi+lo
#pragma unroll
        for (int it = 0; it < 2; it++) {
            int idx = tid + it * 256;
            int r = idx >> 4, c8 = (idx & 15) * 8;
            long gofs = (long)(k0 + r) * 256 + bn + c8;
            *(uint4*)(sBh + r * WBL + c8) = *(const uint4*)(Wh + gofs);
            *(uint4*)(sBl + r * WBL + c8) = *(const uint4*)(Wl + gofs);
        }
        __syncthreads();

#pragma unroll
        for (int kk = 0; kk < 32; kk += 16) {
            wmma::fragment<wmma::matrix_b, 16, 16, 16, __nv_bfloat16, wmma::row_major> bh[2], bl[2];
#pragma unroll
            for (int j = 0; j < 2; j++) {
                wmma::load_matrix_sync(bh[j], sBh + kk * WBL + wn * 32 + j * 16, WBL);
                wmma::load_matrix_sync(bl[j], sBl + kk * WBL + wn * 32 + j * 16, WBL);
            }
#pragma unroll
            for (int i = 0; i < 4; i++) {
                wmma::fragment<wmma::matrix_a, 16, 16, 16, __nv_bfloat16, wmma::row_major> ah, al;
                wmma::load_matrix_sync(ah, sAh + (wm * 64 + i * 16) * WAL + kk, WAL);
                wmma::load_matrix_sync(al, sAl + (wm * 64 + i * 16) * WAL + kk, WAL);
#pragma unroll
                for (int j = 0; j < 2; j++) {
                    wmma::mma_sync(acc[i][j], ah, bh[j], acc[i][j]);
                    wmma::mma_sync(acc[i][j], ah, bl[j], acc[i][j]);
                    wmma::mma_sync(acc[i][j], al, bh[j], acc[i][j]);
                }
            }
        }
        __syncthreads();
    }

    // stage C through smem (operand tiles dead now)
#pragma unroll
    for (int i = 0; i < 4; i++)
#pragma unroll
        for (int j = 0; j < 2; j++)
            wmma::store_matrix_sync(sC + (wm * 64 + i * 16) * 128 + wn * 32 + j * 16,
                                    acc[i][j], 128, wmma::mem_row_major);
    __syncthreads();

    // epilogue: bias + leaky + fused Ws0 dot; row = tid>>1, 64 cols per thread
    {
        int row = tid >> 1, half = tid & 1;
        int gRow = bm + row;
        float rd = 0.f;
        float* dst = X1 + (long)gRow * 256 + bn + half * 64;
#pragma unroll
        for (int c4 = 0; c4 < 16; c4++) {
            int col = half * 64 + c4 * 4;
            float4 v = *(float4*)(sC + row * 128 + col);
            float4 bv = *(const float4*)(bias + bn + col);
            v.x += bv.x; v.y += bv.y; v.z += bv.z; v.w += bv.w;
            v.x = (v.x > 0.f) ? v.x : 0.01f * v.x;
            v.y = (v.y > 0.f) ? v.y : 0.01f * v.y;
            v.z = (v.z > 0.f) ? v.z : 0.01f * v.z;
            v.w = (v.w > 0.f) ? v.w : 0.01f * v.w;
            float4 wv = *(const float4*)(Wsp + bn + col);
            rd += v.x * wv.x + v.y * wv.y + v.z * wv.z + v.w * wv.w;
            *(float4*)(dst + c4 * 4) = v;
        }
        rd += __shfl_xor_sync(0xffffffffu, rd, 1);
        if (half == 0) spreOut[(long)blockIdx.x * (G * NNODE) + gRow] = rd;
    }
}

// ---------------- dense scalar SGEMM (layers 1/2) ------------------------------
#define BM 128
#define BN 128
#define BK 8

__global__ void sgemm_kernel(const float* __restrict__ A, const float* __restrict__ B,
                             float* __restrict__ C,
                             int M, int N, int K,
                             long bA, long bB, long bC,
                             const float* __restrict__ rsA, int rsAstride,
                             const float* __restrict__ rsC, int rsCstride,
                             const float* __restrict__ bias, int leaky)
{
    int g = blockIdx.z;
    const float* Ag = A + (long)g * bA;
    const float* Bg = B + (long)g * bB;
    float* Cg = C + (long)g * bC;
    const float* rsAg = rsA ? rsA + (long)g * rsAstride : nullptr;
    const float* rsCg = rsC ? rsC + (long)g * rsCstride : nullptr;

    int bm = blockIdx.y * BM;
    int bn = blockIdx.x * BN;

    __shared__ __align__(16) float sA[BK][BM + 4];
    __shared__ __align__(16) float sB[BK][BN + 4];

    int tid = threadIdx.x;
    int a_row = tid >> 1;
    int a_col = (tid & 1) * 4;
    int b_row = tid >> 5;
    int b_col = (tid & 31) * 4;
    int tr = tid >> 4;
    int tc = tid & 15;

    float acc[8][8];
#pragma unroll
    for (int i = 0; i < 8; i++)
#pragma unroll
        for (int j = 0; j < 8; j++) acc[i][j] = 0.f;

    float aScale = rsAg ? rsAg[bm + a_row] : 1.f;

    for (int k0 = 0; k0 < K; k0 += BK) {
        float4 av = *(const float4*)(Ag + (long)(bm + a_row) * K + k0 + a_col);
        av.x *= aScale; av.y *= aScale; av.z *= aScale; av.w *= aScale;
        sA[a_col + 0][a_row] = av.x;
        sA[a_col + 1][a_row] = av.y;
        sA[a_col + 2][a_row] = av.z;
        sA[a_col + 3][a_row] = av.w;
        float4 bv = *(const float4*)(Bg + (long)(k0 + b_row) * N + bn + b_col);
        *(float4*)&sB[b_row][b_col] = bv;
        __syncthreads();
#pragma unroll
        for (int k = 0; k < BK; k++) {
            float4 a0 = *(const float4*)&sA[k][tr * 4];
            float4 a1 = *(const float4*)&sA[k][tr * 4 + 64];
            float4 b0 = *(const float4*)&sB[k][tc * 4];
            float4 b1 = *(const float4*)&sB[k][tc * 4 + 64];
            float ar[8] = {a0.x, a0.y, a0.z, a0.w, a1.x, a1.y, a1.z, a1.w};
            float br[8] = {b0.x, b0.y, b0.z, b0.w, b1.x, b1.y, b1.z, b1.w};
#pragma unroll
            for (int i = 0; i < 8; i++)
#pragma unroll
                for (int j = 0; j < 8; j++) acc[i][j] += ar[i] * br[j];
        }
        __syncthreads();
    }

#pragma unroll
    for (int i = 0; i < 8; i++) {
        int row = bm + ((i < 4) ? (tr * 4 + i) : (64 + tr * 4 + i - 4));
        float rs = rsCg ? rsCg[row] : 1.f;
#pragma unroll
        for (int jg = 0; jg < 2; jg++) {
            int col = bn + tc * 4 + jg * 64;
            float v[4];
#pragma unroll
            for (int jj = 0; jj < 4; jj++) {
                float c = acc[i][jg * 4 + jj] * rs;
                if (bias) c += bias[col + jj];
                if (leaky) c = (c > 0.f) ? c : 0.01f * c;
                v[jj] = c;
            }
            float4 o = make_float4(v[0], v[1], v[2], v[3]);
            *(float4*)(Cg + (long)row * N + col) = o;
        }
    }
}

// ---------------- small batched conv: X = leaky(adj@H * norm + b) ---------------
template <int NN>
__global__ void conv_small_kernel(const float* __restrict__ A, const float* __restrict__ H,
                                  const float* __restrict__ nrm, const float* __restrict__ bias,
                                  float* __restrict__ X)
{
    int g = blockIdx.x;
    __shared__ float sAdj[NN][NN + 1];
    __shared__ float sH[NN][256];
    const float* Ag = A + (long)g * NN * NN;
    const float* Hg = H + (long)g * NN * 256;
    int tid = threadIdx.x;
    for (int t = tid; t < NN * NN; t += 256) sAdj[t / NN][t % NN] = Ag[t];
    for (int t = tid; t < NN * 256; t += 256) sH[t / 256][t % 256] = Hg[t];
    __syncthreads();
    int j = tid;
    float bj = bias[j];
#pragma unroll 4
    for (int i = 0; i < NN; i++) {
        float acc = 0.f;
#pragma unroll
        for (int k = 0; k < NN; k++) acc += sAdj[i][k] * sH[k][j];
        float v = acc * nrm[(long)g * NN + i] + bj;
        X[(long)g * NN * 256 + (long)i * 256 + j] = (v > 0.f) ? v : 0.01f * v;
    }
}

// ---------------- SAGPool (round-5 proven version) -----------------------------
template <int NV, int KK>
__global__ void pool_kernel(const float* __restrict__ X, const float* __restrict__ A,
                            const float* __restrict__ nrm,
                            const float* __restrict__ Ws, const float* __restrict__ bs,
                            const unsigned char* __restrict__ colsL,
                            const int* __restrict__ cntL,
                            const float* __restrict__ spreParts,
                            float* __restrict__ Xp, float* __restrict__ Aout,
                            float* __restrict__ normOut, float* __restrict__ readout,
                            int roff)
{
    int g = blockIdx.x;
    const float* Xg = X + (long)g * NV * 256;
    const float* Ag = A + (long)g * NV * NV;
    const float* ng = nrm + (long)g * NV;

    __shared__ float sWs[256];
    __shared__ float spre[NV];
    __shared__ float ssc[NV];
    __shared__ int   sidx[NV];
    __shared__ float sAn[KK * KK];

    int tid = threadIdx.x, lane = tid & 31, warp = tid >> 5;

    if (spreParts) {
        if (tid < NV)
            spre[tid] = (spreParts[(long)g * NV + tid] +
                         spreParts[(long)G * NNODE + (long)g * NV + tid]) * ng[tid];
        __syncthreads();
    } else {
        sWs[tid] = Ws[tid];
        __syncthreads();
        for (int r = warp; r < NV; r += 8) {
            float acc = 0.f;
            for (int q = lane; q < 256; q += 32) acc += Xg[(long)r * 256 + q] * sWs[q];
#pragma unroll
            for (int s = 16; s > 0; s >>= 1) acc += __shfl_down_sync(0xffffffffu, acc, s);
            if (lane == 0) spre[r] = ng[r] * acc;
        }
        __syncthreads();
    }

    float bsv = bs[0];
    if (colsL) {
        for (int r = warp; r < NV; r += 8) {
            int d = cntL[g * NV + r];
            const unsigned char* lst = colsL + ((long)g * NV + r) * MAXD;
            float acc = 0.f;
            for (int q = lane; q < d; q += 32) acc += spre[lst[q]];
#pragma unroll
            for (int s = 16; s > 0; s >>= 1) acc += __shfl_down_sync(0xffffffffu, acc, s);
            if (lane == 0) { ssc[r] = ng[r] * acc + bsv; sidx[r] = r; }
        }
    } else {
        for (int r = warp; r < NV; r += 8) {
            float acc = 0.f;
            for (int q = lane; q < NV; q += 32) acc += Ag[(long)r * NV + q] * spre[q];
#pragma unroll
            for (int s = 16; s > 0; s >>= 1) acc += __shfl_down_sync(0xffffffffu, acc, s);
            if (lane == 0) { ssc[r] = ng[r] * acc + bsv; sidx[r] = r; }
        }
    }
    __syncthreads();

    for (int ksz = 2; ksz <= NV; ksz <<= 1) {
        for (int j = ksz >> 1; j > 0; j >>= 1) {
            if (tid < NV) {
                int ixj = tid ^ j;
                if (ixj > tid) {
                    float s1 = ssc[tid], s2 = ssc[ixj];
                    int i1 = sidx[tid], i2 = sidx[ixj];
                    bool firstWorse = (s1 < s2) || (s1 == s2 && i1 > i2);
                    bool descRegion = ((tid & ksz) == 0);
                    bool doSwap = descRegion ? firstWorse : !firstWorse;
                    if (doSwap) {
                        ssc[tid] = s2; ssc[ixj] = s1;
                        sidx[tid] = i2; sidx[ixj] = i1;
                    }
                }
            }
            __syncthreads();
        }
    }

    if (tid < KK) ssc[tid] = tanhf(ssc[tid]);
    __syncthreads();

    {
        int j = tid;
        float csum = 0.f, cmax = -3.402823466e38f;
#pragma unroll 4
        for (int r = 0; r < KK; r++) {
            int row = sidx[r];
            float v = Xg[(long)row * 256 + j] * ssc[r];
            Xp[(long)g * KK * 256 + (long)r * 256 + j] = v;
            csum += v;
            cmax = fmaxf(cmax, v);
        }
        readout[(long)g * 1536 + roff + j] = csum;
        readout[(long)g * 1536 + roff + 256 + j] = cmax;
    }

    if (Aout) {
        for (int t = tid; t < KK * KK; t += 256) {
            int r = t / KK, c = t % KK;
            sAn[t] = Ag[(long)sidx[r] * NV + sidx[c]];
        }
        __syncthreads();
        for (int t = tid; t < KK * KK; t += 256) Aout[(long)g * KK * KK + t] = sAn[t];
        if (tid < KK) {
            float d = 0.f;
#pragma unroll
            for (int c = 0; c < KK; c++) d += sAn[tid * KK + c];
            normOut[(long)g * KK + tid] = rsqrtf(fmaxf(d, 1.f));
        }
    }
}

// ====== fused MLP head (round-7 proven) ========================================
__global__ void __launch_bounds__(256) mlp_head_kernel(
    const float* __restrict__ read, const float* __restrict__ Wd1,
    const float* __restrict__ bd1, const float* __restrict__ Wd2,
    const float* __restrict__ bd2, float* __restrict__ out)
{
    extern __shared__ float sm[];
    float* sR = sm;
    float* sP = sm + 4 * 1536;
    float* sH = sP;

    int tid = threadIdx.x;
    int g0 = blockIdx.x * 4;
    int lane = tid & 31, kw = tid >> 5;

    {
        const float4* src = (const float4*)(read + (long)g0 * 1536);
        float4* d4 = (float4*)sR;
#pragma unroll
        for (int i = 0; i < 6; i++) d4[tid + i * 256] = src[tid + i * 256];
    }
    __syncthreads();

    float4 acc[4];
#pragma unroll
    for (int gg = 0; gg < 4; gg++) acc[gg] = make_float4(0.f, 0.f, 0.f, 0.f);
    {
        const float4* W14 = (const float4*)Wd1;
        int kbeg = kw * 192;
#pragma unroll 2
        for (int k = kbeg; k < kbeg + 192; k++) {
            float4 wd = __ldg(&W14[k * 32 + lane]);
#pragma unroll
            for (int gg = 0; gg < 4; gg++) {
                float rv = sR[gg * 1536 + k];
                acc[gg].x += rv * wd.x;
                acc[gg].y += rv * wd.y;
                acc[gg].z += rv * wd.z;
                acc[gg].w += rv * wd.w;
            }
        }
    }
#pragma unroll
    for (int gg = 0; gg < 4; gg++)
        ((float4*)sP)[(kw * 4 + gg) * 32 + lane] = acc[gg];
    __syncthreads();

#pragma unroll
    for (int rep = 0; rep < 2; rep++) {
        int idx = tid + rep * 256;
        int gg = idx >> 7, j = idx & 127;
        float s = 0.f;
#pragma unroll
        for (int w = 0; w < 8; w++) s += sP[(w * 4 + gg) * 128 + j];
        s += bd1[j];
        s = (s > 0.f) ? s : 0.01f * s;
        acc[0].x = s;
        __syncthreads();
        sH[gg * 128 + j] = acc[0].x;
        __syncthreads();
    }

    if (kw < 4) {
        float a0 = 0.f, a1 = 0.f;
#pragma unroll
        for (int c = 0; c < 4; c++) {
            int k = lane + c * 32;
            float h = sH[kw * 128 + k];
            a0 += h * Wd2[k * 2 + 0];
            a1 += h * Wd2[k * 2 + 1];
        }
#pragma unroll
        for (int s = 16; s > 0; s >>= 1) {
            a0 += __shfl_down_sync(0xffffffffu, a0, s);
            a1 += __shfl_down_sync(0xffffffffu, a1, s);
        }
        if (lane == 0) {
            out[(g0 + kw) * 2 + 0] = 1.f / (1.f + expf(-(a0 + bd2[0])));
            out[(g0 + kw) * 2 + 1] = 1.f / (1.f + expf(-(a1 + bd2[1])));
        }
    }
}

// --------------------------------- launch --------------------------------------
extern "C" void kernel_launch(void* const* d_in, const int* in_sizes, int n_in,
                              void* d_out, int out_size)
{
    const float* feat = (const float*)d_in[0];
    const float* adj  = (const float*)d_in[1];
    const float* W0   = (const float*)d_in[2];
    const float* b0   = (const float*)d_in[3];
    const float* Ws0  = (const float*)d_in[4];
    const float* bs0  = (const float*)d_in[5];
    const float* W1   = (const float*)d_in[6];
    const float* b1   = (const float*)d_in[7];
    const float* Ws1  = (const float*)d_in[8];
    const float* bs1  = (const float*)d_in[9];
    const float* W2   = (const float*)d_in[10];
    const float* b2   = (const float*)d_in[11];
    const float* Ws2  = (const float*)d_in[12];
    const float* bs2  = (const float*)d_in[13];
    const float* Wd1  = (const float*)d_in[14];
    const float* bd1  = (const float*)d_in[15];
    const float* Wd2  = (const float*)d_in[16];
    const float* bd2  = (const float*)d_in[17];
    float* out = (float*)d_out;

    float *p_norm0, *p_X1, *p_spre, *p_Xp1, *p_A1, *p_norm1, *p_H1, *p_X2;
    float *p_Xp2, *p_A2, *p_norm2, *p_H2, *p_X3, *p_Xp3, *p_read;
    unsigned char* p_cols; int* p_cnt;
    __nv_bfloat16 *p_Yh, *p_Yl, *p_W0h, *p_W0l;
    cudaGetSymbolAddress((void**)&p_norm0, g_norm0);
    cudaGetSymbolAddress((void**)&p_cols, g_cols);
    cudaGetSymbolAddress((void**)&p_cnt, g_cnt);
    cudaGetSymbolAddress((void**)&p_Yh, g_Yh);
    cudaGetSymbolAddress((void**)&p_Yl, g_Yl);
    cudaGetSymbolAddress((void**)&p_W0h, g_W0h);
    cudaGetSymbolAddress((void**)&p_W0l, g_W0l);
    cudaGetSymbolAddress((void**)&p_X1, g_X1);
    cudaGetSymbolAddress((void**)&p_spre, g_spre);
    cudaGetSymbolAddress((void**)&p_Xp1, g_Xp1);
    cudaGetSymbolAddress((void**)&p_A1, g_A1);
    cudaGetSymbolAddress((void**)&p_norm1, g_norm1);
    cudaGetSymbolAddress((void**)&p_H1, g_H1);
    cudaGetSymbolAddress((void**)&p_X2, g_X2);
    cudaGetSymbolAddress((void**)&p_Xp2, g_Xp2);
    cudaGetSymbolAddress((void**)&p_A2, g_A2);
    cudaGetSymbolAddress((void**)&p_norm2, g_norm2);
    cudaGetSymbolAddress((void**)&p_H2, g_H2);
    cudaGetSymbolAddress((void**)&p_X3, g_X3);
    cudaGetSymbolAddress((void**)&p_Xp3, g_Xp3);
    cudaGetSymbolAddress((void**)&p_read, g_read);

    const int headSmem = (4 * 1536 + 8 * 4 * 128) * 4;
    const int wmmaSmem = 128 * 128 * 4;   // 64 KB (epilogue C; operands fit inside)
    cudaFuncSetAttribute(spmm_feat_kernel, cudaFuncAttributeMaxDynamicSharedMemorySize, 131072);
    cudaFuncSetAttribute(mlp_head_kernel, cudaFuncAttributeMaxDynamicSharedMemorySize, headSmem);
    cudaFuncSetAttribute(wmma_feat_kernel, cudaFuncAttributeMaxDynamicSharedMemorySize, wmmaSmem);

    // ---- layer 0
    build_adj_kernel<<<G * NNODE / 8, 256>>>(adj, p_cols, p_cnt, p_norm0);
    split_w_kernel<<<(FIN * DH + 255) / 256, 256>>>(W0, p_W0h, p_W0l, FIN * DH);
    spmm_feat_kernel<<<G, 256, 131072>>>(p_cols, p_cnt, feat, p_norm0, p_Yh, p_Yl);
    wmma_feat_kernel<<<dim3(2, 2048, 1), 256, wmmaSmem>>>(p_Yh, p_Yl, p_W0h, p_W0l,
                                                          b0, Ws0, p_X1, p_spre);
    pool_kernel<256, 32><<<G, 256>>>(p_X1, adj, p_norm0, Ws0, bs0, p_cols, p_cnt,
                                     p_spre, p_Xp1, p_A1, p_norm1, p_read, 0);
    // ---- layer 1
    sgemm_kernel<<<dim3(2, 256, 1), 256>>>(p_Xp1, W1, p_H1, G * 32, DH, DH,
                                           0, 0, 0, p_norm1, 0, nullptr, 0, nullptr, 0);
    conv_small_kernel<32><<<G, 256>>>(p_A1, p_H1, p_norm1, b1, p_X2);
    pool_kernel<32, 16><<<G, 256>>>(p_X2, p_A1, p_norm1, Ws1, bs1, nullptr, nullptr,
                                    nullptr, p_Xp2, p_A2, p_norm2, p_read, 512);
    // ---- layer 2
    sgemm_kernel<<<dim3(2, 128, 1), 256>>>(p_Xp2, W2, p_H2, G * 16, DH, DH,
                                           0, 0, 0, p_norm2, 0, nullptr, 0, nullptr, 0);
    conv_small_kernel<16><<<G, 256>>>(p_A2, p_H2, p_norm2, b2, p_X3);
    pool_kernel<16, 8><<<G, 256>>>(p_X3, p_A2, p_norm2, Ws2, bs2, nullptr, nullptr,
                                   nullptr, p_Xp3, nullptr, nullptr, p_read, 1024);
    // ---- fused MLP head
    mlp_head_kernel<<<G / 4, 256, headSmem>>>(p_read, Wd1, bd1, Wd2, bd2, out);
}

// round 10
// speedup vs baseline: 1.3825x; 1.0592x over previous
#include <cuda_runtime.h>
#include <cuda_bf16.h>
#include <mma.h>
#include <math.h>

using namespace nvcuda;

#define G 1024
#define NNODE 256
#define FIN 128
#define DH 256
#define MAXD 128

// ---------------- scratch (device globals; no allocations allowed) -------------
__device__ float g_norm0[G * NNODE];
__device__ unsigned char g_cols[(long)G * NNODE * MAXD];
__device__ int   g_cnt [G * NNODE];
__device__ __nv_bfloat16 g_Yh[(long)G * NNODE * FIN];
__device__ __nv_bfloat16 g_Yl[(long)G * NNODE * FIN];
__device__ __nv_bfloat16 g_W0h[FIN * DH];
__device__ __nv_bfloat16 g_W0l[FIN * DH];
__device__ float g_X1 [G * NNODE * DH];
__device__ float g_spre[2 * G * NNODE];
__device__ float g_Xp1[G * 32 * DH];
__device__ float g_A1 [G * 32 * 32];
__device__ float g_norm1[G * 32];
__device__ float g_H1 [G * 32 * DH];
__device__ float g_X2 [G * 32 * DH];
__device__ float g_Xp2[G * 16 * DH];
__device__ float g_A2 [G * 16 * 16];
__device__ float g_norm2[G * 16];
__device__ float g_H2 [G * 16 * DH];
__device__ float g_X3 [G * 16 * DH];
__device__ float g_Xp3[G * 8 * DH];
__device__ float g_read[G * 1536];

// ---------------- build sparse adjacency lists + degree norm -------------------
__global__ void build_adj_kernel(const float* __restrict__ adj,
                                 unsigned char* __restrict__ cols,
                                 int* __restrict__ cnt, float* __restrict__ nrm)
{
    int row  = blockIdx.x * 8 + (threadIdx.x >> 5);
    int lane = threadIdx.x & 31;
    const float* a = adj + (long)row * 256;
    unsigned char* lst = cols + (long)row * MAXD;
    int base = 0;
#pragma unroll
    for (int c = 0; c < 8; c++) {
        float v = a[c * 32 + lane];
        unsigned m = __ballot_sync(0xffffffffu, v != 0.f);
        if (v != 0.f) {
            int pos = base + __popc(m & ((1u << lane) - 1));
            if (pos < MAXD) lst[pos] = (unsigned char)(c * 32 + lane);
        }
        base += __popc(m);
    }
    if (lane == 0) {
        cnt[row] = (base > MAXD) ? MAXD : base;
        nrm[row] = rsqrtf(fmaxf((float)base, 1.f));
    }
}

// ---------------- split W0 into bf16 hi/lo -------------------------------------
__global__ void split_w_kernel(const float* __restrict__ W,
                               __nv_bfloat16* __restrict__ Wh,
                               __nv_bfloat16* __restrict__ Wl, int n)
{
    int i = blockIdx.x * 256 + threadIdx.x;
    if (i < n) {
        float v = W[i];
        __nv_bfloat16 h = __float2bfloat16_rn(v);
        Wh[i] = h;
        Wl[i] = __float2bfloat16_rn(v - __bfloat162float(h));
    }
}

// ------- layer-0 sparse aggregation in INPUT space; emits bf16 hi/lo -----------
__global__ void spmm_feat_kernel(const unsigned char* __restrict__ cols,
                                 const int* __restrict__ cnt,
                                 const float* __restrict__ feat,
                                 const float* __restrict__ nrm,
                                 __nv_bfloat16* __restrict__ Yh,
                                 __nv_bfloat16* __restrict__ Yl)
{
    extern __shared__ float sX[];                 // [256][128] = 128 KB
    __shared__ unsigned char sCols[256 * MAXD];   // 32 KB
    __shared__ int   scnt[256];
    __shared__ float snrm[256];

    int g = blockIdx.x, tid = threadIdx.x;
    scnt[tid] = cnt[g * 256 + tid];
    snrm[tid] = nrm[g * 256 + tid];
    __syncthreads();

    {
        const float4* Xg = (const float4*)(feat + (long)g * 32768);
        float4* s4 = (float4*)sX;
        for (int t = tid; t < 8192; t += 256) {
            int r = t >> 5;
            float4 v = Xg[t];
            float s = snrm[r];
            v.x *= s; v.y *= s; v.z *= s; v.w *= s;
            s4[t] = v;
        }
        const uint4* gc = (const uint4*)(cols + (long)g * 256 * MAXD);
        uint4* sc = (uint4*)sCols;
        for (int t = tid; t < 2048; t += 256) sc[t] = gc[t];
    }
    __syncthreads();

    int col4 = tid & 31;
    int rg   = tid >> 5;
    for (int i = rg; i < 256; i += 8) {
        int d = scnt[i];
        const unsigned char* lst = &sCols[i * MAXD];
        float a0 = 0.f, a1 = 0.f, a2 = 0.f, a3 = 0.f;
        int k = 0;
        for (; k + 4 <= d; k += 4) {
            unsigned w = *(const unsigned*)(lst + k);
            int j0 = w & 255, j1 = (w >> 8) & 255, j2 = (w >> 16) & 255, j3 = w >> 24;
            float4 h0 = *(const float4*)(sX + j0 * 128 + col4 * 4);
            float4 h1 = *(const float4*)(sX + j1 * 128 + col4 * 4);
            float4 h2 = *(const float4*)(sX + j2 * 128 + col4 * 4);
            float4 h3 = *(const float4*)(sX + j3 * 128 + col4 * 4);
            a0 += h0.x + h1.x + h2.x + h3.x;
            a1 += h0.y + h1.y + h2.y + h3.y;
            a2 += h0.z + h1.z + h2.z + h3.z;
            a3 += h0.w + h1.w + h2.w + h3.w;
        }
        for (; k < d; k++) {
            int j = lst[k];
            float4 h = *(const float4*)(sX + j * 128 + col4 * 4);
            a0 += h.x; a1 += h.y; a2 += h.z; a3 += h.w;
        }
        float nr = snrm[i];
        float o0 = a0 * nr, o1 = a1 * nr, o2 = a2 * nr, o3 = a3 * nr;
        __nv_bfloat16 h0 = __float2bfloat16_rn(o0);
        __nv_bfloat16 h1 = __float2bfloat16_rn(o1);
        __nv_bfloat16 h2 = __float2bfloat16_rn(o2);
        __nv_bfloat16 h3 = __float2bfloat16_rn(o3);
        long base = (long)g * 32768 + (long)i * 128 + col4 * 4;
        *(__nv_bfloat162*)(Yh + base)     = __nv_bfloat162(h0, h1);
        *(__nv_bfloat162*)(Yh + base + 2) = __nv_bfloat162(h2, h3);
        *(__nv_bfloat162*)(Yl + base) = __nv_bfloat162(
            __float2bfloat16_rn(o0 - __bfloat162float(h0)),
            __float2bfloat16_rn(o1 - __bfloat162float(h1)));
        *(__nv_bfloat162*)(Yl + base + 2) = __nv_bfloat162(
            __float2bfloat16_rn(o2 - __bfloat162float(h2)),
            __float2bfloat16_rn(o3 - __bfloat162float(h3)));
    }
}

// ===== bf16 wmma 3-chain GEMM: X1 = leaky(Y@W0 + b0), fused Ws0 dot ============
// grid (2, 2048), 256 threads (8 warps, 2x4), warp tile 64x32, BK=32.
// C staged in smem with stride 132 (NOT 128): stride-128 rows alias to the same
// banks (512B = 0 mod 128), giving 16-way conflicts on epilogue LDS.128 and on
// store_matrix_sync. 132 words -> 4r mod 32 spread, worst-case 2-way.
#define WAL 40     // A smem row stride (elems)
#define WBL 136    // B smem row stride (elems)
#define WCL 132    // C smem row stride (floats) — bank-conflict padding

__global__ void __launch_bounds__(256, 2) wmma_feat_kernel(
    const __nv_bfloat16* __restrict__ Yh, const __nv_bfloat16* __restrict__ Yl,
    const __nv_bfloat16* __restrict__ Wh, const __nv_bfloat16* __restrict__ Wl,
    const float* __restrict__ bias, const float* __restrict__ Wsp,
    float* __restrict__ X1, float* __restrict__ spreOut)
{
    extern __shared__ char smem[];
    __nv_bfloat16* sAh = (__nv_bfloat16*)smem;      // [128][WAL]
    __nv_bfloat16* sAl = sAh + 128 * WAL;
    __nv_bfloat16* sBh = sAl + 128 * WAL;           // [32][WBL]
    __nv_bfloat16* sBl = sBh + 32 * WBL;
    float* sC = (float*)smem;                       // [128][WCL] (reused)

    int tid = threadIdx.x, warp = tid >> 5;
    int bm = blockIdx.y * 128, bn = blockIdx.x * 128;
    int wm = warp >> 2, wn = warp & 3;

    wmma::fragment<wmma::accumulator, 16, 16, 16, float> acc[4][2];
#pragma unroll
    for (int i = 0; i < 4; i++)
#pragma unroll
        for (int j = 0; j < 2; j++) wmma::fill_fragment(acc[i][j], 0.f);

    for (int k0 = 0; k0 < 128; k0 += 32) {
        // A tile: 128 rows x 32 cols, hi+lo  (512 uint4 each -> 2 per thread)
#pragma unroll
        for (int it = 0; it < 2; it++) {
            int idx = tid + it * 256;
            int r = idx >> 2, c8 = (idx & 3) * 8;
            long gofs = (long)(bm + r) * 128 + k0 + c8;
            *(uint4*)(sAh + r * WAL + c8) = *(const uint4*)(Yh + gofs);
            *(uint4*)(sAl + r * WAL + c8) = *(const uint4*)(Yl + gofs);
        }
        // B tile: 32 rows x 128 cols, hi+lo
#pragma unroll
        for (int it = 0; it < 2; it++) {
            int idx = tid + it * 256;
            int r = idx >> 4, c8 = (idx & 15) * 8;
            long gofs = (long)(k0 + r) * 256 + bn + c8;
            *(uint4*)(sBh + r * WBL + c8) = *(const uint4*)(Wh + gofs);
            *(uint4*)(sBl + r * WBL + c8) = *(const uint4*)(Wl + gofs);
        }
        __syncthreads();

#pragma unroll
        for (int kk = 0; kk < 32; kk += 16) {
            wmma::fragment<wmma::matrix_b, 16, 16, 16, __nv_bfloat16, wmma::row_major> bh[2], bl[2];
#pragma unroll
            for (int j = 0; j < 2; j++) {
                wmma::load_matrix_sync(bh[j], sBh + kk * WBL + wn * 32 + j * 16, WBL);
                wmma::load_matrix_sync(bl[j], sBl + kk * WBL + wn * 32 + j * 16, WBL);
            }
#pragma unroll
            for (int i = 0; i < 4; i++) {
                wmma::fragment<wmma::matrix_a, 16, 16, 16, __nv_bfloat16, wmma::row_major> ah, al;
                wmma::load_matrix_sync(ah, sAh + (wm * 64 + i * 16) * WAL + kk, WAL);
                wmma::load_matrix_sync(al, sAl + (wm * 64 + i * 16) * WAL + kk, WAL);
#pragma unroll
                for (int j = 0; j < 2; j++) {
                    wmma::mma_sync(acc[i][j], ah, bh[j], acc[i][j]);
                    wmma::mma_sync(acc[i][j], ah, bl[j], acc[i][j]);
                    wmma::mma_sync(acc[i][j], al, bh[j], acc[i][j]);
                }
            }
        }
        __syncthreads();
    }

    // stage C through smem (operand tiles dead now) — padded stride WCL
#pragma unroll
    for (int i = 0; i < 4; i++)
#pragma unroll
        for (int j = 0; j < 2; j++)
            wmma::store_matrix_sync(sC + (wm * 64 + i * 16) * WCL + wn * 32 + j * 16,
                                    acc[i][j], WCL, wmma::mem_row_major);
    __syncthreads();

    // epilogue: bias + leaky + fused Ws0 dot; row = tid>>1, 64 cols per thread
    {
        int row = tid >> 1, half = tid & 1;
        int gRow = bm + row;
        float rd = 0.f;
        float* dst = X1 + (long)gRow * 256 + bn + half * 64;
#pragma unroll
        for (int c4 = 0; c4 < 16; c4++) {
            int col = half * 64 + c4 * 4;
            float4 v = *(float4*)(sC + row * WCL + col);
            float4 bv = *(const float4*)(bias + bn + col);
            v.x += bv.x; v.y += bv.y; v.z += bv.z; v.w += bv.w;
            v.x = (v.x > 0.f) ? v.x : 0.01f * v.x;
            v.y = (v.y > 0.f) ? v.y : 0.01f * v.y;
            v.z = (v.z > 0.f) ? v.z : 0.01f * v.z;
            v.w = (v.w > 0.f) ? v.w : 0.01f * v.w;
            float4 wv = *(const float4*)(Wsp + bn + col);
            rd += v.x * wv.x + v.y * wv.y + v.z * wv.z + v.w * wv.w;
            *(float4*)(dst + c4 * 4) = v;
        }
        rd += __shfl_xor_sync(0xffffffffu, rd, 1);
        if (half == 0) spreOut[(long)blockIdx.x * (G * NNODE) + gRow] = rd;
    }
}

// ---------------- dense scalar SGEMM (layers 1/2) ------------------------------
#define BM 128
#define BN 128
#define BK 8

__global__ void sgemm_kernel(const float* __restrict__ A, const float* __restrict__ B,
                             float* __restrict__ C,
                             int M, int N, int K,
                             long bA, long bB, long bC,
                             const float* __restrict__ rsA, int rsAstride,
                             const float* __restrict__ rsC, int rsCstride,
                             const float* __restrict__ bias, int leaky)
{
    int g = blockIdx.z;
    const float* Ag = A + (long)g * bA;
    const float* Bg = B + (long)g * bB;
    float* Cg = C + (long)g * bC;
    const float* rsAg = rsA ? rsA + (long)g * rsAstride : nullptr;
    const float* rsCg = rsC ? rsC + (long)g * rsCstride : nullptr;

    int bm = blockIdx.y * BM;
    int bn = blockIdx.x * BN;

    __shared__ __align__(16) float sA[BK][BM + 4];
    __shared__ __align__(16) float sB[BK][BN + 4];

    int tid = threadIdx.x;
    int a_row = tid >> 1;
    int a_col = (tid & 1) * 4;
    int b_row = tid >> 5;
    int b_col = (tid & 31) * 4;
    int tr = tid >> 4;
    int tc = tid & 15;

    float acc[8][8];
#pragma unroll
    for (int i = 0; i < 8; i++)
#pragma unroll
        for (int j = 0; j < 8; j++) acc[i][j] = 0.f;

    float aScale = rsAg ? rsAg[bm + a_row] : 1.f;

    for (int k0 = 0; k0 < K; k0 += BK) {
        float4 av = *(const float4*)(Ag + (long)(bm + a_row) * K + k0 + a_col);
        av.x *= aScale; av.y *= aScale; av.z *= aScale; av.w *= aScale;
        sA[a_col + 0][a_row] = av.x;
        sA[a_col + 1][a_row] = av.y;
        sA[a_col + 2][a_row] = av.z;
        sA[a_col + 3][a_row] = av.w;
        float4 bv = *(const float4*)(Bg + (long)(k0 + b_row) * N + bn + b_col);
        *(float4*)&sB[b_row][b_col] = bv;
        __syncthreads();
#pragma unroll
        for (int k = 0; k < BK; k++) {
            float4 a0 = *(const float4*)&sA[k][tr * 4];
            float4 a1 = *(const float4*)&sA[k][tr * 4 + 64];
            float4 b0 = *(const float4*)&sB[k][tc * 4];
            float4 b1 = *(const float4*)&sB[k][tc * 4 + 64];
            float ar[8] = {a0.x, a0.y, a0.z, a0.w, a1.x, a1.y, a1.z, a1.w};
            float br[8] = {b0.x, b0.y, b0.z, b0.w, b1.x, b1.y, b1.z, b1.w};
#pragma unroll
            for (int i = 0; i < 8; i++)
#pragma unroll
                for (int j = 0; j < 8; j++) acc[i][j] += ar[i] * br[j];
        }
        __syncthreads();
    }

#pragma unroll
    for (int i = 0; i < 8; i++) {
        int row = bm + ((i < 4) ? (tr * 4 + i) : (64 + tr * 4 + i - 4));
        float rs = rsCg ? rsCg[row] : 1.f;
#pragma unroll
        for (int jg = 0; jg < 2; jg++) {
            int col = bn + tc * 4 + jg * 64;
            float v[4];
#pragma unroll
            for (int jj = 0; jj < 4; jj++) {
                float c = acc[i][jg * 4 + jj] * rs;
                if (bias) c += bias[col + jj];
                if (leaky) c = (c > 0.f) ? c : 0.01f * c;
                v[jj] = c;
            }
            float4 o = make_float4(v[0], v[1], v[2], v[3]);
            *(float4*)(Cg + (long)row * N + col) = o;
        }
    }
}

// ---------------- small batched conv: X = leaky(adj@H * norm + b) ---------------
template <int NN>
__global__ void conv_small_kernel(const float* __restrict__ A, const float* __restrict__ H,
                                  const float* __restrict__ nrm, const float* __restrict__ bias,
                                  float* __restrict__ X)
{
    int g = blockIdx.x;
    __shared__ float sAdj[NN][NN + 1];
    __shared__ float sH[NN][256];
    const float* Ag = A + (long)g * NN * NN;
    const float* Hg = H + (long)g * NN * 256;
    int tid = threadIdx.x;
    for (int t = tid; t < NN * NN; t += 256) sAdj[t / NN][t % NN] = Ag[t];
    for (int t = tid; t < NN * 256; t += 256) sH[t / 256][t % 256] = Hg[t];
    __syncthreads();
    int j = tid;
    float bj = bias[j];
#pragma unroll 4
    for (int i = 0; i < NN; i++) {
        float acc = 0.f;
#pragma unroll
        for (int k = 0; k < NN; k++) acc += sAdj[i][k] * sH[k][j];
        float v = acc * nrm[(long)g * NN + i] + bj;
        X[(long)g * NN * 256 + (long)i * 256 + j] = (v > 0.f) ? v : 0.01f * v;
    }
}

// ---------------- SAGPool (round-5 proven version) -----------------------------
template <int NV, int KK>
__global__ void pool_kernel(const float* __restrict__ X, const float* __restrict__ A,
                            const float* __restrict__ nrm,
                            const float* __restrict__ Ws, const float* __restrict__ bs,
                            const unsigned char* __restrict__ colsL,
                            const int* __restrict__ cntL,
                            const float* __restrict__ spreParts,
                            float* __restrict__ Xp, float* __restrict__ Aout,
                            float* __restrict__ normOut, float* __restrict__ readout,
                            int roff)
{
    int g = blockIdx.x;
    const float* Xg = X + (long)g * NV * 256;
    const float* Ag = A + (long)g * NV * NV;
    const float* ng = nrm + (long)g * NV;

    __shared__ float sWs[256];
    __shared__ float spre[NV];
    __shared__ float ssc[NV];
    __shared__ int   sidx[NV];
    __shared__ float sAn[KK * KK];

    int tid = threadIdx.x, lane = tid & 31, warp = tid >> 5;

    if (spreParts) {
        if (tid < NV)
            spre[tid] = (spreParts[(long)g * NV + tid] +
                         spreParts[(long)G * NNODE + (long)g * NV + tid]) * ng[tid];
        __syncthreads();
    } else {
        sWs[tid] = Ws[tid];
        __syncthreads();
        for (int r = warp; r < NV; r += 8) {
            float acc = 0.f;
            for (int q = lane; q < 256; q += 32) acc += Xg[(long)r * 256 + q] * sWs[q];
#pragma unroll
            for (int s = 16; s > 0; s >>= 1) acc += __shfl_down_sync(0xffffffffu, acc, s);
            if (lane == 0) spre[r] = ng[r] * acc;
        }
        __syncthreads();
    }

    float bsv = bs[0];
    if (colsL) {
        for (int r = warp; r < NV; r += 8) {
            int d = cntL[g * NV + r];
            const unsigned char* lst = colsL + ((long)g * NV + r) * MAXD;
            float acc = 0.f;
            for (int q = lane; q < d; q += 32) acc += spre[lst[q]];
#pragma unroll
            for (int s = 16; s > 0; s >>= 1) acc += __shfl_down_sync(0xffffffffu, acc, s);
            if (lane == 0) { ssc[r] = ng[r] * acc + bsv; sidx[r] = r; }
        }
    } else {
        for (int r = warp; r < NV; r += 8) {
            float acc = 0.f;
            for (int q = lane; q < NV; q += 32) acc += Ag[(long)r * NV + q] * spre[q];
#pragma unroll
            for (int s = 16; s > 0; s >>= 1) acc += __shfl_down_sync(0xffffffffu, acc, s);
            if (lane == 0) { ssc[r] = ng[r] * acc + bsv; sidx[r] = r; }
        }
    }
    __syncthreads();

    for (int ksz = 2; ksz <= NV; ksz <<= 1) {
        for (int j = ksz >> 1; j > 0; j >>= 1) {
            if (tid < NV) {
                int ixj = tid ^ j;
                if (ixj > tid) {
                    float s1 = ssc[tid], s2 = ssc[ixj];
                    int i1 = sidx[tid], i2 = sidx[ixj];
                    bool firstWorse = (s1 < s2) || (s1 == s2 && i1 > i2);
                    bool descRegion = ((tid & ksz) == 0);
                    bool doSwap = descRegion ? firstWorse : !firstWorse;
                    if (doSwap) {
                        ssc[tid] = s2; ssc[ixj] = s1;
                        sidx[tid] = i2; sidx[ixj] = i1;
                    }
                }
            }
            __syncthreads();
        }
    }

    if (tid < KK) ssc[tid] = tanhf(ssc[tid]);
    __syncthreads();

    {
        int j = tid;
        float csum = 0.f, cmax = -3.402823466e38f;
#pragma unroll 4
        for (int r = 0; r < KK; r++) {
            int row = sidx[r];
            float v = Xg[(long)row * 256 + j] * ssc[r];
            Xp[(long)g * KK * 256 + (long)r * 256 + j] = v;
            csum += v;
            cmax = fmaxf(cmax, v);
        }
        readout[(long)g * 1536 + roff + j] = csum;
        readout[(long)g * 1536 + roff + 256 + j] = cmax;
    }

    if (Aout) {
        for (int t = tid; t < KK * KK; t += 256) {
            int r = t / KK, c = t % KK;
            sAn[t] = Ag[(long)sidx[r] * NV + sidx[c]];
        }
        __syncthreads();
        for (int t = tid; t < KK * KK; t += 256) Aout[(long)g * KK * KK + t] = sAn[t];
        if (tid < KK) {
            float d = 0.f;
#pragma unroll
            for (int c = 0; c < KK; c++) d += sAn[tid * KK + c];
            normOut[(long)g * KK + tid] = rsqrtf(fmaxf(d, 1.f));
        }
    }
}

// ====== fused MLP head (round-7 proven) ========================================
__global__ void __launch_bounds__(256) mlp_head_kernel(
    const float* __restrict__ read, const float* __restrict__ Wd1,
    const float* __restrict__ bd1, const float* __restrict__ Wd2,
    const float* __restrict__ bd2, float* __restrict__ out)
{
    extern __shared__ float sm[];
    float* sR = sm;
    float* sP = sm + 4 * 1536;
    float* sH = sP;

    int tid = threadIdx.x;
    int g0 = blockIdx.x * 4;
    int lane = tid & 31, kw = tid >> 5;

    {
        const float4* src = (const float4*)(read + (long)g0 * 1536);
        float4* d4 = (float4*)sR;
#pragma unroll
        for (int i = 0; i < 6; i++) d4[tid + i * 256] = src[tid + i * 256];
    }
    __syncthreads();

    float4 acc[4];
#pragma unroll
    for (int gg = 0; gg < 4; gg++) acc[gg] = make_float4(0.f, 0.f, 0.f, 0.f);
    {
        const float4* W14 = (const float4*)Wd1;
        int kbeg = kw * 192;
#pragma unroll 2
        for (int k = kbeg; k < kbeg + 192; k++) {
            float4 wd = __ldg(&W14[k * 32 + lane]);
#pragma unroll
            for (int gg = 0; gg < 4; gg++) {
                float rv = sR[gg * 1536 + k];
                acc[gg].x += rv * wd.x;
                acc[gg].y += rv * wd.y;
                acc[gg].z += rv * wd.z;
                acc[gg].w += rv * wd.w;
            }
        }
    }
#pragma unroll
    for (int gg = 0; gg < 4; gg++)
        ((float4*)sP)[(kw * 4 + gg) * 32 + lane] = acc[gg];
    __syncthreads();

#pragma unroll
    for (int rep = 0; rep < 2; rep++) {
        int idx = tid + rep * 256;
        int gg = idx >> 7, j = idx & 127;
        float s = 0.f;
#pragma unroll
        for (int w = 0; w < 8; w++) s += sP[(w * 4 + gg) * 128 + j];
        s += bd1[j];
        s = (s > 0.f) ? s : 0.01f * s;
        acc[0].x = s;
        __syncthreads();
        sH[gg * 128 + j] = acc[0].x;
        __syncthreads();
    }

    if (kw < 4) {
        float a0 = 0.f, a1 = 0.f;
#pragma unroll
        for (int c = 0; c < 4; c++) {
            int k = lane + c * 32;
            float h = sH[kw * 128 + k];
            a0 += h * Wd2[k * 2 + 0];
            a1 += h * Wd2[k * 2 + 1];
        }
#pragma unroll
        for (int s = 16; s > 0; s >>= 1) {
            a0 += __shfl_down_sync(0xffffffffu, a0, s);
            a1 += __shfl_down_sync(0xffffffffu, a1, s);
        }
        if (lane == 0) {
            out[(g0 + kw) * 2 + 0] = 1.f / (1.f + expf(-(a0 + bd2[0])));
            out[(g0 + kw) * 2 + 1] = 1.f / (1.f + expf(-(a1 + bd2[1])));
        }
    }
}

// --------------------------------- launch --------------------------------------
extern "C" void kernel_launch(void* const* d_in, const int* in_sizes, int n_in,
                              void* d_out, int out_size)
{
    const float* feat = (const float*)d_in[0];
    const float* adj  = (const float*)d_in[1];
    const float* W0   = (const float*)d_in[2];
    const float* b0   = (const float*)d_in[3];
    const float* Ws0  = (const float*)d_in[4];
    const float* bs0  = (const float*)d_in[5];
    const float* W1   = (const float*)d_in[6];
    const float* b1   = (const float*)d_in[7];
    const float* Ws1  = (const float*)d_in[8];
    const float* bs1  = (const float*)d_in[9];
    const float* W2   = (const float*)d_in[10];
    const float* b2   = (const float*)d_in[11];
    const float* Ws2  = (const float*)d_in[12];
    const float* bs2  = (const float*)d_in[13];
    const float* Wd1  = (const float*)d_in[14];
    const float* bd1  = (const float*)d_in[15];
    const float* Wd2  = (const float*)d_in[16];
    const float* bd2  = (const float*)d_in[17];
    float* out = (float*)d_out;

    float *p_norm0, *p_X1, *p_spre, *p_Xp1, *p_A1, *p_norm1, *p_H1, *p_X2;
    float *p_Xp2, *p_A2, *p_norm2, *p_H2, *p_X3, *p_Xp3, *p_read;
    unsigned char* p_cols; int* p_cnt;
    __nv_bfloat16 *p_Yh, *p_Yl, *p_W0h, *p_W0l;
    cudaGetSymbolAddress((void**)&p_norm0, g_norm0);
    cudaGetSymbolAddress((void**)&p_cols, g_cols);
    cudaGetSymbolAddress((void**)&p_cnt, g_cnt);
    cudaGetSymbolAddress((void**)&p_Yh, g_Yh);
    cudaGetSymbolAddress((void**)&p_Yl, g_Yl);
    cudaGetSymbolAddress((void**)&p_W0h, g_W0h);
    cudaGetSymbolAddress((void**)&p_W0l, g_W0l);
    cudaGetSymbolAddress((void**)&p_X1, g_X1);
    cudaGetSymbolAddress((void**)&p_spre, g_spre);
    cudaGetSymbolAddress((void**)&p_Xp1, g_Xp1);
    cudaGetSymbolAddress((void**)&p_A1, g_A1);
    cudaGetSymbolAddress((void**)&p_norm1, g_norm1);
    cudaGetSymbolAddress((void**)&p_H1, g_H1);
    cudaGetSymbolAddress((void**)&p_X2, g_X2);
    cudaGetSymbolAddress((void**)&p_Xp2, g_Xp2);
    cudaGetSymbolAddress((void**)&p_A2, g_A2);
    cudaGetSymbolAddress((void**)&p_norm2, g_norm2);
    cudaGetSymbolAddress((void**)&p_H2, g_H2);
    cudaGetSymbolAddress((void**)&p_X3, g_X3);
    cudaGetSymbolAddress((void**)&p_Xp3, g_Xp3);
    cudaGetSymbolAddress((void**)&p_read, g_read);

    const int headSmem = (4 * 1536 + 8 * 4 * 128) * 4;
    const int wmmaSmem = 128 * 132 * 4;   // 67.6 KB: C staging padded to stride 132
    cudaFuncSetAttribute(spmm_feat_kernel, cudaFuncAttributeMaxDynamicSharedMemorySize, 131072);
    cudaFuncSetAttribute(mlp_head_kernel, cudaFuncAttributeMaxDynamicSharedMemorySize, headSmem);
    cudaFuncSetAttribute(wmma_feat_kernel, cudaFuncAttributeMaxDynamicSharedMemorySize, wmmaSmem);

    // ---- layer 0
    build_adj_kernel<<<G * NNODE / 8, 256>>>(adj, p_cols, p_cnt, p_norm0);
    split_w_kernel<<<(FIN * DH + 255) / 256, 256>>>(W0, p_W0h, p_W0l, FIN * DH);
    spmm_feat_kernel<<<G, 256, 131072>>>(p_cols, p_cnt, feat, p_norm0, p_Yh, p_Yl);
    wmma_feat_kernel<<<dim3(2, 2048, 1), 256, wmmaSmem>>>(p_Yh, p_Yl, p_W0h, p_W0l,
                                                          b0, Ws0, p_X1, p_spre);
    pool_kernel<256, 32><<<G, 256>>>(p_X1, adj, p_norm0, Ws0, bs0, p_cols, p_cnt,
                                     p_spre, p_Xp1, p_A1, p_norm1, p_read, 0);
    // ---- layer 1
    sgemm_kernel<<<dim3(2, 256, 1), 256>>>(p_Xp1, W1, p_H1, G * 32, DH, DH,
                                           0, 0, 0, p_norm1, 0, nullptr, 0, nullptr, 0);
    conv_small_kernel<32><<<G, 256>>>(p_A1, p_H1, p_norm1, b1, p_X2);
    pool_kernel<32, 16><<<G, 256>>>(p_X2, p_A1, p_norm1, Ws1, bs1, nullptr, nullptr,
                                    nullptr, p_Xp2, p_A2, p_norm2, p_read, 512);
    // ---- layer 2
    sgemm_kernel<<<dim3(2, 128, 1), 256>>>(p_Xp2, W2, p_H2, G * 16, DH, DH,
                                           0, 0, 0, p_norm2, 0, nullptr, 0, nullptr, 0);
    conv_small_kernel<16><<<G, 256>>>(p_A2, p_H2, p_norm2, b2, p_X3);
    pool_kernel<16, 8><<<G, 256>>>(p_X3, p_A2, p_norm2, Ws2, bs2, nullptr, nullptr,
                                   nullptr, p_Xp3, nullptr, nullptr, p_read, 1024);
    // ---- fused MLP head
    mlp_head_kernel<<<G / 4, 256, headSmem>>>(p_read, Wd1, bd1, Wd2, bd2, out);
}

// round 11
// speedup vs baseline: 1.4110x; 1.0206x over previous
#include <cuda_runtime.h>
#include <cuda_bf16.h>
#include <mma.h>
#include <math.h>

using namespace nvcuda;

#define G 1024
#define NNODE 256
#define FIN 128
#define DH 256
#define MAXD 128

// ---------------- scratch (device globals; no allocations allowed) -------------
__device__ float g_norm0[G * NNODE];
__device__ unsigned char g_cols[(long)G * NNODE * MAXD];
__device__ int   g_cnt [G * NNODE];
__device__ __nv_bfloat16 g_Yh[(long)G * NNODE * FIN];
__device__ __nv_bfloat16 g_Yl[(long)G * NNODE * FIN];
__device__ __nv_bfloat16 g_W0h[FIN * DH];
__device__ __nv_bfloat16 g_W0l[FIN * DH];
__device__ float g_X1 [G * NNODE * DH];
__device__ float g_spre[2 * G * NNODE];
__device__ float g_Xp1[G * 32 * DH];
__device__ float g_A1 [G * 32 * 32];
__device__ float g_norm1[G * 32];
__device__ float g_H1 [G * 32 * DH];
__device__ float g_X2 [G * 32 * DH];
__device__ float g_Xp2[G * 16 * DH];
__device__ float g_A2 [G * 16 * 16];
__device__ float g_norm2[G * 16];
__device__ float g_H2 [G * 16 * DH];
__device__ float g_X3 [G * 16 * DH];
__device__ float g_Xp3[G * 8 * DH];
__device__ float g_read[G * 1536];

// ---------------- cp.async helpers ---------------------------------------------
__device__ __forceinline__ void cp_async16(unsigned saddr, const void* gptr) {
    asm volatile("cp.async.cg.shared.global [%0], [%1], 16;" :: "r"(saddr), "l"(gptr));
}

// ---------------- build sparse adjacency lists + degree norm -------------------
__global__ void build_adj_kernel(const float* __restrict__ adj,
                                 unsigned char* __restrict__ cols,
                                 int* __restrict__ cnt, float* __restrict__ nrm)
{
    int row  = blockIdx.x * 8 + (threadIdx.x >> 5);
    int lane = threadIdx.x & 31;
    const float* a = adj + (long)row * 256;
    unsigned char* lst = cols + (long)row * MAXD;
    int base = 0;
#pragma unroll
    for (int c = 0; c < 8; c++) {
        float v = a[c * 32 + lane];
        unsigned m = __ballot_sync(0xffffffffu, v != 0.f);
        if (v != 0.f) {
            int pos = base + __popc(m & ((1u << lane) - 1));
            if (pos < MAXD) lst[pos] = (unsigned char)(c * 32 + lane);
        }
        base += __popc(m);
    }
    if (lane == 0) {
        cnt[row] = (base > MAXD) ? MAXD : base;
        nrm[row] = rsqrtf(fmaxf((float)base, 1.f));
    }
}

// ---------------- split W0 into bf16 hi/lo -------------------------------------
__global__ void split_w_kernel(const float* __restrict__ W,
                               __nv_bfloat16* __restrict__ Wh,
                               __nv_bfloat16* __restrict__ Wl, int n)
{
    int i = blockIdx.x * 256 + threadIdx.x;
    if (i < n) {
        float v = W[i];
        __nv_bfloat16 h = __float2bfloat16_rn(v);
        Wh[i] = h;
        Wl[i] = __float2bfloat16_rn(v - __bfloat162float(h));
    }
}

// ------- layer-0 sparse aggregation in INPUT space; emits bf16 hi/lo -----------
__global__ void spmm_feat_kernel(const unsigned char* __restrict__ cols,
                                 const int* __restrict__ cnt,
                                 const float* __restrict__ feat,
                                 const float* __restrict__ nrm,
                                 __nv_bfloat16* __restrict__ Yh,
                                 __nv_bfloat16* __restrict__ Yl)
{
    extern __shared__ float sX[];                 // [256][128] = 128 KB
    __shared__ unsigned char sCols[256 * MAXD];   // 32 KB
    __shared__ int   scnt[256];
    __shared__ float snrm[256];

    int g = blockIdx.x, tid = threadIdx.x;
    scnt[tid] = cnt[g * 256 + tid];
    snrm[tid] = nrm[g * 256 + tid];
    __syncthreads();

    {
        const float4* Xg = (const float4*)(feat + (long)g * 32768);
        float4* s4 = (float4*)sX;
        for (int t = tid; t < 8192; t += 256) {
            int r = t >> 5;
            float4 v = Xg[t];
            float s = snrm[r];
            v.x *= s; v.y *= s; v.z *= s; v.w *= s;
            s4[t] = v;
        }
        const uint4* gc = (const uint4*)(cols + (long)g * 256 * MAXD);
        uint4* sc = (uint4*)sCols;
        for (int t = tid; t < 2048; t += 256) sc[t] = gc[t];
    }
    __syncthreads();

    int col4 = tid & 31;
    int rg   = tid >> 5;
    for (int i = rg; i < 256; i += 8) {
        int d = scnt[i];
        const unsigned char* lst = &sCols[i * MAXD];
        float a0 = 0.f, a1 = 0.f, a2 = 0.f, a3 = 0.f;
        int k = 0;
        for (; k + 4 <= d; k += 4) {
            unsigned w = *(const unsigned*)(lst + k);
            int j0 = w & 255, j1 = (w >> 8) & 255, j2 = (w >> 16) & 255, j3 = w >> 24;
            float4 h0 = *(const float4*)(sX + j0 * 128 + col4 * 4);
            float4 h1 = *(const float4*)(sX + j1 * 128 + col4 * 4);
            float4 h2 = *(const float4*)(sX + j2 * 128 + col4 * 4);
            float4 h3 = *(const float4*)(sX + j3 * 128 + col4 * 4);
            a0 += h0.x + h1.x + h2.x + h3.x;
            a1 += h0.y + h1.y + h2.y + h3.y;
            a2 += h0.z + h1.z + h2.z + h3.z;
            a3 += h0.w + h1.w + h2.w + h3.w;
        }
        for (; k < d; k++) {
            int j = lst[k];
            float4 h = *(const float4*)(sX + j * 128 + col4 * 4);
            a0 += h.x; a1 += h.y; a2 += h.z; a3 += h.w;
        }
        float nr = snrm[i];
        float o0 = a0 * nr, o1 = a1 * nr, o2 = a2 * nr, o3 = a3 * nr;
        __nv_bfloat16 h0 = __float2bfloat16_rn(o0);
        __nv_bfloat16 h1 = __float2bfloat16_rn(o1);
        __nv_bfloat16 h2 = __float2bfloat16_rn(o2);
        __nv_bfloat16 h3 = __float2bfloat16_rn(o3);
        long base = (long)g * 32768 + (long)i * 128 + col4 * 4;
        *(__nv_bfloat162*)(Yh + base)     = __nv_bfloat162(h0, h1);
        *(__nv_bfloat162*)(Yh + base + 2) = __nv_bfloat162(h2, h3);
        *(__nv_bfloat162*)(Yl + base) = __nv_bfloat162(
            __float2bfloat16_rn(o0 - __bfloat162float(h0)),
            __float2bfloat16_rn(o1 - __bfloat162float(h1)));
        *(__nv_bfloat162*)(Yl + base + 2) = __nv_bfloat162(
            __float2bfloat16_rn(o2 - __bfloat162float(h2)),
            __float2bfloat16_rn(o3 - __bfloat162float(h3)));
    }
}

// ===== bf16 wmma 3-chain GEMM, cp.async double-buffered ========================
// grid (2, 2048), 256 threads (8 warps, 2x4), warp tile 64x32, BK=32.
// WAL=56 (112B row stride): 16B-aligned for cp.async AND conflict-free for LDSM
// (28r mod 32 distinct over 8 rows). WBL=136 (272B) likewise. C staged at WCL=132.
#define WAL 56     // A smem row stride (elems)
#define WBL 136    // B smem row stride (elems)
#define WCL 132    // C smem row stride (floats)
// stage layout (bytes): Ah@0 (14336), Al@14336, Bh@28672 (8704), Bl@37376; total 46080
#define STG_B 46080
#define STG_E 23040

__global__ void __launch_bounds__(256, 2) wmma_feat_kernel(
    const __nv_bfloat16* __restrict__ Yh, const __nv_bfloat16* __restrict__ Yl,
    const __nv_bfloat16* __restrict__ Wh, const __nv_bfloat16* __restrict__ Wl,
    const float* __restrict__ bias, const float* __restrict__ Wsp,
    float* __restrict__ X1, float* __restrict__ spreOut)
{
    extern __shared__ char smem[];
    __nv_bfloat16* sb = (__nv_bfloat16*)smem;
    float* sC = (float*)smem;                       // [128][WCL] (reused after loop)
    unsigned sb32 = (unsigned)__cvta_generic_to_shared(smem);

    int tid = threadIdx.x, warp = tid >> 5;
    int bm = blockIdx.y * 128, bn = blockIdx.x * 128;
    int wm = warp >> 2, wn = warp & 3;

    wmma::fragment<wmma::accumulator, 16, 16, 16, float> acc[4][2];
#pragma unroll
    for (int i = 0; i < 4; i++)
#pragma unroll
        for (int j = 0; j < 2; j++) wmma::fill_fragment(acc[i][j], 0.f);

    // async tile loader: tile k0 (element col offset) into buffer buf
    auto issue_tile = [&](int k0, int buf) {
        unsigned base = sb32 + buf * STG_B;
#pragma unroll
        for (int it = 0; it < 2; it++) {
            int idx = tid + it * 256;
            int r = idx >> 2, c8 = (idx & 3) * 8;
            long gofs = (long)(bm + r) * 128 + k0 + c8;
            unsigned aoff = (unsigned)(r * WAL + c8) * 2;
            cp_async16(base + aoff, Yh + gofs);
            cp_async16(base + 14336 + aoff, Yl + gofs);
        }
#pragma unroll
        for (int it = 0; it < 2; it++) {
            int idx = tid + it * 256;
            int r = idx >> 4, c8 = (idx & 15) * 8;
            long gofs = (long)(k0 + r) * 256 + bn + c8;
            unsigned boff = (unsigned)(r * WBL + c8) * 2;
            cp_async16(base + 28672 + boff, Wh + gofs);
            cp_async16(base + 37376 + boff, Wl + gofs);
        }
        asm volatile("cp.async.commit_group;" ::: "memory");
    };

    issue_tile(0, 0);

    for (int k = 0; k < 4; k++) {
        if (k < 3) {
            issue_tile((k + 1) * 32, (k + 1) & 1);
            asm volatile("cp.async.wait_group 1;" ::: "memory");
        } else {
            asm volatile("cp.async.wait_group 0;" ::: "memory");
        }
        __syncthreads();

        __nv_bfloat16* sAh = sb + (k & 1) * STG_E;
        __nv_bfloat16* sAl = sAh + 7168;
        __nv_bfloat16* sBh = sAh + 14336;
        __nv_bfloat16* sBl = sAh + 18688;

#pragma unroll
        for (int kk = 0; kk < 32; kk += 16) {
            wmma::fragment<wmma::matrix_b, 16, 16, 16, __nv_bfloat16, wmma::row_major> bh[2], bl[2];
#pragma unroll
            for (int j = 0; j < 2; j++) {
                wmma::load_matrix_sync(bh[j], sBh + kk * WBL + wn * 32 + j * 16, WBL);
                wmma::load_matrix_sync(bl[j], sBl + kk * WBL + wn * 32 + j * 16, WBL);
            }
#pragma unroll
            for (int i = 0; i < 4; i++) {
                wmma::fragment<wmma::matrix_a, 16, 16, 16, __nv_bfloat16, wmma::row_major> ah, al;
                wmma::load_matrix_sync(ah, sAh + (wm * 64 + i * 16) * WAL + kk, WAL);
                wmma::load_matrix_sync(al, sAl + (wm * 64 + i * 16) * WAL + kk, WAL);
#pragma unroll
                for (int j = 0; j < 2; j++) {
                    wmma::mma_sync(acc[i][j], ah, bh[j], acc[i][j]);
                    wmma::mma_sync(acc[i][j], ah, bl[j], acc[i][j]);
                    wmma::mma_sync(acc[i][j], al, bh[j], acc[i][j]);
                }
            }
        }
        __syncthreads();
    }

    // stage C through smem (operand stages dead now) — padded stride WCL
#pragma unroll
    for (int i = 0; i < 4; i++)
#pragma unroll
        for (int j = 0; j < 2; j++)
            wmma::store_matrix_sync(sC + (wm * 64 + i * 16) * WCL + wn * 32 + j * 16,
                                    acc[i][j], WCL, wmma::mem_row_major);
    __syncthreads();

    // epilogue: bias + leaky + fused Ws0 dot; row = tid>>1, 64 cols per thread
    {
        int row = tid >> 1, half = tid & 1;
        int gRow = bm + row;
        float rd = 0.f;
        float* dst = X1 + (long)gRow * 256 + bn + half * 64;
#pragma unroll
        for (int c4 = 0; c4 < 16; c4++) {
            int col = half * 64 + c4 * 4;
            float4 v = *(float4*)(sC + row * WCL + col);
            float4 bv = *(const float4*)(bias + bn + col);
            v.x += bv.x; v.y += bv.y; v.z += bv.z; v.w += bv.w;
            v.x = (v.x > 0.f) ? v.x : 0.01f * v.x;
            v.y = (v.y > 0.f) ? v.y : 0.01f * v.y;
            v.z = (v.z > 0.f) ? v.z : 0.01f * v.z;
            v.w = (v.w > 0.f) ? v.w : 0.01f * v.w;
            float4 wv = *(const float4*)(Wsp + bn + col);
            rd += v.x * wv.x + v.y * wv.y + v.z * wv.z + v.w * wv.w;
            *(float4*)(dst + c4 * 4) = v;
        }
        rd += __shfl_xor_sync(0xffffffffu, rd, 1);
        if (half == 0) spreOut[(long)blockIdx.x * (G * NNODE) + gRow] = rd;
    }
}

// ---------------- dense scalar SGEMM (layers 1/2) ------------------------------
#define BM 128
#define BN 128
#define BK 8

__global__ void sgemm_kernel(const float* __restrict__ A, const float* __restrict__ B,
                             float* __restrict__ C,
                             int M, int N, int K,
                             long bA, long bB, long bC,
                             const float* __restrict__ rsA, int rsAstride,
                             const float* __restrict__ rsC, int rsCstride,
                             const float* __restrict__ bias, int leaky)
{
    int g = blockIdx.z;
    const float* Ag = A + (long)g * bA;
    const float* Bg = B + (long)g * bB;
    float* Cg = C + (long)g * bC;
    const float* rsAg = rsA ? rsA + (long)g * rsAstride : nullptr;
    const float* rsCg = rsC ? rsC + (long)g * rsCstride : nullptr;

    int bm = blockIdx.y * BM;
    int bn = blockIdx.x * BN;

    __shared__ __align__(16) float sA[BK][BM + 4];
    __shared__ __align__(16) float sB[BK][BN + 4];

    int tid = threadIdx.x;
    int a_row = tid >> 1;
    int a_col = (tid & 1) * 4;
    int b_row = tid >> 5;
    int b_col = (tid & 31) * 4;
    int tr = tid >> 4;
    int tc = tid & 15;

    float acc[8][8];
#pragma unroll
    for (int i = 0; i < 8; i++)
#pragma unroll
        for (int j = 0; j < 8; j++) acc[i][j] = 0.f;

    float aScale = rsAg ? rsAg[bm + a_row] : 1.f;

    for (int k0 = 0; k0 < K; k0 += BK) {
        float4 av = *(const float4*)(Ag + (long)(bm + a_row) * K + k0 + a_col);
        av.x *= aScale; av.y *= aScale; av.z *= aScale; av.w *= aScale;
        sA[a_col + 0][a_row] = av.x;
        sA[a_col + 1][a_row] = av.y;
        sA[a_col + 2][a_row] = av.z;
        sA[a_col + 3][a_row] = av.w;
        float4 bv = *(const float4*)(Bg + (long)(k0 + b_row) * N + bn + b_col);
        *(float4*)&sB[b_row][b_col] = bv;
        __syncthreads();
#pragma unroll
        for (int k = 0; k < BK; k++) {
            float4 a0 = *(const float4*)&sA[k][tr * 4];
            float4 a1 = *(const float4*)&sA[k][tr * 4 + 64];
            float4 b0 = *(const float4*)&sB[k][tc * 4];
            float4 b1 = *(const float4*)&sB[k][tc * 4 + 64];
            float ar[8] = {a0.x, a0.y, a0.z, a0.w, a1.x, a1.y, a1.z, a1.w};
            float br[8] = {b0.x, b0.y, b0.z, b0.w, b1.x, b1.y, b1.z, b1.w};
#pragma unroll
            for (int i = 0; i < 8; i++)
#pragma unroll
                for (int j = 0; j < 8; j++) acc[i][j] += ar[i] * br[j];
        }
        __syncthreads();
    }

#pragma unroll
    for (int i = 0; i < 8; i++) {
        int row = bm + ((i < 4) ? (tr * 4 + i) : (64 + tr * 4 + i - 4));
        float rs = rsCg ? rsCg[row] : 1.f;
#pragma unroll
        for (int jg = 0; jg < 2; jg++) {
            int col = bn + tc * 4 + jg * 64;
            float v[4];
#pragma unroll
            for (int jj = 0; jj < 4; jj++) {
                float c = acc[i][jg * 4 + jj] * rs;
                if (bias) c += bias[col + jj];
                if (leaky) c = (c > 0.f) ? c : 0.01f * c;
                v[jj] = c;
            }
            float4 o = make_float4(v[0], v[1], v[2], v[3]);
            *(float4*)(Cg + (long)row * N + col) = o;
        }
    }
}

// ---------------- small batched conv: X = leaky(adj@H * norm + b) ---------------
template <int NN>
__global__ void conv_small_kernel(const float* __restrict__ A, const float* __restrict__ H,
                                  const float* __restrict__ nrm, const float* __restrict__ bias,
                                  float* __restrict__ X)
{
    int g = blockIdx.x;
    __shared__ float sAdj[NN][NN + 1];
    __shared__ float sH[NN][256];
    const float* Ag = A + (long)g * NN * NN;
    const float* Hg = H + (long)g * NN * 256;
    int tid = threadIdx.x;
    for (int t = tid; t < NN * NN; t += 256) sAdj[t / NN][t % NN] = Ag[t];
    for (int t = tid; t < NN * 256; t += 256) sH[t / 256][t % 256] = Hg[t];
    __syncthreads();
    int j = tid;
    float bj = bias[j];
#pragma unroll 4
    for (int i = 0; i < NN; i++) {
        float acc = 0.f;
#pragma unroll
        for (int k = 0; k < NN; k++) acc += sAdj[i][k] * sH[k][j];
        float v = acc * nrm[(long)g * NN + i] + bj;
        X[(long)g * NN * 256 + (long)i * 256 + j] = (v > 0.f) ? v : 0.01f * v;
    }
}

// ---------------- SAGPool (round-5 proven version) -----------------------------
template <int NV, int KK>
__global__ void pool_kernel(const float* __restrict__ X, const float* __restrict__ A,
                            const float* __restrict__ nrm,
                            const float* __restrict__ Ws, const float* __restrict__ bs,
                            const unsigned char* __restrict__ colsL,
                            const int* __restrict__ cntL,
                            const float* __restrict__ spreParts,
                            float* __restrict__ Xp, float* __restrict__ Aout,
                            float* __restrict__ normOut, float* __restrict__ readout,
                            int roff)
{
    int g = blockIdx.x;
    const float* Xg = X + (long)g * NV * 256;
    const float* Ag = A + (long)g * NV * NV;
    const float* ng = nrm + (long)g * NV;

    __shared__ float sWs[256];
    __shared__ float spre[NV];
    __shared__ float ssc[NV];
    __shared__ int   sidx[NV];
    __shared__ float sAn[KK * KK];

    int tid = threadIdx.x, lane = tid & 31, warp = tid >> 5;

    if (spreParts) {
        if (tid < NV)
            spre[tid] = (spreParts[(long)g * NV + tid] +
                         spreParts[(long)G * NNODE + (long)g * NV + tid]) * ng[tid];
        __syncthreads();
    } else {
        sWs[tid] = Ws[tid];
        __syncthreads();
        for (int r = warp; r < NV; r += 8) {
            float acc = 0.f;
            for (int q = lane; q < 256; q += 32) acc += Xg[(long)r * 256 + q] * sWs[q];
#pragma unroll
            for (int s = 16; s > 0; s >>= 1) acc += __shfl_down_sync(0xffffffffu, acc, s);
            if (lane == 0) spre[r] = ng[r] * acc;
        }
        __syncthreads();
    }

    float bsv = bs[0];
    if (colsL) {
        for (int r = warp; r < NV; r += 8) {
            int d = cntL[g * NV + r];
            const unsigned char* lst = colsL + ((long)g * NV + r) * MAXD;
            float acc = 0.f;
            for (int q = lane; q < d; q += 32) acc += spre[lst[q]];
#pragma unroll
            for (int s = 16; s > 0; s >>= 1) acc += __shfl_down_sync(0xffffffffu, acc, s);
            if (lane == 0) { ssc[r] = ng[r] * acc + bsv; sidx[r] = r; }
        }
    } else {
        for (int r = warp; r < NV; r += 8) {
            float acc = 0.f;
            for (int q = lane; q < NV; q += 32) acc += Ag[(long)r * NV + q] * spre[q];
#pragma unroll
            for (int s = 16; s > 0; s >>= 1) acc += __shfl_down_sync(0xffffffffu, acc, s);
            if (lane == 0) { ssc[r] = ng[r] * acc + bsv; sidx[r] = r; }
        }
    }
    __syncthreads();

    for (int ksz = 2; ksz <= NV; ksz <<= 1) {
        for (int j = ksz >> 1; j > 0; j >>= 1) {
            if (tid < NV) {
                int ixj = tid ^ j;
                if (ixj > tid) {
                    float s1 = ssc[tid], s2 = ssc[ixj];
                    int i1 = sidx[tid], i2 = sidx[ixj];
                    bool firstWorse = (s1 < s2) || (s1 == s2 && i1 > i2);
                    bool descRegion = ((tid & ksz) == 0);
                    bool doSwap = descRegion ? firstWorse : !firstWorse;
                    if (doSwap) {
                        ssc[tid] = s2; ssc[ixj] = s1;
                        sidx[tid] = i2; sidx[ixj] = i1;
                    }
                }
            }
            __syncthreads();
        }
    }

    if (tid < KK) ssc[tid] = tanhf(ssc[tid]);
    __syncthreads();

    {
        int j = tid;
        float csum = 0.f, cmax = -3.402823466e38f;
#pragma unroll 4
        for (int r = 0; r < KK; r++) {
            int row = sidx[r];
            float v = Xg[(long)row * 256 + j] * ssc[r];
            Xp[(long)g * KK * 256 + (long)r * 256 + j] = v;
            csum += v;
            cmax = fmaxf(cmax, v);
        }
        readout[(long)g * 1536 + roff + j] = csum;
        readout[(long)g * 1536 + roff + 256 + j] = cmax;
    }

    if (Aout) {
        for (int t = tid; t < KK * KK; t += 256) {
            int r = t / KK, c = t % KK;
            sAn[t] = Ag[(long)sidx[r] * NV + sidx[c]];
        }
        __syncthreads();
        for (int t = tid; t < KK * KK; t += 256) Aout[(long)g * KK * KK + t] = sAn[t];
        if (tid < KK) {
            float d = 0.f;
#pragma unroll
            for (int c = 0; c < KK; c++) d += sAn[tid * KK + c];
            normOut[(long)g * KK + tid] = rsqrtf(fmaxf(d, 1.f));
        }
    }
}

// ====== fused MLP head (round-7 proven) ========================================
__global__ void __launch_bounds__(256) mlp_head_kernel(
    const float* __restrict__ read, const float* __restrict__ Wd1,
    const float* __restrict__ bd1, const float* __restrict__ Wd2,
    const float* __restrict__ bd2, float* __restrict__ out)
{
    extern __shared__ float sm[];
    float* sR = sm;
    float* sP = sm + 4 * 1536;
    float* sH = sP;

    int tid = threadIdx.x;
    int g0 = blockIdx.x * 4;
    int lane = tid & 31, kw = tid >> 5;

    {
        const float4* src = (const float4*)(read + (long)g0 * 1536);
        float4* d4 = (float4*)sR;
#pragma unroll
        for (int i = 0; i < 6; i++) d4[tid + i * 256] = src[tid + i * 256];
    }
    __syncthreads();

    float4 acc[4];
#pragma unroll
    for (int gg = 0; gg < 4; gg++) acc[gg] = make_float4(0.f, 0.f, 0.f, 0.f);
    {
        const float4* W14 = (const float4*)Wd1;
        int kbeg = kw * 192;
#pragma unroll 2
        for (int k = kbeg; k < kbeg + 192; k++) {
            float4 wd = __ldg(&W14[k * 32 + lane]);
#pragma unroll
            for (int gg = 0; gg < 4; gg++) {
                float rv = sR[gg * 1536 + k];
                acc[gg].x += rv * wd.x;
                acc[gg].y += rv * wd.y;
                acc[gg].z += rv * wd.z;
                acc[gg].w += rv * wd.w;
            }
        }
    }
#pragma unroll
    for (int gg = 0; gg < 4; gg++)
        ((float4*)sP)[(kw * 4 + gg) * 32 + lane] = acc[gg];
    __syncthreads();

#pragma unroll
    for (int rep = 0; rep < 2; rep++) {
        int idx = tid + rep * 256;
        int gg = idx >> 7, j = idx & 127;
        float s = 0.f;
#pragma unroll
        for (int w = 0; w < 8; w++) s += sP[(w * 4 + gg) * 128 + j];
        s += bd1[j];
        s = (s > 0.f) ? s : 0.01f * s;
        acc[0].x = s;
        __syncthreads();
        sH[gg * 128 + j] = acc[0].x;
        __syncthreads();
    }

    if (kw < 4) {
        float a0 = 0.f, a1 = 0.f;
#pragma unroll
        for (int c = 0; c < 4; c++) {
            int k = lane + c * 32;
            float h = sH[kw * 128 + k];
            a0 += h * Wd2[k * 2 + 0];
            a1 += h * Wd2[k * 2 + 1];
        }
#pragma unroll
        for (int s = 16; s > 0; s >>= 1) {
            a0 += __shfl_down_sync(0xffffffffu, a0, s);
            a1 += __shfl_down_sync(0xffffffffu, a1, s);
        }
        if (lane == 0) {
            out[(g0 + kw) * 2 + 0] = 1.f / (1.f + expf(-(a0 + bd2[0])));
            out[(g0 + kw) * 2 + 1] = 1.f / (1.f + expf(-(a1 + bd2[1])));
        }
    }
}

// --------------------------------- launch --------------------------------------
extern "C" void kernel_launch(void* const* d_in, const int* in_sizes, int n_in,
                              void* d_out, int out_size)
{
    const float* feat = (const float*)d_in[0];
    const float* adj  = (const float*)d_in[1];
    const float* W0   = (const float*)d_in[2];
    const float* b0   = (const float*)d_in[3];
    const float* Ws0  = (const float*)d_in[4];
    const float* bs0  = (const float*)d_in[5];
    const float* W1   = (const float*)d_in[6];
    const float* b1   = (const float*)d_in[7];
    const float* Ws1  = (const float*)d_in[8];
    const float* bs1  = (const float*)d_in[9];
    const float* W2   = (const float*)d_in[10];
    const float* b2   = (const float*)d_in[11];
    const float* Ws2  = (const float*)d_in[12];
    const float* bs2  = (const float*)d_in[13];
    const float* Wd1  = (const float*)d_in[14];
    const float* bd1  = (const float*)d_in[15];
    const float* Wd2  = (const float*)d_in[16];
    const float* bd2  = (const float*)d_in[17];
    float* out = (float*)d_out;

    float *p_norm0, *p_X1, *p_spre, *p_Xp1, *p_A1, *p_norm1, *p_H1, *p_X2;
    float *p_Xp2, *p_A2, *p_norm2, *p_H2, *p_X3, *p_Xp3, *p_read;
    unsigned char* p_cols; int* p_cnt;
    __nv_bfloat16 *p_Yh, *p_Yl, *p_W0h, *p_W0l;
    cudaGetSymbolAddress((void**)&p_norm0, g_norm0);
    cudaGetSymbolAddress((void**)&p_cols, g_cols);
    cudaGetSymbolAddress((void**)&p_cnt, g_cnt);
    cudaGetSymbolAddress((void**)&p_Yh, g_Yh);
    cudaGetSymbolAddress((void**)&p_Yl, g_Yl);
    cudaGetSymbolAddress((void**)&p_W0h, g_W0h);
    cudaGetSymbolAddress((void**)&p_W0l, g_W0l);
    cudaGetSymbolAddress((void**)&p_X1, g_X1);
    cudaGetSymbolAddress((void**)&p_spre, g_spre);
    cudaGetSymbolAddress((void**)&p_Xp1, g_Xp1);
    cudaGetSymbolAddress((void**)&p_A1, g_A1);
    cudaGetSymbolAddress((void**)&p_norm1, g_norm1);
    cudaGetSymbolAddress((void**)&p_H1, g_H1);
    cudaGetSymbolAddress((void**)&p_X2, g_X2);
    cudaGetSymbolAddress((void**)&p_Xp2, g_Xp2);
    cudaGetSymbolAddress((void**)&p_A2, g_A2);
    cudaGetSymbolAddress((void**)&p_norm2, g_norm2);
    cudaGetSymbolAddress((void**)&p_H2, g_H2);
    cudaGetSymbolAddress((void**)&p_X3, g_X3);
    cudaGetSymbolAddress((void**)&p_Xp3, g_Xp3);
    cudaGetSymbolAddress((void**)&p_read, g_read);

    const int headSmem = (4 * 1536 + 8 * 4 * 128) * 4;
    const int wmmaSmem = 2 * STG_B;   // 92160 B: double-buffered operands (C fits inside)
    cudaFuncSetAttribute(spmm_feat_kernel, cudaFuncAttributeMaxDynamicSharedMemorySize, 131072);
    cudaFuncSetAttribute(mlp_head_kernel, cudaFuncAttributeMaxDynamicSharedMemorySize, headSmem);
    cudaFuncSetAttribute(wmma_feat_kernel, cudaFuncAttributeMaxDynamicSharedMemorySize, wmmaSmem);

    // ---- layer 0
    build_adj_kernel<<<G * NNODE / 8, 256>>>(adj, p_cols, p_cnt, p_norm0);
    split_w_kernel<<<(FIN * DH + 255) / 256, 256>>>(W0, p_W0h, p_W0l, FIN * DH);
    spmm_feat_kernel<<<G, 256, 131072>>>(p_cols, p_cnt, feat, p_norm0, p_Yh, p_Yl);
    wmma_feat_kernel<<<dim3(2, 2048, 1), 256, wmmaSmem>>>(p_Yh, p_Yl, p_W0h, p_W0l,
                                                          b0, Ws0, p_X1, p_spre);
    pool_kernel<256, 32><<<G, 256>>>(p_X1, adj, p_norm0, Ws0, bs0, p_cols, p_cnt,
                                     p_spre, p_Xp1, p_A1, p_norm1, p_read, 0);
    // ---- layer 1
    sgemm_kernel<<<dim3(2, 256, 1), 256>>>(p_Xp1, W1, p_H1, G * 32, DH, DH,
                                           0, 0, 0, p_norm1, 0, nullptr, 0, nullptr, 0);
    conv_small_kernel<32><<<G, 256>>>(p_A1, p_H1, p_norm1, b1, p_X2);
    pool_kernel<32, 16><<<G, 256>>>(p_X2, p_A1, p_norm1, Ws1, bs1, nullptr, nullptr,
                                    nullptr, p_Xp2, p_A2, p_norm2, p_read, 512);
    // ---- layer 2
    sgemm_kernel<<<dim3(2, 128, 1), 256>>>(p_Xp2, W2, p_H2, G * 16, DH, DH,
                                           0, 0, 0, p_norm2, 0, nullptr, 0, nullptr, 0);
    conv_small_kernel<16><<<G, 256>>>(p_A2, p_H2, p_norm2, b2, p_X3);
    pool_kernel<16, 8><<<G, 256>>>(p_X3, p_A2, p_norm2, Ws2, bs2, nullptr, nullptr,
                                   nullptr, p_Xp3, nullptr, nullptr, p_read, 1024);
    // ---- fused MLP head
    mlp_head_kernel<<<G / 4, 256, headSmem>>>(p_read, Wd1, bd1, Wd2, bd2, out);
}

// round 12
// speedup vs baseline: 1.5118x; 1.0715x over previous
#include <cuda_runtime.h>
#include <cuda_bf16.h>
#include <mma.h>
#include <math.h>

using namespace nvcuda;

#define G 1024
#define NNODE 256
#define FIN 128
#define DH 256
#define MAXD 128

// ---------------- scratch (device globals; no allocations allowed) -------------
__device__ float g_norm0[G * NNODE];
__device__ unsigned char g_cols[(long)G * NNODE * MAXD];
__device__ int   g_cnt [G * NNODE];
__device__ __nv_bfloat16 g_Yh[(long)G * NNODE * FIN];
__device__ __nv_bfloat16 g_Yl[(long)G * NNODE * FIN];
__device__ __nv_bfloat16 g_W0h[FIN * DH];
__device__ __nv_bfloat16 g_W0l[FIN * DH];
__device__ __nv_bfloat16 g_W1h[DH * DH];
__device__ __nv_bfloat16 g_W1l[DH * DH];
__device__ __nv_bfloat16 g_W2h[DH * DH];
__device__ __nv_bfloat16 g_W2l[DH * DH];
__device__ float g_X1 [G * NNODE * DH];
__device__ float g_spre[2 * G * NNODE];
__device__ __nv_bfloat16 g_Xp1h[(long)G * 32 * DH];
__device__ __nv_bfloat16 g_Xp1l[(long)G * 32 * DH];
__device__ float g_A1 [G * 32 * 32];
__device__ float g_norm1[G * 32];
__device__ float g_H1 [G * 32 * DH];
__device__ float g_X2 [G * 32 * DH];
__device__ __nv_bfloat16 g_Xp2h[(long)G * 16 * DH];
__device__ __nv_bfloat16 g_Xp2l[(long)G * 16 * DH];
__device__ float g_A2 [G * 16 * 16];
__device__ float g_norm2[G * 16];
__device__ float g_H2 [G * 16 * DH];
__device__ float g_X3 [G * 16 * DH];
__device__ float g_read[G * 1536];

// ---------------- cp.async helpers ---------------------------------------------
__device__ __forceinline__ void cp_async16(unsigned saddr, const void* gptr) {
    asm volatile("cp.async.cg.shared.global [%0], [%1], 16;" :: "r"(saddr), "l"(gptr));
}

// ---------------- build sparse adjacency lists + degree norm -------------------
__global__ void build_adj_kernel(const float* __restrict__ adj,
                                 unsigned char* __restrict__ cols,
                                 int* __restrict__ cnt, float* __restrict__ nrm)
{
    int row  = blockIdx.x * 8 + (threadIdx.x >> 5);
    int lane = threadIdx.x & 31;
    const float* a = adj + (long)row * 256;
    unsigned char* lst = cols + (long)row * MAXD;
    int base = 0;
#pragma unroll
    for (int c = 0; c < 8; c++) {
        float v = a[c * 32 + lane];
        unsigned m = __ballot_sync(0xffffffffu, v != 0.f);
        if (v != 0.f) {
            int pos = base + __popc(m & ((1u << lane) - 1));
            if (pos < MAXD) lst[pos] = (unsigned char)(c * 32 + lane);
        }
        base += __popc(m);
    }
    if (lane == 0) {
        cnt[row] = (base > MAXD) ? MAXD : base;
        nrm[row] = rsqrtf(fmaxf((float)base, 1.f));
    }
}

// ---------------- split fp32 weight into bf16 hi/lo ----------------------------
__global__ void split_w_kernel(const float* __restrict__ W,
                               __nv_bfloat16* __restrict__ Wh,
                               __nv_bfloat16* __restrict__ Wl, int n)
{
    int i = blockIdx.x * 256 + threadIdx.x;
    if (i < n) {
        float v = W[i];
        __nv_bfloat16 h = __float2bfloat16_rn(v);
        Wh[i] = h;
        Wl[i] = __float2bfloat16_rn(v - __bfloat162float(h));
    }
}

// ------- layer-0 sparse aggregation in INPUT space; emits bf16 hi/lo -----------
__global__ void spmm_feat_kernel(const unsigned char* __restrict__ cols,
                                 const int* __restrict__ cnt,
                                 const float* __restrict__ feat,
                                 const float* __restrict__ nrm,
                                 __nv_bfloat16* __restrict__ Yh,
                                 __nv_bfloat16* __restrict__ Yl)
{
    extern __shared__ float sX[];                 // [256][128] = 128 KB
    __shared__ unsigned char sCols[256 * MAXD];   // 32 KB
    __shared__ int   scnt[256];
    __shared__ float snrm[256];

    int g = blockIdx.x, tid = threadIdx.x;
    scnt[tid] = cnt[g * 256 + tid];
    snrm[tid] = nrm[g * 256 + tid];
    __syncthreads();

    {
        const float4* Xg = (const float4*)(feat + (long)g * 32768);
        float4* s4 = (float4*)sX;
        for (int t = tid; t < 8192; t += 256) {
            int r = t >> 5;
            float4 v = Xg[t];
            float s = snrm[r];
            v.x *= s; v.y *= s; v.z *= s; v.w *= s;
            s4[t] = v;
        }
        const uint4* gc = (const uint4*)(cols + (long)g * 256 * MAXD);
        uint4* sc = (uint4*)sCols;
        for (int t = tid; t < 2048; t += 256) sc[t] = gc[t];
    }
    __syncthreads();

    int col4 = tid & 31;
    int rg   = tid >> 5;
    for (int i = rg; i < 256; i += 8) {
        int d = scnt[i];
        const unsigned char* lst = &sCols[i * MAXD];
        float a0 = 0.f, a1 = 0.f, a2 = 0.f, a3 = 0.f;
        int k = 0;
        for (; k + 4 <= d; k += 4) {
            unsigned w = *(const unsigned*)(lst + k);
            int j0 = w & 255, j1 = (w >> 8) & 255, j2 = (w >> 16) & 255, j3 = w >> 24;
            float4 h0 = *(const float4*)(sX + j0 * 128 + col4 * 4);
            float4 h1 = *(const float4*)(sX + j1 * 128 + col4 * 4);
            float4 h2 = *(const float4*)(sX + j2 * 128 + col4 * 4);
            float4 h3 = *(const float4*)(sX + j3 * 128 + col4 * 4);
            a0 += h0.x + h1.x + h2.x + h3.x;
            a1 += h0.y + h1.y + h2.y + h3.y;
            a2 += h0.z + h1.z + h2.z + h3.z;
            a3 += h0.w + h1.w + h2.w + h3.w;
        }
        for (; k < d; k++) {
            int j = lst[k];
            float4 h = *(const float4*)(sX + j * 128 + col4 * 4);
            a0 += h.x; a1 += h.y; a2 += h.z; a3 += h.w;
        }
        float nr = snrm[i];
        float o0 = a0 * nr, o1 = a1 * nr, o2 = a2 * nr, o3 = a3 * nr;
        __nv_bfloat16 h0 = __float2bfloat16_rn(o0);
        __nv_bfloat16 h1 = __float2bfloat16_rn(o1);
        __nv_bfloat16 h2 = __float2bfloat16_rn(o2);
        __nv_bfloat16 h3 = __float2bfloat16_rn(o3);
        long base = (long)g * 32768 + (long)i * 128 + col4 * 4;
        *(__nv_bfloat162*)(Yh + base)     = __nv_bfloat162(h0, h1);
        *(__nv_bfloat162*)(Yh + base + 2) = __nv_bfloat162(h2, h3);
        *(__nv_bfloat162*)(Yl + base) = __nv_bfloat162(
            __float2bfloat16_rn(o0 - __bfloat162float(h0)),
            __float2bfloat16_rn(o1 - __bfloat162float(h1)));
        *(__nv_bfloat162*)(Yl + base + 2) = __nv_bfloat162(
            __float2bfloat16_rn(o2 - __bfloat162float(h2)),
            __float2bfloat16_rn(o3 - __bfloat162float(h3)));
    }
}

// ===== generalized bf16 wmma 3-chain GEMM, cp.async double-buffered ============
// C[M,256] = A[M,K] @ B[K,256] with A=Ah+Al, B=Bh+Bl (3 chains).
// EPI=1: += bias, leaky, fused Wsp row-dot into spreOut. EPI=0: plain store.
#define WAL 56
#define WBL 136
#define WCL 132
#define STG_B 46080
#define STG_E 23040

template <int EPI>
__global__ void __launch_bounds__(256, 2) wmma_gen_kernel(
    const __nv_bfloat16* __restrict__ Ah, const __nv_bfloat16* __restrict__ Al,
    const __nv_bfloat16* __restrict__ Bh, const __nv_bfloat16* __restrict__ Bl,
    const float* __restrict__ bias, const float* __restrict__ Wsp,
    float* __restrict__ C, float* __restrict__ spreOut, int M, int K)
{
    extern __shared__ char smem[];
    __nv_bfloat16* sb = (__nv_bfloat16*)smem;
    float* sC = (float*)smem;
    unsigned sb32 = (unsigned)__cvta_generic_to_shared(smem);

    int tid = threadIdx.x, warp = tid >> 5;
    int bm = blockIdx.y * 128, bn = blockIdx.x * 128;
    int wm = warp >> 2, wn = warp & 3;

    wmma::fragment<wmma::accumulator, 16, 16, 16, float> acc[4][2];
#pragma unroll
    for (int i = 0; i < 4; i++)
#pragma unroll
        for (int j = 0; j < 2; j++) wmma::fill_fragment(acc[i][j], 0.f);

    auto issue_tile = [&](int k0, int buf) {
        unsigned base = sb32 + buf * STG_B;
#pragma unroll
        for (int it = 0; it < 2; it++) {
            int idx = tid + it * 256;
            int r = idx >> 2, c8 = (idx & 3) * 8;
            long gofs = (long)(bm + r) * K + k0 + c8;
            unsigned aoff = (unsigned)(r * WAL + c8) * 2;
            cp_async16(base + aoff, Ah + gofs);
            cp_async16(base + 14336 + aoff, Al + gofs);
        }
#pragma unroll
        for (int it = 0; it < 2; it++) {
            int idx = tid + it * 256;
            int r = idx >> 4, c8 = (idx & 15) * 8;
            long gofs = (long)(k0 + r) * 256 + bn + c8;
            unsigned boff = (unsigned)(r * WBL + c8) * 2;
            cp_async16(base + 28672 + boff, Bh + gofs);
            cp_async16(base + 37376 + boff, Bl + gofs);
        }
        asm volatile("cp.async.commit_group;" ::: "memory");
    };

    int NT = K >> 5;
    issue_tile(0, 0);

    for (int k = 0; k < NT; k++) {
        if (k < NT - 1) {
            issue_tile((k + 1) * 32, (k + 1) & 1);
            asm volatile("cp.async.wait_group 1;" ::: "memory");
        } else {
            asm volatile("cp.async.wait_group 0;" ::: "memory");
        }
        __syncthreads();

        __nv_bfloat16* sAh = sb + (k & 1) * STG_E;
        __nv_bfloat16* sAl = sAh + 7168;
        __nv_bfloat16* sBh = sAh + 14336;
        __nv_bfloat16* sBl = sAh + 18688;

#pragma unroll
        for (int kk = 0; kk < 32; kk += 16) {
            wmma::fragment<wmma::matrix_b, 16, 16, 16, __nv_bfloat16, wmma::row_major> bh[2], bl[2];
#pragma unroll
            for (int j = 0; j < 2; j++) {
                wmma::load_matrix_sync(bh[j], sBh + kk * WBL + wn * 32 + j * 16, WBL);
                wmma::load_matrix_sync(bl[j], sBl + kk * WBL + wn * 32 + j * 16, WBL);
            }
#pragma unroll
            for (int i = 0; i < 4; i++) {
                wmma::fragment<wmma::matrix_a, 16, 16, 16, __nv_bfloat16, wmma::row_major> ah, al;
                wmma::load_matrix_sync(ah, sAh + (wm * 64 + i * 16) * WAL + kk, WAL);
                wmma::load_matrix_sync(al, sAl + (wm * 64 + i * 16) * WAL + kk, WAL);
#pragma unroll
                for (int j = 0; j < 2; j++) {
                    wmma::mma_sync(acc[i][j], ah, bh[j], acc[i][j]);
                    wmma::mma_sync(acc[i][j], ah, bl[j], acc[i][j]);
                    wmma::mma_sync(acc[i][j], al, bh[j], acc[i][j]);
                }
            }
        }
        __syncthreads();
    }

    // stage C through smem — padded stride WCL
#pragma unroll
    for (int i = 0; i < 4; i++)
#pragma unroll
        for (int j = 0; j < 2; j++)
            wmma::store_matrix_sync(sC + (wm * 64 + i * 16) * WCL + wn * 32 + j * 16,
                                    acc[i][j], WCL, wmma::mem_row_major);
    __syncthreads();

    {
        int row = tid >> 1, half = tid & 1;
        int gRow = bm + row;
        float rd = 0.f;
        float* dst = C + (long)gRow * 256 + bn + half * 64;
#pragma unroll
        for (int c4 = 0; c4 < 16; c4++) {
            int col = half * 64 + c4 * 4;
            float4 v = *(float4*)(sC + row * WCL + col);
            if (EPI) {
                float4 bv = *(const float4*)(bias + bn + col);
                v.x += bv.x; v.y += bv.y; v.z += bv.z; v.w += bv.w;
                v.x = (v.x > 0.f) ? v.x : 0.01f * v.x;
                v.y = (v.y > 0.f) ? v.y : 0.01f * v.y;
                v.z = (v.z > 0.f) ? v.z : 0.01f * v.z;
                v.w = (v.w > 0.f) ? v.w : 0.01f * v.w;
                float4 wv = *(const float4*)(Wsp + bn + col);
                rd += v.x * wv.x + v.y * wv.y + v.z * wv.z + v.w * wv.w;
            }
            *(float4*)(dst + c4 * 4) = v;
        }
        if (EPI) {
            rd += __shfl_xor_sync(0xffffffffu, rd, 1);
            if (half == 0) spreOut[(long)blockIdx.x * M + gRow] = rd;
        }
    }
}

// ---------------- small batched conv: X = leaky(adj@H * norm + b) ---------------
template <int NN>
__global__ void conv_small_kernel(const float* __restrict__ A, const float* __restrict__ H,
                                  const float* __restrict__ nrm, const float* __restrict__ bias,
                                  float* __restrict__ X)
{
    int g = blockIdx.x;
    __shared__ float sAdj[NN][NN + 1];
    __shared__ float sH[NN][256];
    const float* Ag = A + (long)g * NN * NN;
    const float* Hg = H + (long)g * NN * 256;
    int tid = threadIdx.x;
    for (int t = tid; t < NN * NN; t += 256) sAdj[t / NN][t % NN] = Ag[t];
    for (int t = tid; t < NN * 256; t += 256) sH[t / 256][t % 256] = Hg[t];
    __syncthreads();
    int j = tid;
    float bj = bias[j];
#pragma unroll 4
    for (int i = 0; i < NN; i++) {
        float acc = 0.f;
#pragma unroll
        for (int k = 0; k < NN; k++) acc += sAdj[i][k] * sH[k][j];
        float v = acc * nrm[(long)g * NN + i] + bj;
        X[(long)g * NN * 256 + (long)i * 256 + j] = (v > 0.f) ? v : 0.01f * v;
    }
}

// ---------------- SAGPool: emits Xp as bf16 hi/lo with next norm folded --------
template <int NV, int KK>
__global__ void pool_kernel(const float* __restrict__ X, const float* __restrict__ A,
                            const float* __restrict__ nrm,
                            const float* __restrict__ Ws, const float* __restrict__ bs,
                            const unsigned char* __restrict__ colsL,
                            const int* __restrict__ cntL,
                            const float* __restrict__ spreParts,
                            __nv_bfloat16* __restrict__ Xph,
                            __nv_bfloat16* __restrict__ Xpl,
                            float* __restrict__ Aout,
                            float* __restrict__ normOut, float* __restrict__ readout,
                            int roff)
{
    int g = blockIdx.x;
    const float* Xg = X + (long)g * NV * 256;
    const float* Ag = A + (long)g * NV * NV;
    const float* ng = nrm + (long)g * NV;

    __shared__ float sWs[256];
    __shared__ float spre[NV];
    __shared__ float ssc[NV];
    __shared__ int   sidx[NV];
    __shared__ float sAn[KK * KK];
    __shared__ float snrm2[KK];

    int tid = threadIdx.x, lane = tid & 31, warp = tid >> 5;

    if (spreParts) {
        if (tid < NV)
            spre[tid] = (spreParts[(long)g * NV + tid] +
                         spreParts[(long)G * NNODE + (long)g * NV + tid]) * ng[tid];
        __syncthreads();
    } else {
        sWs[tid] = Ws[tid];
        __syncthreads();
        for (int r = warp; r < NV; r += 8) {
            float acc = 0.f;
            for (int q = lane; q < 256; q += 32) acc += Xg[(long)r * 256 + q] * sWs[q];
#pragma unroll
            for (int s = 16; s > 0; s >>= 1) acc += __shfl_down_sync(0xffffffffu, acc, s);
            if (lane == 0) spre[r] = ng[r] * acc;
        }
        __syncthreads();
    }

    float bsv = bs[0];
    if (colsL) {
        for (int r = warp; r < NV; r += 8) {
            int d = cntL[g * NV + r];
            const unsigned char* lst = colsL + ((long)g * NV + r) * MAXD;
            float acc = 0.f;
            for (int q = lane; q < d; q += 32) acc += spre[lst[q]];
#pragma unroll
            for (int s = 16; s > 0; s >>= 1) acc += __shfl_down_sync(0xffffffffu, acc, s);
            if (lane == 0) { ssc[r] = ng[r] * acc + bsv; sidx[r] = r; }
        }
    } else {
        for (int r = warp; r < NV; r += 8) {
            float acc = 0.f;
            for (int q = lane; q < NV; q += 32) acc += Ag[(long)r * NV + q] * spre[q];
#pragma unroll
            for (int s = 16; s > 0; s >>= 1) acc += __shfl_down_sync(0xffffffffu, acc, s);
            if (lane == 0) { ssc[r] = ng[r] * acc + bsv; sidx[r] = r; }
        }
    }
    __syncthreads();

    for (int ksz = 2; ksz <= NV; ksz <<= 1) {
        for (int j = ksz >> 1; j > 0; j >>= 1) {
            if (tid < NV) {
                int ixj = tid ^ j;
                if (ixj > tid) {
                    float s1 = ssc[tid], s2 = ssc[ixj];
                    int i1 = sidx[tid], i2 = sidx[ixj];
                    bool firstWorse = (s1 < s2) || (s1 == s2 && i1 > i2);
                    bool descRegion = ((tid & ksz) == 0);
                    bool doSwap = descRegion ? firstWorse : !firstWorse;
                    if (doSwap) {
                        ssc[tid] = s2; ssc[ixj] = s1;
                        sidx[tid] = i2; sidx[ixj] = i1;
                    }
                }
            }
            __syncthreads();
        }
    }

    // induced sub-adjacency + next-layer norm FIRST (needs only sidx)
    if (Aout) {
        for (int t = tid; t < KK * KK; t += 256) {
            int r = t / KK, c = t % KK;
            sAn[t] = Ag[(long)sidx[r] * NV + sidx[c]];
        }
        __syncthreads();
        for (int t = tid; t < KK * KK; t += 256) Aout[(long)g * KK * KK + t] = sAn[t];
        if (tid < KK) {
            float d = 0.f;
#pragma unroll
            for (int c = 0; c < KK; c++) d += sAn[tid * KK + c];
            float nv = rsqrtf(fmaxf(d, 1.f));
            normOut[(long)g * KK + tid] = nv;
            snrm2[tid] = nv;
        }
    }
    __syncthreads();

    if (tid < KK) ssc[tid] = tanhf(ssc[tid]);
    __syncthreads();

    // gather + gate + readout; emit bf16 hi/lo with next norm folded
    {
        int j = tid;
        float csum = 0.f, cmax = -3.402823466e38f;
#pragma unroll 4
        for (int r = 0; r < KK; r++) {
            int row = sidx[r];
            float v = Xg[(long)row * 256 + j] * ssc[r];
            csum += v;
            cmax = fmaxf(cmax, v);
            if (Xph) {
                float vs = v * snrm2[r];
                __nv_bfloat16 h = __float2bfloat16_rn(vs);
                long o = (long)g * KK * 256 + (long)r * 256 + j;
                Xph[o] = h;
                Xpl[o] = __float2bfloat16_rn(vs - __bfloat162float(h));
            }
        }
        readout[(long)g * 1536 + roff + j] = csum;
        readout[(long)g * 1536 + roff + 256 + j] = cmax;
    }
}

// ====== fused MLP head (round-7 proven) ========================================
__global__ void __launch_bounds__(256) mlp_head_kernel(
    const float* __restrict__ read, const float* __restrict__ Wd1,
    const float* __restrict__ bd1, const float* __restrict__ Wd2,
    const float* __restrict__ bd2, float* __restrict__ out)
{
    extern __shared__ float sm[];
    float* sR = sm;
    float* sP = sm + 4 * 1536;
    float* sH = sP;

    int tid = threadIdx.x;
    int g0 = blockIdx.x * 4;
    int lane = tid & 31, kw = tid >> 5;

    {
        const float4* src = (const float4*)(read + (long)g0 * 1536);
        float4* d4 = (float4*)sR;
#pragma unroll
        for (int i = 0; i < 6; i++) d4[tid + i * 256] = src[tid + i * 256];
    }
    __syncthreads();

    float4 acc[4];
#pragma unroll
    for (int gg = 0; gg < 4; gg++) acc[gg] = make_float4(0.f, 0.f, 0.f, 0.f);
    {
        const float4* W14 = (const float4*)Wd1;
        int kbeg = kw * 192;
#pragma unroll 2
        for (int k = kbeg; k < kbeg + 192; k++) {
            float4 wd = __ldg(&W14[k * 32 + lane]);
#pragma unroll
            for (int gg = 0; gg < 4; gg++) {
                float rv = sR[gg * 1536 + k];
                acc[gg].x += rv * wd.x;
                acc[gg].y += rv * wd.y;
                acc[gg].z += rv * wd.z;
                acc[gg].w += rv * wd.w;
            }
        }
    }
#pragma unroll
    for (int gg = 0; gg < 4; gg++)
        ((float4*)sP)[(kw * 4 + gg) * 32 + lane] = acc[gg];
    __syncthreads();

#pragma unroll
    for (int rep = 0; rep < 2; rep++) {
        int idx = tid + rep * 256;
        int gg = idx >> 7, j = idx & 127;
        float s = 0.f;
#pragma unroll
        for (int w = 0; w < 8; w++) s += sP[(w * 4 + gg) * 128 + j];
        s += bd1[j];
        s = (s > 0.f) ? s : 0.01f * s;
        acc[0].x = s;
        __syncthreads();
        sH[gg * 128 + j] = acc[0].x;
        __syncthreads();
    }

    if (kw < 4) {
        float a0 = 0.f, a1 = 0.f;
#pragma unroll
        for (int c = 0; c < 4; c++) {
            int k = lane + c * 32;
            float h = sH[kw * 128 + k];
            a0 += h * Wd2[k * 2 + 0];
            a1 += h * Wd2[k * 2 + 1];
        }
#pragma unroll
        for (int s = 16; s > 0; s >>= 1) {
            a0 += __shfl_down_sync(0xffffffffu, a0, s);
            a1 += __shfl_down_sync(0xffffffffu, a1, s);
        }
        if (lane == 0) {
            out[(g0 + kw) * 2 + 0] = 1.f / (1.f + expf(-(a0 + bd2[0])));
            out[(g0 + kw) * 2 + 1] = 1.f / (1.f + expf(-(a1 + bd2[1])));
        }
    }
}

// --------------------------------- launch --------------------------------------
extern "C" void kernel_launch(void* const* d_in, const int* in_sizes, int n_in,
                              void* d_out, int out_size)
{
    const float* feat = (const float*)d_in[0];
    const float* adj  = (const float*)d_in[1];
    const float* W0   = (const float*)d_in[2];
    const float* b0   = (const float*)d_in[3];
    const float* Ws0  = (const float*)d_in[4];
    const float* bs0  = (const float*)d_in[5];
    const float* W1   = (const float*)d_in[6];
    const float* b1   = (const float*)d_in[7];
    const float* Ws1  = (const float*)d_in[8];
    const float* bs1  = (const float*)d_in[9];
    const float* W2   = (const float*)d_in[10];
    const float* b2   = (const float*)d_in[11];
    const float* Ws2  = (const float*)d_in[12];
    const float* bs2  = (const float*)d_in[13];
    const float* Wd1  = (const float*)d_in[14];
    const float* bd1  = (const float*)d_in[15];
    const float* Wd2  = (const float*)d_in[16];
    const float* bd2  = (const float*)d_in[17];
    float* out = (float*)d_out;

    float *p_norm0, *p_X1, *p_spre, *p_A1, *p_norm1, *p_H1, *p_X2;
    float *p_A2, *p_norm2, *p_H2, *p_X3, *p_read;
    unsigned char* p_cols; int* p_cnt;
    __nv_bfloat16 *p_Yh, *p_Yl, *p_W0h, *p_W0l, *p_W1h, *p_W1l, *p_W2h, *p_W2l;
    __nv_bfloat16 *p_Xp1h, *p_Xp1l, *p_Xp2h, *p_Xp2l;
    cudaGetSymbolAddress((void**)&p_norm0, g_norm0);
    cudaGetSymbolAddress((void**)&p_cols, g_cols);
    cudaGetSymbolAddress((void**)&p_cnt, g_cnt);
    cudaGetSymbolAddress((void**)&p_Yh, g_Yh);
    cudaGetSymbolAddress((void**)&p_Yl, g_Yl);
    cudaGetSymbolAddress((void**)&p_W0h, g_W0h);
    cudaGetSymbolAddress((void**)&p_W0l, g_W0l);
    cudaGetSymbolAddress((void**)&p_W1h, g_W1h);
    cudaGetSymbolAddress((void**)&p_W1l, g_W1l);
    cudaGetSymbolAddress((void**)&p_W2h, g_W2h);
    cudaGetSymbolAddress((void**)&p_W2l, g_W2l);
    cudaGetSymbolAddress((void**)&p_X1, g_X1);
    cudaGetSymbolAddress((void**)&p_spre, g_spre);
    cudaGetSymbolAddress((void**)&p_Xp1h, g_Xp1h);
    cudaGetSymbolAddress((void**)&p_Xp1l, g_Xp1l);
    cudaGetSymbolAddress((void**)&p_A1, g_A1);
    cudaGetSymbolAddress((void**)&p_norm1, g_norm1);
    cudaGetSymbolAddress((void**)&p_H1, g_H1);
    cudaGetSymbolAddress((void**)&p_X2, g_X2);
    cudaGetSymbolAddress((void**)&p_Xp2h, g_Xp2h);
    cudaGetSymbolAddress((void**)&p_Xp2l, g_Xp2l);
    cudaGetSymbolAddress((void**)&p_A2, g_A2);
    cudaGetSymbolAddress((void**)&p_norm2, g_norm2);
    cudaGetSymbolAddress((void**)&p_H2, g_H2);
    cudaGetSymbolAddress((void**)&p_X3, g_X3);
    cudaGetSymbolAddress((void**)&p_read, g_read);

    const int headSmem = (4 * 1536 + 8 * 4 * 128) * 4;
    const int wmmaSmem = 2 * STG_B;   // 92160 B
    cudaFuncSetAttribute(spmm_feat_kernel, cudaFuncAttributeMaxDynamicSharedMemorySize, 131072);
    cudaFuncSetAttribute(mlp_head_kernel, cudaFuncAttributeMaxDynamicSharedMemorySize, headSmem);
    cudaFuncSetAttribute(wmma_gen_kernel<1>, cudaFuncAttributeMaxDynamicSharedMemorySize, wmmaSmem);
    cudaFuncSetAttribute(wmma_gen_kernel<0>, cudaFuncAttributeMaxDynamicSharedMemorySize, wmmaSmem);

    // ---- layer 0
    build_adj_kernel<<<G * NNODE / 8, 256>>>(adj, p_cols, p_cnt, p_norm0);
    split_w_kernel<<<(FIN * DH + 255) / 256, 256>>>(W0, p_W0h, p_W0l, FIN * DH);
    split_w_kernel<<<(DH * DH + 255) / 256, 256>>>(W1, p_W1h, p_W1l, DH * DH);
    split_w_kernel<<<(DH * DH + 255) / 256, 256>>>(W2, p_W2h, p_W2l, DH * DH);
    spmm_feat_kernel<<<G, 256, 131072>>>(p_cols, p_cnt, feat, p_norm0, p_Yh, p_Yl);
    wmma_gen_kernel<1><<<dim3(2, 2048, 1), 256, wmmaSmem>>>(
        p_Yh, p_Yl, p_W0h, p_W0l, b0, Ws0, p_X1, p_spre, G * NNODE, FIN);
    pool_kernel<256, 32><<<G, 256>>>(p_X1, adj, p_norm0, Ws0, bs0, p_cols, p_cnt,
                                     p_spre, p_Xp1h, p_Xp1l, p_A1, p_norm1, p_read, 0);
    // ---- layer 1: H1 = (norm1.*Xp1) @ W1  (norm folded into Xp1h/l)
    wmma_gen_kernel<0><<<dim3(2, 256, 1), 256, wmmaSmem>>>(
        p_Xp1h, p_Xp1l, p_W1h, p_W1l, nullptr, nullptr, p_H1, nullptr, G * 32, DH);
    conv_small_kernel<32><<<G, 256>>>(p_A1, p_H1, p_norm1, b1, p_X2);
    pool_kernel<32, 16><<<G, 256>>>(p_X2, p_A1, p_norm1, Ws1, bs1, nullptr, nullptr,
                                    nullptr, p_Xp2h, p_Xp2l, p_A2, p_norm2, p_read, 512);
    // ---- layer 2
    wmma_gen_kernel<0><<<dim3(2, 128, 1), 256, wmmaSmem>>>(
        p_Xp2h, p_Xp2l, p_W2h, p_W2l, nullptr, nullptr, p_H2, nullptr, G * 16, DH);
    conv_small_kernel<16><<<G, 256>>>(p_A2, p_H2, p_norm2, b2, p_X3);
    pool_kernel<16, 8><<<G, 256>>>(p_X3, p_A2, p_norm2, Ws2, bs2, nullptr, nullptr,
                                   nullptr, nullptr, nullptr, nullptr, nullptr, p_read, 1024);
    // ---- fused MLP head
    mlp_head_kernel<<<G / 4, 256, headSmem>>>(p_read, Wd1, bd1, Wd2, bd2, out);
}

// round 13
// speedup vs baseline: 1.5433x; 1.0208x over previous
#include <cuda_runtime.h>
#include <cuda_bf16.h>
#include <mma.h>
#include <math.h>

using namespace nvcuda;

#define G 1024
#define NNODE 256
#define FIN 128
#define DH 256
#define MAXD 128

// ---------------- scratch (device globals; no allocations allowed) -------------
__device__ float g_norm0[G * NNODE];
__device__ unsigned char g_cols[(long)G * NNODE * MAXD];
__device__ int   g_cnt [G * NNODE];
__device__ __nv_bfloat16 g_Yh[(long)G * NNODE * FIN];
__device__ __nv_bfloat16 g_Yl[(long)G * NNODE * FIN];
__device__ __nv_bfloat16 g_W0h[FIN * DH];
__device__ __nv_bfloat16 g_W0l[FIN * DH];
__device__ __nv_bfloat16 g_W1h[DH * DH];
__device__ __nv_bfloat16 g_W1l[DH * DH];
__device__ __nv_bfloat16 g_W2h[DH * DH];
__device__ __nv_bfloat16 g_W2l[DH * DH];
__device__ float g_X1 [G * NNODE * DH];
__device__ float g_spre[2 * G * NNODE];
__device__ __nv_bfloat16 g_Xp1h[(long)G * 32 * DH];
__device__ __nv_bfloat16 g_Xp1l[(long)G * 32 * DH];
__device__ float g_A1 [G * 32 * 32];
__device__ float g_norm1[G * 32];
__device__ float g_H1 [G * 32 * DH];
__device__ float g_X2 [G * 32 * DH];
__device__ __nv_bfloat16 g_Xp2h[(long)G * 16 * DH];
__device__ __nv_bfloat16 g_Xp2l[(long)G * 16 * DH];
__device__ float g_A2 [G * 16 * 16];
__device__ float g_norm2[G * 16];
__device__ float g_H2 [G * 16 * DH];
__device__ float g_X3 [G * 16 * DH];
__device__ float g_read[G * 1536];

// ---------------- cp.async helpers ---------------------------------------------
__device__ __forceinline__ void cp_async16(unsigned saddr, const void* gptr) {
    asm volatile("cp.async.cg.shared.global [%0], [%1], 16;" :: "r"(saddr), "l"(gptr));
}

// ---------------- build sparse adjacency lists + degree norm -------------------
__global__ void build_adj_kernel(const float* __restrict__ adj,
                                 unsigned char* __restrict__ cols,
                                 int* __restrict__ cnt, float* __restrict__ nrm)
{
    int row  = blockIdx.x * 8 + (threadIdx.x >> 5);
    int lane = threadIdx.x & 31;
    const float* a = adj + (long)row * 256;
    unsigned char* lst = cols + (long)row * MAXD;
    int base = 0;
#pragma unroll
    for (int c = 0; c < 8; c++) {
        float v = a[c * 32 + lane];
        unsigned m = __ballot_sync(0xffffffffu, v != 0.f);
        if (v != 0.f) {
            int pos = base + __popc(m & ((1u << lane) - 1));
            if (pos < MAXD) lst[pos] = (unsigned char)(c * 32 + lane);
        }
        base += __popc(m);
    }
    if (lane == 0) {
        cnt[row] = (base > MAXD) ? MAXD : base;
        nrm[row] = rsqrtf(fmaxf((float)base, 1.f));
    }
}

// ---------------- split fp32 weight into bf16 hi/lo ----------------------------
__global__ void split_w_kernel(const float* __restrict__ W,
                               __nv_bfloat16* __restrict__ Wh,
                               __nv_bfloat16* __restrict__ Wl, int n)
{
    int i = blockIdx.x * 256 + threadIdx.x;
    if (i < n) {
        float v = W[i];
        __nv_bfloat16 h = __float2bfloat16_rn(v);
        Wh[i] = h;
        Wl[i] = __float2bfloat16_rn(v - __bfloat162float(h));
    }
}

// ------- layer-0 sparse aggregation, 64-col halves (2 CTA/SM); bf16 hi/lo out --
__global__ void spmm_feat_kernel(const unsigned char* __restrict__ cols,
                                 const int* __restrict__ cnt,
                                 const float* __restrict__ feat,
                                 const float* __restrict__ nrm,
                                 __nv_bfloat16* __restrict__ Yh,
                                 __nv_bfloat16* __restrict__ Yl)
{
    extern __shared__ float sX[];                 // [256][64] = 64 KB
    __shared__ float snrm[256];
    __shared__ int   scnt[256];

    int g = blockIdx.y, half = blockIdx.x;
    int tid = threadIdx.x;
    snrm[tid] = nrm[g * 256 + tid];
    scnt[tid] = cnt[g * 256 + tid];
    __syncthreads();

    {
        const float4* F = (const float4*)(feat + (long)g * 32768 + half * 64);
        float4* s4 = (float4*)sX;
        for (int t = tid; t < 4096; t += 256) {
            int r = t >> 4, c4 = t & 15;
            float4 v = F[(long)r * 32 + c4];
            float s = snrm[r];
            v.x *= s; v.y *= s; v.z *= s; v.w *= s;
            s4[r * 16 + c4] = v;
        }
    }
    __syncthreads();

    int lane = tid & 31, warp = tid >> 5;
    for (int i = warp; i < 256; i += 8) {
        int d = scnt[i];
        const unsigned char* lst = cols + ((long)g * 256 + i) * MAXD;
        float a0 = 0.f, a1 = 0.f;
        int k = 0;
        for (; k + 4 <= d; k += 4) {
            unsigned w = *(const unsigned*)(lst + k);   // warp-uniform -> broadcast
            int j0 = w & 255, j1 = (w >> 8) & 255, j2 = (w >> 16) & 255, j3 = w >> 24;
            float2 h0 = *(const float2*)(sX + j0 * 64 + lane * 2);
            float2 h1 = *(const float2*)(sX + j1 * 64 + lane * 2);
            float2 h2 = *(const float2*)(sX + j2 * 64 + lane * 2);
            float2 h3 = *(const float2*)(sX + j3 * 64 + lane * 2);
            a0 += h0.x + h1.x + h2.x + h3.x;
            a1 += h0.y + h1.y + h2.y + h3.y;
        }
        for (; k < d; k++) {
            int j = lst[k];
            float2 h = *(const float2*)(sX + j * 64 + lane * 2);
            a0 += h.x; a1 += h.y;
        }
        float nr = snrm[i];
        float o0 = a0 * nr, o1 = a1 * nr;
        __nv_bfloat16 h0 = __float2bfloat16_rn(o0);
        __nv_bfloat16 h1 = __float2bfloat16_rn(o1);
        long base = (long)g * 32768 + (long)i * 128 + half * 64 + lane * 2;
        *(__nv_bfloat162*)(Yh + base) = __nv_bfloat162(h0, h1);
        *(__nv_bfloat162*)(Yl + base) = __nv_bfloat162(
            __float2bfloat16_rn(o0 - __bfloat162float(h0)),
            __float2bfloat16_rn(o1 - __bfloat162float(h1)));
    }
}

// ===== generalized bf16 wmma 3-chain GEMM, cp.async double-buffered ============
#define WAL 56
#define WBL 136
#define WCL 132
#define STG_B 46080
#define STG_E 23040

template <int EPI>
__global__ void __launch_bounds__(256, 2) wmma_gen_kernel(
    const __nv_bfloat16* __restrict__ Ah, const __nv_bfloat16* __restrict__ Al,
    const __nv_bfloat16* __restrict__ Bh, const __nv_bfloat16* __restrict__ Bl,
    const float* __restrict__ bias, const float* __restrict__ Wsp,
    float* __restrict__ C, float* __restrict__ spreOut, int M, int K)
{
    extern __shared__ char smem[];
    __nv_bfloat16* sb = (__nv_bfloat16*)smem;
    float* sC = (float*)smem;
    unsigned sb32 = (unsigned)__cvta_generic_to_shared(smem);

    int tid = threadIdx.x, warp = tid >> 5;
    int bm = blockIdx.y * 128, bn = blockIdx.x * 128;
    int wm = warp >> 2, wn = warp & 3;

    wmma::fragment<wmma::accumulator, 16, 16, 16, float> acc[4][2];
#pragma unroll
    for (int i = 0; i < 4; i++)
#pragma unroll
        for (int j = 0; j < 2; j++) wmma::fill_fragment(acc[i][j], 0.f);

    auto issue_tile = [&](int k0, int buf) {
        unsigned base = sb32 + buf * STG_B;
#pragma unroll
        for (int it = 0; it < 2; it++) {
            int idx = tid + it * 256;
            int r = idx >> 2, c8 = (idx & 3) * 8;
            long gofs = (long)(bm + r) * K + k0 + c8;
            unsigned aoff = (unsigned)(r * WAL + c8) * 2;
            cp_async16(base + aoff, Ah + gofs);
            cp_async16(base + 14336 + aoff, Al + gofs);
        }
#pragma unroll
        for (int it = 0; it < 2; it++) {
            int idx = tid + it * 256;
            int r = idx >> 4, c8 = (idx & 15) * 8;
            long gofs = (long)(k0 + r) * 256 + bn + c8;
            unsigned boff = (unsigned)(r * WBL + c8) * 2;
            cp_async16(base + 28672 + boff, Bh + gofs);
            cp_async16(base + 37376 + boff, Bl + gofs);
        }
        asm volatile("cp.async.commit_group;" ::: "memory");
    };

    int NT = K >> 5;
    issue_tile(0, 0);

    for (int k = 0; k < NT; k++) {
        if (k < NT - 1) {
            issue_tile((k + 1) * 32, (k + 1) & 1);
            asm volatile("cp.async.wait_group 1;" ::: "memory");
        } else {
            asm volatile("cp.async.wait_group 0;" ::: "memory");
        }
        __syncthreads();

        __nv_bfloat16* sAh = sb + (k & 1) * STG_E;
        __nv_bfloat16* sAl = sAh + 7168;
        __nv_bfloat16* sBh = sAh + 14336;
        __nv_bfloat16* sBl = sAh + 18688;

#pragma unroll
        for (int kk = 0; kk < 32; kk += 16) {
            wmma::fragment<wmma::matrix_b, 16, 16, 16, __nv_bfloat16, wmma::row_major> bh[2], bl[2];
#pragma unroll
            for (int j = 0; j < 2; j++) {
                wmma::load_matrix_sync(bh[j], sBh + kk * WBL + wn * 32 + j * 16, WBL);
                wmma::load_matrix_sync(bl[j], sBl + kk * WBL + wn * 32 + j * 16, WBL);
            }
#pragma unroll
            for (int i = 0; i < 4; i++) {
                wmma::fragment<wmma::matrix_a, 16, 16, 16, __nv_bfloat16, wmma::row_major> ah, al;
                wmma::load_matrix_sync(ah, sAh + (wm * 64 + i * 16) * WAL + kk, WAL);
                wmma::load_matrix_sync(al, sAl + (wm * 64 + i * 16) * WAL + kk, WAL);
#pragma unroll
                for (int j = 0; j < 2; j++) {
                    wmma::mma_sync(acc[i][j], ah, bh[j], acc[i][j]);
                    wmma::mma_sync(acc[i][j], ah, bl[j], acc[i][j]);
                    wmma::mma_sync(acc[i][j], al, bh[j], acc[i][j]);
                }
            }
        }
        __syncthreads();
    }

    // stage C through smem — padded stride WCL
#pragma unroll
    for (int i = 0; i < 4; i++)
#pragma unroll
        for (int j = 0; j < 2; j++)
            wmma::store_matrix_sync(sC + (wm * 64 + i * 16) * WCL + wn * 32 + j * 16,
                                    acc[i][j], WCL, wmma::mem_row_major);
    __syncthreads();

    {
        int row = tid >> 1, half = tid & 1;
        int gRow = bm + row;
        float rd = 0.f;
        float* dst = C + (long)gRow * 256 + bn + half * 64;
#pragma unroll
        for (int c4 = 0; c4 < 16; c4++) {
            int col = half * 64 + c4 * 4;
            float4 v = *(float4*)(sC + row * WCL + col);
            if (EPI) {
                float4 bv = *(const float4*)(bias + bn + col);
                v.x += bv.x; v.y += bv.y; v.z += bv.z; v.w += bv.w;
                v.x = (v.x > 0.f) ? v.x : 0.01f * v.x;
                v.y = (v.y > 0.f) ? v.y : 0.01f * v.y;
                v.z = (v.z > 0.f) ? v.z : 0.01f * v.z;
                v.w = (v.w > 0.f) ? v.w : 0.01f * v.w;
                float4 wv = *(const float4*)(Wsp + bn + col);
                rd += v.x * wv.x + v.y * wv.y + v.z * wv.z + v.w * wv.w;
            }
            *(float4*)(dst + c4 * 4) = v;
        }
        if (EPI) {
            rd += __shfl_xor_sync(0xffffffffu, rd, 1);
            if (half == 0) spreOut[(long)blockIdx.x * M + gRow] = rd;
        }
    }
}

// ---------------- small batched conv: X = leaky(adj@H * norm + b) ---------------
template <int NN>
__global__ void conv_small_kernel(const float* __restrict__ A, const float* __restrict__ H,
                                  const float* __restrict__ nrm, const float* __restrict__ bias,
                                  float* __restrict__ X)
{
    int g = blockIdx.x;
    __shared__ float sAdj[NN][NN + 1];
    __shared__ float sH[NN][256];
    const float* Ag = A + (long)g * NN * NN;
    int tid = threadIdx.x;
    for (int t = tid; t < NN * NN; t += 256) sAdj[t / NN][t % NN] = Ag[t];
    {
        const float4* Hg4 = (const float4*)(H + (long)g * NN * 256);
        float4* s4 = (float4*)sH;
        for (int t = tid; t < NN * 64; t += 256) s4[t] = Hg4[t];
    }
    __syncthreads();
    int j = tid;
    float bj = bias[j];
#pragma unroll 4
    for (int i = 0; i < NN; i++) {
        float acc = 0.f;
#pragma unroll
        for (int k = 0; k < NN; k++) acc += sAdj[i][k] * sH[k][j];
        float v = acc * nrm[(long)g * NN + i] + bj;
        X[(long)g * NN * 256 + (long)i * 256 + j] = (v > 0.f) ? v : 0.01f * v;
    }
}

// ---------------- SAGPool: emits Xp as bf16 hi/lo with next norm folded --------
template <int NV, int KK>
__global__ void pool_kernel(const float* __restrict__ X, const float* __restrict__ A,
                            const float* __restrict__ nrm,
                            const float* __restrict__ Ws, const float* __restrict__ bs,
                            const unsigned char* __restrict__ colsL,
                            const int* __restrict__ cntL,
                            const float* __restrict__ spreParts,
                            __nv_bfloat16* __restrict__ Xph,
                            __nv_bfloat16* __restrict__ Xpl,
                            float* __restrict__ Aout,
                            float* __restrict__ normOut, float* __restrict__ readout,
                            int roff)
{
    int g = blockIdx.x;
    const float* Xg = X + (long)g * NV * 256;
    const float* Ag = A + (long)g * NV * NV;
    const float* ng = nrm + (long)g * NV;

    __shared__ float sWs[256];
    __shared__ float spre[NV];
    __shared__ float ssc[NV];
    __shared__ int   sidx[NV];
    __shared__ float sAn[KK * KK];
    __shared__ float snrm2[KK];

    int tid = threadIdx.x, lane = tid & 31, warp = tid >> 5;

    if (spreParts) {
        if (tid < NV)
            spre[tid] = (spreParts[(long)g * NV + tid] +
                         spreParts[(long)G * NNODE + (long)g * NV + tid]) * ng[tid];
        __syncthreads();
    } else {
        sWs[tid] = Ws[tid];
        __syncthreads();
        for (int r = warp; r < NV; r += 8) {
            float acc = 0.f;
            for (int q = lane; q < 256; q += 32) acc += Xg[(long)r * 256 + q] * sWs[q];
#pragma unroll
            for (int s = 16; s > 0; s >>= 1) acc += __shfl_down_sync(0xffffffffu, acc, s);
            if (lane == 0) spre[r] = ng[r] * acc;
        }
        __syncthreads();
    }

    float bsv = bs[0];
    if (colsL) {
        for (int r = warp; r < NV; r += 8) {
            int d = cntL[g * NV + r];
            const unsigned char* lst = colsL + ((long)g * NV + r) * MAXD;
            float acc = 0.f;
            for (int q = lane; q < d; q += 32) acc += spre[lst[q]];
#pragma unroll
            for (int s = 16; s > 0; s >>= 1) acc += __shfl_down_sync(0xffffffffu, acc, s);
            if (lane == 0) { ssc[r] = ng[r] * acc + bsv; sidx[r] = r; }
        }
    } else {
        for (int r = warp; r < NV; r += 8) {
            float acc = 0.f;
            for (int q = lane; q < NV; q += 32) acc += Ag[(long)r * NV + q] * spre[q];
#pragma unroll
            for (int s = 16; s > 0; s >>= 1) acc += __shfl_down_sync(0xffffffffu, acc, s);
            if (lane == 0) { ssc[r] = ng[r] * acc + bsv; sidx[r] = r; }
        }
    }
    __syncthreads();

    for (int ksz = 2; ksz <= NV; ksz <<= 1) {
        for (int j = ksz >> 1; j > 0; j >>= 1) {
            if (tid < NV) {
                int ixj = tid ^ j;
                if (ixj > tid) {
                    float s1 = ssc[tid], s2 = ssc[ixj];
                    int i1 = sidx[tid], i2 = sidx[ixj];
                    bool firstWorse = (s1 < s2) || (s1 == s2 && i1 > i2);
                    bool descRegion = ((tid & ksz) == 0);
                    bool doSwap = descRegion ? firstWorse : !firstWorse;
                    if (doSwap) {
                        ssc[tid] = s2; ssc[ixj] = s1;
                        sidx[tid] = i2; sidx[ixj] = i1;
                    }
                }
            }
            __syncthreads();
        }
    }

    if (Aout) {
        for (int t = tid; t < KK * KK; t += 256) {
            int r = t / KK, c = t % KK;
            sAn[t] = Ag[(long)sidx[r] * NV + sidx[c]];
        }
        __syncthreads();
        for (int t = tid; t < KK * KK; t += 256) Aout[(long)g * KK * KK + t] = sAn[t];
        if (tid < KK) {
            float d = 0.f;
#pragma unroll
            for (int c = 0; c < KK; c++) d += sAn[tid * KK + c];
            float nv = rsqrtf(fmaxf(d, 1.f));
            normOut[(long)g * KK + tid] = nv;
            snrm2[tid] = nv;
        }
    }
    __syncthreads();

    if (tid < KK) ssc[tid] = tanhf(ssc[tid]);
    __syncthreads();

    {
        int j = tid;
        float csum = 0.f, cmax = -3.402823466e38f;
#pragma unroll 4
        for (int r = 0; r < KK; r++) {
            int row = sidx[r];
            float v = Xg[(long)row * 256 + j] * ssc[r];
            csum += v;
            cmax = fmaxf(cmax, v);
            if (Xph) {
                float vs = v * snrm2[r];
                __nv_bfloat16 h = __float2bfloat16_rn(vs);
                long o = (long)g * KK * 256 + (long)r * 256 + j;
                Xph[o] = h;
                Xpl[o] = __float2bfloat16_rn(vs - __bfloat162float(h));
            }
        }
        readout[(long)g * 1536 + roff + j] = csum;
        readout[(long)g * 1536 + roff + 256 + j] = cmax;
    }
}

// ====== fused MLP head (round-7 proven) ========================================
__global__ void __launch_bounds__(256) mlp_head_kernel(
    const float* __restrict__ read, const float* __restrict__ Wd1,
    const float* __restrict__ bd1, const float* __restrict__ Wd2,
    const float* __restrict__ bd2, float* __restrict__ out)
{
    extern __shared__ float sm[];
    float* sR = sm;
    float* sP = sm + 4 * 1536;
    float* sH = sP;

    int tid = threadIdx.x;
    int g0 = blockIdx.x * 4;
    int lane = tid & 31, kw = tid >> 5;

    {
        const float4* src = (const float4*)(read + (long)g0 * 1536);
        float4* d4 = (float4*)sR;
#pragma unroll
        for (int i = 0; i < 6; i++) d4[tid + i * 256] = src[tid + i * 256];
    }
    __syncthreads();

    float4 acc[4];
#pragma unroll
    for (int gg = 0; gg < 4; gg++) acc[gg] = make_float4(0.f, 0.f, 0.f, 0.f);
    {
        const float4* W14 = (const float4*)Wd1;
        int kbeg = kw * 192;
#pragma unroll 2
        for (int k = kbeg; k < kbeg + 192; k++) {
            float4 wd = __ldg(&W14[k * 32 + lane]);
#pragma unroll
            for (int gg = 0; gg < 4; gg++) {
                float rv = sR[gg * 1536 + k];
                acc[gg].x += rv * wd.x;
                acc[gg].y += rv * wd.y;
                acc[gg].z += rv * wd.z;
                acc[gg].w += rv * wd.w;
            }
        }
    }
#pragma unroll
    for (int gg = 0; gg < 4; gg++)
        ((float4*)sP)[(kw * 4 + gg) * 32 + lane] = acc[gg];
    __syncthreads();

#pragma unroll
    for (int rep = 0; rep < 2; rep++) {
        int idx = tid + rep * 256;
        int gg = idx >> 7, j = idx & 127;
        float s = 0.f;
#pragma unroll
        for (int w = 0; w < 8; w++) s += sP[(w * 4 + gg) * 128 + j];
        s += bd1[j];
        s = (s > 0.f) ? s : 0.01f * s;
        acc[0].x = s;
        __syncthreads();
        sH[gg * 128 + j] = acc[0].x;
        __syncthreads();
    }

    if (kw < 4) {
        float a0 = 0.f, a1 = 0.f;
#pragma unroll
        for (int c = 0; c < 4; c++) {
            int k = lane + c * 32;
            float h = sH[kw * 128 + k];
            a0 += h * Wd2[k * 2 + 0];
            a1 += h * Wd2[k * 2 + 1];
        }
#pragma unroll
        for (int s = 16; s > 0; s >>= 1) {
            a0 += __shfl_down_sync(0xffffffffu, a0, s);
            a1 += __shfl_down_sync(0xffffffffu, a1, s);
        }
        if (lane == 0) {
            out[(g0 + kw) * 2 + 0] = 1.f / (1.f + expf(-(a0 + bd2[0])));
            out[(g0 + kw) * 2 + 1] = 1.f / (1.f + expf(-(a1 + bd2[1])));
        }
    }
}

// --------------------------------- launch --------------------------------------
extern "C" void kernel_launch(void* const* d_in, const int* in_sizes, int n_in,
                              void* d_out, int out_size)
{
    const float* feat = (const float*)d_in[0];
    const float* adj  = (const float*)d_in[1];
    const float* W0   = (const float*)d_in[2];
    const float* b0   = (const float*)d_in[3];
    const float* Ws0  = (const float*)d_in[4];
    const float* bs0  = (const float*)d_in[5];
    const float* W1   = (const float*)d_in[6];
    const float* b1   = (const float*)d_in[7];
    const float* Ws1  = (const float*)d_in[8];
    const float* bs1  = (const float*)d_in[9];
    const float* W2   = (const float*)d_in[10];
    const float* b2   = (const float*)d_in[11];
    const float* Ws2  = (const float*)d_in[12];
    const float* bs2  = (const float*)d_in[13];
    const float* Wd1  = (const float*)d_in[14];
    const float* bd1  = (const float*)d_in[15];
    const float* Wd2  = (const float*)d_in[16];
    const float* bd2  = (const float*)d_in[17];
    float* out = (float*)d_out;

    float *p_norm0, *p_X1, *p_spre, *p_A1, *p_norm1, *p_H1, *p_X2;
    float *p_A2, *p_norm2, *p_H2, *p_X3, *p_read;
    unsigned char* p_cols; int* p_cnt;
    __nv_bfloat16 *p_Yh, *p_Yl, *p_W0h, *p_W0l, *p_W1h, *p_W1l, *p_W2h, *p_W2l;
    __nv_bfloat16 *p_Xp1h, *p_Xp1l, *p_Xp2h, *p_Xp2l;
    cudaGetSymbolAddress((void**)&p_norm0, g_norm0);
    cudaGetSymbolAddress((void**)&p_cols, g_cols);
    cudaGetSymbolAddress((void**)&p_cnt, g_cnt);
    cudaGetSymbolAddress((void**)&p_Yh, g_Yh);
    cudaGetSymbolAddress((void**)&p_Yl, g_Yl);
    cudaGetSymbolAddress((void**)&p_W0h, g_W0h);
    cudaGetSymbolAddress((void**)&p_W0l, g_W0l);
    cudaGetSymbolAddress((void**)&p_W1h, g_W1h);
    cudaGetSymbolAddress((void**)&p_W1l, g_W1l);
    cudaGetSymbolAddress((void**)&p_W2h, g_W2h);
    cudaGetSymbolAddress((void**)&p_W2l, g_W2l);
    cudaGetSymbolAddress((void**)&p_X1, g_X1);
    cudaGetSymbolAddress((void**)&p_spre, g_spre);
    cudaGetSymbolAddress((void**)&p_Xp1h, g_Xp1h);
    cudaGetSymbolAddress((void**)&p_Xp1l, g_Xp1l);
    cudaGetSymbolAddress((void**)&p_A1, g_A1);
    cudaGetSymbolAddress((void**)&p_norm1, g_norm1);
    cudaGetSymbolAddress((void**)&p_H1, g_H1);
    cudaGetSymbolAddress((void**)&p_X2, g_X2);
    cudaGetSymbolAddress((void**)&p_Xp2h, g_Xp2h);
    cudaGetSymbolAddress((void**)&p_Xp2l, g_Xp2l);
    cudaGetSymbolAddress((void**)&p_A2, g_A2);
    cudaGetSymbolAddress((void**)&p_norm2, g_norm2);
    cudaGetSymbolAddress((void**)&p_H2, g_H2);
    cudaGetSymbolAddress((void**)&p_X3, g_X3);
    cudaGetSymbolAddress((void**)&p_read, g_read);

    const int headSmem = (4 * 1536 + 8 * 4 * 128) * 4;
    const int wmmaSmem = 2 * STG_B;   // 92160 B
    const int spmmSmem = 65536;
    cudaFuncSetAttribute(spmm_feat_kernel, cudaFuncAttributeMaxDynamicSharedMemorySize, spmmSmem);
    cudaFuncSetAttribute(mlp_head_kernel, cudaFuncAttributeMaxDynamicSharedMemorySize, headSmem);
    cudaFuncSetAttribute(wmma_gen_kernel<1>, cudaFuncAttributeMaxDynamicSharedMemorySize, wmmaSmem);
    cudaFuncSetAttribute(wmma_gen_kernel<0>, cudaFuncAttributeMaxDynamicSharedMemorySize, wmmaSmem);

    // ---- layer 0
    build_adj_kernel<<<G * NNODE / 8, 256>>>(adj, p_cols, p_cnt, p_norm0);
    split_w_kernel<<<(FIN * DH + 255) / 256, 256>>>(W0, p_W0h, p_W0l, FIN * DH);
    split_w_kernel<<<(DH * DH + 255) / 256, 256>>>(W1, p_W1h, p_W1l, DH * DH);
    split_w_kernel<<<(DH * DH + 255) / 256, 256>>>(W2, p_W2h, p_W2l, DH * DH);
    spmm_feat_kernel<<<dim3(2, G, 1), 256, spmmSmem>>>(p_cols, p_cnt, feat, p_norm0,
                                                       p_Yh, p_Yl);
    wmma_gen_kernel<1><<<dim3(2, 2048, 1), 256, wmmaSmem>>>(
        p_Yh, p_Yl, p_W0h, p_W0l, b0, Ws0, p_X1, p_spre, G * NNODE, FIN);
    pool_kernel<256, 32><<<G, 256>>>(p_X1, adj, p_norm0, Ws0, bs0, p_cols, p_cnt,
                                     p_spre, p_Xp1h, p_Xp1l, p_A1, p_norm1, p_read, 0);
    // ---- layer 1
    wmma_gen_kernel<0><<<dim3(2, 256, 1), 256, wmmaSmem>>>(
        p_Xp1h, p_Xp1l, p_W1h, p_W1l, nullptr, nullptr, p_H1, nullptr, G * 32, DH);
    conv_small_kernel<32><<<G, 256>>>(p_A1, p_H1, p_norm1, b1, p_X2);
    pool_kernel<32, 16><<<G, 256>>>(p_X2, p_A1, p_norm1, Ws1, bs1, nullptr, nullptr,
                                    nullptr, p_Xp2h, p_Xp2l, p_A2, p_norm2, p_read, 512);
    // ---- layer 2
    wmma_gen_kernel<0><<<dim3(2, 128, 1), 256, wmmaSmem>>>(
        p_Xp2h, p_Xp2l, p_W2h, p_W2l, nullptr, nullptr, p_H2, nullptr, G * 16, DH);
    conv_small_kernel<16><<<G, 256>>>(p_A2, p_H2, p_norm2, b2, p_X3);
    pool_kernel<16, 8><<<G, 256>>>(p_X3, p_A2, p_norm2, Ws2, bs2, nullptr, nullptr,
                                   nullptr, nullptr, nullptr, nullptr, nullptr, p_read, 1024);
    // ---- fused MLP head
    mlp_head_kernel<<<G / 4, 256, headSmem>>>(p_read, Wd1, bd1, Wd2, bd2, out);
}